// round 1
// baseline (speedup 1.0000x reference)
#include <cuda_runtime.h>
#include <math.h>

// Problem constants
#define B    32
#define NS   4096
#define D    256
#define H    4
#define LVL  6
#define NQ   512
#define NK   1024
#define DH   64
#define ATTN_SCALE 0.125f   // 1/sqrt(64)

// ---------------------------------------------------------------------------
// Scratch (no allocations allowed -> device globals)
// ---------------------------------------------------------------------------
__device__ float g_upd [(size_t)B * NS * D];   // working copy of update_tensor
__device__ float g_qn  [(size_t)B * NQ * D];
__device__ float g_kn  [(size_t)B * NK * D];
__device__ float g_Q   [(size_t)B * NQ * D];
__device__ float g_K   [(size_t)B * NK * D];
__device__ float g_V   [(size_t)B * NK * D];
__device__ float g_ctx [(size_t)B * NQ * D];
__device__ float g_hraw[(size_t)B * NQ * D];
__device__ float g_h   [(size_t)B * NQ * D];
__device__ float g_gact[(size_t)B * NQ * D];
__device__ float g_ffn [(size_t)B * NQ * D];
__device__ float g_res [(size_t)B * NQ * D];

// ---------------------------------------------------------------------------
// Helpers
// ---------------------------------------------------------------------------
__device__ __forceinline__ float gelu_tanh(float x) {
    // matches jax.nn.gelu(approximate=True)
    float x3 = x * x * x;
    return 0.5f * x * (1.0f + tanhf(0.7978845608028654f * (x + 0.044715f * x3)));
}

// LayerNorm stats for a 256-wide row handled by a 256-thread block.
// red must point to >= 18 floats of shared memory.
__device__ __forceinline__ float2 ln_stats256(float v, float* red) {
    float a = v, b2 = v * v;
#pragma unroll
    for (int o = 16; o > 0; o >>= 1) {
        a  += __shfl_down_sync(0xffffffffu, a,  o);
        b2 += __shfl_down_sync(0xffffffffu, b2, o);
    }
    int w = threadIdx.x >> 5;
    if ((threadIdx.x & 31) == 0) { red[w] = a; red[8 + w] = b2; }
    __syncthreads();
    if (threadIdx.x == 0) {
        float s1 = 0.f, s2 = 0.f;
#pragma unroll
        for (int k = 0; k < 8; k++) { s1 += red[k]; s2 += red[8 + k]; }
        float mean = s1 * (1.0f / D);
        float var  = s2 * (1.0f / D) - mean * mean;
        red[16] = mean;
        red[17] = rsqrtf(var + 1e-5f);
    }
    __syncthreads();
    float2 r = make_float2(red[16], red[17]);
    __syncthreads();   // safe reuse of red
    return r;
}

// ---------------------------------------------------------------------------
// init: copy update_tensor into working buffer, zero output
// ---------------------------------------------------------------------------
__global__ void init_kernel(const float* __restrict__ src, float* __restrict__ upd,
                            float* __restrict__ outp) {
    size_t i = (size_t)blockIdx.x * blockDim.x + threadIdx.x;   // float4 index
    float4 v = reinterpret_cast<const float4*>(src)[i];
    reinterpret_cast<float4*>(upd)[i]  = v;
    reinterpret_cast<float4*>(outp)[i] = make_float4(0.f, 0.f, 0.f, 0.f);
}

// ---------------------------------------------------------------------------
// gather + LayerNorm(sys): builds qn [B,NQ,D] and kn [B,NK,D]
// one 256-thread block per row
// ---------------------------------------------------------------------------
__global__ void gather_ln_kernel(const float* __restrict__ emb,
                                 const float* __restrict__ upd,
                                 const float* __restrict__ sscale,
                                 const float* __restrict__ sbias,
                                 const int* __restrict__ qidx,
                                 const int* __restrict__ kidx,
                                 float* __restrict__ qn,
                                 float* __restrict__ kn) {
    __shared__ float red[18];
    int r = blockIdx.x;
    int t = threadIdx.x;
    int b, s;
    float* dst;
    if (r < B * NQ) {
        b = r / NQ;
        s = qidx[r % NQ];
        dst = qn + (size_t)r * D;
    } else {
        int r2 = r - B * NQ;
        b = r2 / NK;
        s = kidx[r2 % NK];
        dst = kn + (size_t)r2 * D;
    }
    float v = emb[(size_t)s * D + t] + upd[((size_t)b * NS + s) * D + t];
    float2 st = ln_stats256(v, red);
    dst[t] = (v - st.x) * st.y * sscale[t] + sbias[t];
}

// ---------------------------------------------------------------------------
// SGEMM: C[M,256] = A[M,256] @ W[256,256]  (+bias, +gelu per MODE)
// 64x64 block tile, 256 threads, 4x4 microtile
// MODE: 0 = plain, 1 = +bias, 2 = +bias+gelu
// ---------------------------------------------------------------------------
template <int MODE>
__global__ __launch_bounds__(256)
void gemm256_kernel(const float* __restrict__ A, const float* __restrict__ W,
                    const float* __restrict__ bias, float* __restrict__ C) {
    __shared__ float As[16][65];   // [k][m], padded
    __shared__ float Bs[16][64];   // [k][n]
    int tid = threadIdx.x;
    int tx = tid & 15, ty = tid >> 4;
    int mBase = blockIdx.x * 64;
    int nBase = blockIdx.y * 64;
    float acc[4][4] = {};
    for (int k0 = 0; k0 < 256; k0 += 16) {
#pragma unroll
        for (int it = 0; it < 4; it++) {
            int idx = tid + it * 256;
            int m = idx >> 4, kk = idx & 15;
            As[kk][m] = A[(size_t)(mBase + m) * 256 + k0 + kk];
        }
#pragma unroll
        for (int it = 0; it < 4; it++) {
            int idx = tid + it * 256;
            int kk = idx >> 6, n = idx & 63;
            Bs[kk][n] = W[(size_t)(k0 + kk) * 256 + nBase + n];
        }
        __syncthreads();
#pragma unroll
        for (int kk = 0; kk < 16; kk++) {
            float a[4], bb[4];
#pragma unroll
            for (int i = 0; i < 4; i++) a[i] = As[kk][ty * 4 + i];
            float4 b4 = *reinterpret_cast<const float4*>(&Bs[kk][tx * 4]);
            bb[0] = b4.x; bb[1] = b4.y; bb[2] = b4.z; bb[3] = b4.w;
#pragma unroll
            for (int i = 0; i < 4; i++)
#pragma unroll
                for (int j = 0; j < 4; j++) acc[i][j] += a[i] * bb[j];
        }
        __syncthreads();
    }
#pragma unroll
    for (int i = 0; i < 4; i++) {
        int m = mBase + ty * 4 + i;
#pragma unroll
        for (int j = 0; j < 4; j++) {
            int n = nBase + tx * 4 + j;
            float v = acc[i][j];
            if (MODE >= 1) v += bias[n];
            if (MODE == 2) v = gelu_tanh(v);
            C[(size_t)m * 256 + n] = v;
        }
    }
}

// ---------------------------------------------------------------------------
// Fused attention: grid (NQ/64, H, B), 64 threads; each thread owns one query.
// Online softmax with per-key max updates; K/V/mask chunks staged in smem.
// ---------------------------------------------------------------------------
__global__ __launch_bounds__(64)
void attn_kernel(const float* __restrict__ Q, const float* __restrict__ K,
                 const float* __restrict__ V, const float* __restrict__ mask,
                 float* __restrict__ ctx) {
    __shared__ float Ks[64][64];
    __shared__ float Vs[64][64];
    __shared__ unsigned char Ms[64][65];
    int t  = threadIdx.x;
    int q0 = blockIdx.x * 64;
    int h  = blockIdx.y;
    int b  = blockIdx.z;

    // this thread's query vector (head slice) in registers
    float qreg[DH];
    const float* qrow = Q + ((size_t)(b * NQ + q0 + t)) * D + h * DH;
#pragma unroll
    for (int d4 = 0; d4 < DH / 4; d4++) {
        float4 v = reinterpret_cast<const float4*>(qrow)[d4];
        qreg[d4 * 4 + 0] = v.x; qreg[d4 * 4 + 1] = v.y;
        qreg[d4 * 4 + 2] = v.z; qreg[d4 * 4 + 3] = v.w;
    }

    float m = -1e30f, l = 0.f;
    float acc[DH];
#pragma unroll
    for (int d = 0; d < DH; d++) acc[d] = 0.f;

    for (int c = 0; c < NK; c += 64) {
        const float* Kb = K + ((size_t)(b * NK + c)) * D + h * DH;
        const float* Vb = V + ((size_t)(b * NK + c)) * D + h * DH;
        // cooperative loads: thread t loads column t (coalesced across threads)
#pragma unroll 8
        for (int r = 0; r < 64; r++) {
            Ks[r][t] = Kb[(size_t)r * D + t];
            Vs[r][t] = Vb[(size_t)r * D + t];
            Ms[r][t] = (mask[((size_t)(q0 + r)) * NK + c + t] > 0.5f) ? 1 : 0;
        }
        __syncthreads();

        for (int kk = 0; kk < 64; kk++) {
            // dot(q, K[kk]) with 4-way ILP; Ks reads are warp-broadcast
            const float4* kr = reinterpret_cast<const float4*>(Ks[kk]);
            float s0 = 0.f, s1 = 0.f, s2 = 0.f, s3 = 0.f;
#pragma unroll
            for (int d4 = 0; d4 < DH / 4; d4++) {
                float4 kv = kr[d4];
                s0 += qreg[d4 * 4 + 0] * kv.x;
                s1 += qreg[d4 * 4 + 1] * kv.y;
                s2 += qreg[d4 * 4 + 2] * kv.z;
                s3 += qreg[d4 * 4 + 3] * kv.w;
            }
            float s = (s0 + s1) + (s2 + s3);
            s *= ATTN_SCALE;
            s = Ms[t][kk] ? s : -1e9f;
            if (s > m) {
                float corr = __expf(m - s);
                l *= corr;
#pragma unroll
                for (int d = 0; d < DH; d++) acc[d] *= corr;
                m = s;
            }
            float p = __expf(s - m);
            l += p;
            const float4* vr = reinterpret_cast<const float4*>(Vs[kk]);
#pragma unroll
            for (int d4 = 0; d4 < DH / 4; d4++) {
                float4 vv = vr[d4];
                acc[d4 * 4 + 0] += p * vv.x;
                acc[d4 * 4 + 1] += p * vv.y;
                acc[d4 * 4 + 2] += p * vv.z;
                acc[d4 * 4 + 3] += p * vv.w;
            }
        }
        __syncthreads();
    }

    float inv = 1.0f / l;
    float* crow = ctx + ((size_t)(b * NQ + q0 + t)) * D + h * DH;
#pragma unroll
    for (int d4 = 0; d4 < DH / 4; d4++) {
        float4 o;
        o.x = acc[d4 * 4 + 0] * inv; o.y = acc[d4 * 4 + 1] * inv;
        o.z = acc[d4 * 4 + 2] * inv; o.w = acc[d4 * 4 + 3] * inv;
        reinterpret_cast<float4*>(crow)[d4] = o;
    }
}

// ---------------------------------------------------------------------------
// Plain row-LayerNorm: one 256-thread block per row
// ---------------------------------------------------------------------------
__global__ void ln_rows_kernel(const float* __restrict__ x,
                               const float* __restrict__ scale,
                               const float* __restrict__ bias,
                               float* __restrict__ out) {
    __shared__ float red[18];
    size_t idx = (size_t)blockIdx.x * D + threadIdx.x;
    float v = x[idx];
    float2 st = ln_stats256(v, red);
    out[idx] = (v - st.x) * st.y * scale[threadIdx.x] + bias[threadIdx.x];
}

// ---------------------------------------------------------------------------
// res = LN_eff( LN_outer( h + ffn ) )
// ---------------------------------------------------------------------------
__global__ void res_ln_kernel(const float* __restrict__ hbuf,
                              const float* __restrict__ ffn,
                              const float* __restrict__ os, const float* __restrict__ ob,
                              const float* __restrict__ es, const float* __restrict__ eb,
                              float* __restrict__ res) {
    __shared__ float red[18];
    size_t idx = (size_t)blockIdx.x * D + threadIdx.x;
    int t = threadIdx.x;
    float x = hbuf[idx] + ffn[idx];
    float2 st1 = ln_stats256(x, red);
    float y = (x - st1.x) * st1.y * os[t] + ob[t];
    float2 st2 = ln_stats256(y, red);
    res[idx] = (y - st2.x) * st2.y * es[t] + eb[t];
}

// ---------------------------------------------------------------------------
// scatter-add res into update_tensor working copy and output (duplicates -> atomics)
// ---------------------------------------------------------------------------
__global__ void scatter_kernel(const float* __restrict__ res,
                               const int* __restrict__ qidx,
                               float* __restrict__ upd,
                               float* __restrict__ outp) {
    int bi = blockIdx.x;                 // b*NQ + i
    int b = bi / NQ, i = bi % NQ;
    int s = qidx[i];
    float v = res[(size_t)bi * D + threadIdx.x];
    size_t off = ((size_t)b * NS + s) * D + threadIdx.x;
    atomicAdd(&upd[off], v);
    atomicAdd(&outp[off], v);
}

// ---------------------------------------------------------------------------
// launch
// ---------------------------------------------------------------------------
extern "C" void kernel_launch(void* const* d_in, const int* in_sizes, int n_in,
                              void* d_out, int out_size) {
    const float* update_tensor = (const float*)d_in[0];
    const float* emb   = (const float*)d_in[1];
    const float* mask  = (const float*)d_in[2];
    const float* Wq    = (const float*)d_in[3];
    const float* Wk    = (const float*)d_in[4];
    const float* Wv    = (const float*)d_in[5];
    const float* Wo    = (const float*)d_in[6];
    const float* W1    = (const float*)d_in[7];
    const float* b1    = (const float*)d_in[8];
    const float* W2    = (const float*)d_in[9];
    const float* b2    = (const float*)d_in[10];
    const float* sys_s = (const float*)d_in[11];
    const float* sys_b = (const float*)d_in[12];
    const float* eff_s = (const float*)d_in[13];
    const float* eff_b = (const float*)d_in[14];
    const float* in_s  = (const float*)d_in[15];
    const float* in_b  = (const float*)d_in[16];
    const float* out_s = (const float*)d_in[17];
    const float* out_b = (const float*)d_in[18];
    const int*   qidx  = (const int*)d_in[19];
    const int*   kidx  = (const int*)d_in[20];
    float* outp = (float*)d_out;

    float *p_upd, *p_qn, *p_kn, *p_Q, *p_K, *p_V, *p_ctx, *p_hraw, *p_h, *p_g, *p_ffn, *p_res;
    cudaGetSymbolAddress((void**)&p_upd,  g_upd);
    cudaGetSymbolAddress((void**)&p_qn,   g_qn);
    cudaGetSymbolAddress((void**)&p_kn,   g_kn);
    cudaGetSymbolAddress((void**)&p_Q,    g_Q);
    cudaGetSymbolAddress((void**)&p_K,    g_K);
    cudaGetSymbolAddress((void**)&p_V,    g_V);
    cudaGetSymbolAddress((void**)&p_ctx,  g_ctx);
    cudaGetSymbolAddress((void**)&p_hraw, g_hraw);
    cudaGetSymbolAddress((void**)&p_h,    g_h);
    cudaGetSymbolAddress((void**)&p_g,    g_gact);
    cudaGetSymbolAddress((void**)&p_ffn,  g_ffn);
    cudaGetSymbolAddress((void**)&p_res,  g_res);

    // copy mutable state + zero output
    {
        int n4 = (B * NS * D) / 4;
        init_kernel<<<n4 / 256, 256>>>(update_tensor, p_upd, outp);
    }

    for (int l = 0; l < LVL; l++) {
        const int*   qi = qidx + l * NQ;
        const int*   ki = kidx + l * NK;
        const float* ml = mask + (size_t)l * NQ * NK;

        gather_ln_kernel<<<B * (NQ + NK), 256>>>(emb, p_upd, sys_s, sys_b, qi, ki, p_qn, p_kn);

        gemm256_kernel<0><<<dim3(B * NQ / 64, 4), 256>>>(p_qn, Wq, nullptr, p_Q);
        gemm256_kernel<0><<<dim3(B * NK / 64, 4), 256>>>(p_kn, Wk, nullptr, p_K);
        gemm256_kernel<0><<<dim3(B * NK / 64, 4), 256>>>(p_kn, Wv, nullptr, p_V);

        attn_kernel<<<dim3(NQ / 64, H, B), 64>>>(p_Q, p_K, p_V, ml, p_ctx);

        gemm256_kernel<0><<<dim3(B * NQ / 64, 4), 256>>>(p_ctx, Wo, nullptr, p_hraw);
        ln_rows_kernel<<<B * NQ, 256>>>(p_hraw, in_s, in_b, p_h);

        gemm256_kernel<2><<<dim3(B * NQ / 64, 4), 256>>>(p_h, W1, b1, p_g);
        gemm256_kernel<1><<<dim3(B * NQ / 64, 4), 256>>>(p_g, W2, b2, p_ffn);

        res_ln_kernel<<<B * NQ, 256>>>(p_h, p_ffn, out_s, out_b, eff_s, eff_b, p_res);

        scatter_kernel<<<B * NQ, 256>>>(p_res, qi, p_upd, outp);
    }
}

// round 3
// speedup vs baseline: 1.3670x; 1.3670x over previous
#include <cuda_runtime.h>
#include <cuda_bf16.h>
#include <math.h>
#include <stdint.h>

// Problem constants
#define B    32
#define NS   4096
#define D    256
#define H    4
#define LVL  6
#define NQ   512
#define NK   1024
#define DH   64
#define ATTN_SCALE 0.125f   // 1/sqrt(64)

// ---------------------------------------------------------------------------
// Scratch (no allocations allowed -> device globals)
// ---------------------------------------------------------------------------
__device__ float g_upd [(size_t)B * NS * D];   // working copy of update_tensor
__device__ float g_qn  [(size_t)B * NQ * D];
__device__ float g_kn  [(size_t)B * NK * D];
__device__ float g_Q   [(size_t)B * NQ * D];
__device__ float g_K   [(size_t)B * NK * D];
__device__ float g_V   [(size_t)B * NK * D];
__device__ float g_ctx [(size_t)B * NQ * D];
__device__ float g_hraw[(size_t)B * NQ * D];
__device__ float g_h   [(size_t)B * NQ * D];
__device__ float g_gact[(size_t)B * NQ * D];
__device__ float g_ffn [(size_t)B * NQ * D];
__device__ float g_res [(size_t)B * NQ * D];

// split-KV attention partials
__device__ float  g_pacc[(size_t)4 * B * NQ * D];
__device__ float2 g_pml [(size_t)4 * B * NQ * H];

// transposed + bf16 hi/lo decomposed weights: [6][N=256][K=256]
__device__ __nv_bfloat16 g_Wt_hi[6 * 256 * 256];
__device__ __nv_bfloat16 g_Wt_lo[6 * 256 * 256];

// ---------------------------------------------------------------------------
// Helpers
// ---------------------------------------------------------------------------
__device__ __forceinline__ uint32_t smem_u32(const void* p) {
    uint32_t a;
    asm("{ .reg .u64 t; cvta.to.shared.u64 t, %1; cvt.u32.u64 %0, t; }" : "=r"(a) : "l"(p));
    return a;
}

__device__ __forceinline__ float gelu_tanh(float x) {
    float x3 = x * x * x;
    return 0.5f * x * (1.0f + tanhf(0.7978845608028654f * (x + 0.044715f * x3)));
}

__device__ __forceinline__ float2 ln_stats256(float v, float* red) {
    float a = v, b2 = v * v;
#pragma unroll
    for (int o = 16; o > 0; o >>= 1) {
        a  += __shfl_down_sync(0xffffffffu, a,  o);
        b2 += __shfl_down_sync(0xffffffffu, b2, o);
    }
    int w = threadIdx.x >> 5;
    if ((threadIdx.x & 31) == 0) { red[w] = a; red[8 + w] = b2; }
    __syncthreads();
    if (threadIdx.x == 0) {
        float s1 = 0.f, s2 = 0.f;
#pragma unroll
        for (int k = 0; k < 8; k++) { s1 += red[k]; s2 += red[8 + k]; }
        float mean = s1 * (1.0f / D);
        float var  = s2 * (1.0f / D) - mean * mean;
        red[16] = mean;
        red[17] = rsqrtf(var + 1e-5f);
    }
    __syncthreads();
    float2 r = make_float2(red[16], red[17]);
    __syncthreads();
    return r;
}

// mma.sync m16n8k16 bf16 (base-target legal; runs on HMMA pipe)
__device__ __forceinline__ void mma16816(float* c, const uint32_t* a, uint32_t b0, uint32_t b1) {
    asm volatile(
        "mma.sync.aligned.m16n8k16.row.col.f32.bf16.bf16.f32 "
        "{%0,%1,%2,%3}, {%4,%5,%6,%7}, {%8,%9}, {%0,%1,%2,%3};"
        : "+f"(c[0]), "+f"(c[1]), "+f"(c[2]), "+f"(c[3])
        : "r"(a[0]), "r"(a[1]), "r"(a[2]), "r"(a[3]), "r"(b0), "r"(b1));
}

__device__ __forceinline__ void ldmatrix_x4(uint32_t* r, uint32_t addr) {
    asm volatile("ldmatrix.sync.aligned.m8n8.x4.shared.b16 {%0,%1,%2,%3}, [%4];"
                 : "=r"(r[0]), "=r"(r[1]), "=r"(r[2]), "=r"(r[3]) : "r"(addr));
}

// ---------------------------------------------------------------------------
// init: copy update_tensor into working buffer, zero output
// ---------------------------------------------------------------------------
__global__ void init_kernel(const float* __restrict__ src, float* __restrict__ upd,
                            float* __restrict__ outp) {
    size_t i = (size_t)blockIdx.x * blockDim.x + threadIdx.x;
    float4 v = reinterpret_cast<const float4*>(src)[i];
    reinterpret_cast<float4*>(upd)[i]  = v;
    reinterpret_cast<float4*>(outp)[i] = make_float4(0.f, 0.f, 0.f, 0.f);
}

// ---------------------------------------------------------------------------
// weight prep: Wt[n][k] = W[k][n], decomposed into bf16 hi + lo
// ---------------------------------------------------------------------------
__global__ void prep_w_kernel(const float* __restrict__ W,
                              __nv_bfloat16* __restrict__ Th,
                              __nv_bfloat16* __restrict__ Tl) {
    __shared__ float t[32][33];
    int bx = blockIdx.x * 32;   // n tile
    int by = blockIdx.y * 32;   // k tile
#pragma unroll
    for (int i = threadIdx.y; i < 32; i += 8)
        t[i][threadIdx.x] = W[(size_t)(by + i) * 256 + bx + threadIdx.x];  // t[k][n]
    __syncthreads();
#pragma unroll
    for (int i = threadIdx.y; i < 32; i += 8) {
        float v = t[threadIdx.x][i];        // k = by+tx, n = bx+i
        __nv_bfloat16 h = __float2bfloat16(v);
        float r = v - __bfloat162float(h);
        size_t o = (size_t)(bx + i) * 256 + by + threadIdx.x;
        Th[o] = h;
        Tl[o] = __float2bfloat16(r);
    }
}

// ---------------------------------------------------------------------------
// gather + LayerNorm(sys)
// ---------------------------------------------------------------------------
__global__ void gather_ln_kernel(const float* __restrict__ emb,
                                 const float* __restrict__ upd,
                                 const float* __restrict__ sscale,
                                 const float* __restrict__ sbias,
                                 const int* __restrict__ qidx,
                                 const int* __restrict__ kidx,
                                 float* __restrict__ qn,
                                 float* __restrict__ kn) {
    __shared__ float red[18];
    int r = blockIdx.x;
    int t = threadIdx.x;
    int b, s;
    float* dst;
    if (r < B * NQ) {
        b = r / NQ;
        s = qidx[r % NQ];
        dst = qn + (size_t)r * D;
    } else {
        int r2 = r - B * NQ;
        b = r2 / NK;
        s = kidx[r2 % NK];
        dst = kn + (size_t)r2 * D;
    }
    float v = emb[(size_t)s * D + t] + upd[((size_t)b * NS + s) * D + t];
    float2 st = ln_stats256(v, red);
    dst[t] = (v - st.x) * st.y * sscale[t] + sbias[t];
}

// ---------------------------------------------------------------------------
// mma.sync GEMM: C[M,256] = A[M,256] @ W[256,256]
// A fp32 gmem -> bf16 hi/lo on the fly; W pre-transposed bf16 hi/lo [N][K]
// split-3: D = Ah*Bh + Ah*Bl + Al*Bh   (~fp32 precision)
// CTA: 128(M) x 128(N), 8 warps (4 x 2), warp tile 32 x 64; K chunks of 64.
// MODE: 0 = plain, 1 = +bias, 2 = +bias+gelu
// ---------------------------------------------------------------------------
#define GPAD 72                                      // bf16 elems per smem row
#define GEMM_SMEM_BYTES (4 * 128 * GPAD * 2)         // 73728

template <int MODE>
__global__ __launch_bounds__(256)
void gemm_mma_kernel(const float* __restrict__ A,
                     const __nv_bfloat16* __restrict__ Bth,
                     const __nv_bfloat16* __restrict__ Btl,
                     const float* __restrict__ bias,
                     float* __restrict__ C) {
    extern __shared__ char smem[];
    const uint32_t sb = smem_u32(smem);
    const int OFF_AH = 0;
    const int OFF_AL = 128 * GPAD * 2;
    const int OFF_BH = 2 * 128 * GPAD * 2;
    const int OFF_BL = 3 * 128 * GPAD * 2;

    int tid  = threadIdx.x;
    int wid  = tid >> 5, lane = tid & 31;
    int warpM = wid & 3;      // 0..3 -> 32 rows each
    int warpN = wid >> 2;     // 0..1 -> 64 cols each
    int mBase = blockIdx.x * 128;
    int nBase = blockIdx.y * 128;

    float acc[2][8][4];
#pragma unroll
    for (int i = 0; i < 2; i++)
#pragma unroll
        for (int j = 0; j < 8; j++)
#pragma unroll
            for (int k = 0; k < 4; k++) acc[i][j][k] = 0.f;

    for (int kc = 0; kc < 4; kc++) {
        int k0 = kc * 64;
        // stage A chunk (fp32 -> bf16 hi/lo) : 128 rows x 64 k
#pragma unroll
        for (int it = 0; it < 16; it++) {
            int p = tid + it * 256;           // pair index
            int m = p >> 5, j = p & 31;
            float2 v = *reinterpret_cast<const float2*>(
                A + (size_t)(mBase + m) * 256 + k0 + 2 * j);
            __nv_bfloat16 h0 = __float2bfloat16(v.x);
            __nv_bfloat16 h1 = __float2bfloat16(v.y);
            __nv_bfloat16 l0 = __float2bfloat16(v.x - __bfloat162float(h0));
            __nv_bfloat16 l1 = __float2bfloat16(v.y - __bfloat162float(h1));
            uint32_t hp = ((uint32_t)__bfloat16_as_ushort(h1) << 16) | __bfloat16_as_ushort(h0);
            uint32_t lp = ((uint32_t)__bfloat16_as_ushort(l1) << 16) | __bfloat16_as_ushort(l0);
            int off = (m * GPAD + 2 * j) * 2;
            *reinterpret_cast<uint32_t*>(smem + OFF_AH + off) = hp;
            *reinterpret_cast<uint32_t*>(smem + OFF_AL + off) = lp;
        }
        // stage B chunk (already bf16) : 128 n-rows x 64 k
#pragma unroll
        for (int it = 0; it < 16; it++) {
            int p = tid + it * 256;
            int n = p >> 5, j = p & 31;
            size_t go = (size_t)(nBase + n) * 256 + k0 + 2 * j;
            int off = (n * GPAD + 2 * j) * 2;
            *reinterpret_cast<uint32_t*>(smem + OFF_BH + off) =
                *reinterpret_cast<const uint32_t*>(Bth + go);
            *reinterpret_cast<uint32_t*>(smem + OFF_BL + off) =
                *reinterpret_cast<const uint32_t*>(Btl + go);
        }
        __syncthreads();

        for (int ks = 0; ks < 4; ks++) {
            int lrow = lane & 15;
            int lcol = ks * 16 + (lane >> 4) * 8;
            uint32_t ah[2][4], al[2][4];
#pragma unroll
            for (int mt = 0; mt < 2; mt++) {
                int row = warpM * 32 + mt * 16 + lrow;
                uint32_t ad = sb + (uint32_t)((row * GPAD + lcol) * 2);
                ldmatrix_x4(ah[mt], ad + OFF_AH);
                ldmatrix_x4(al[mt], ad + OFF_AL);
            }
#pragma unroll
            for (int nt2 = 0; nt2 < 4; nt2++) {
                int row = warpN * 64 + nt2 * 16 + lrow;
                uint32_t bd = sb + (uint32_t)((row * GPAD + lcol) * 2);
                uint32_t bh[4], bl[4];
                ldmatrix_x4(bh, bd + OFF_BH);
                ldmatrix_x4(bl, bd + OFF_BL);
#pragma unroll
                for (int mt = 0; mt < 2; mt++) {
                    // even n8 frag: regs {0,2}; odd: regs {1,3}
                    mma16816(acc[mt][nt2 * 2 + 0], ah[mt], bh[0], bh[2]);
                    mma16816(acc[mt][nt2 * 2 + 0], ah[mt], bl[0], bl[2]);
                    mma16816(acc[mt][nt2 * 2 + 0], al[mt], bh[0], bh[2]);
                    mma16816(acc[mt][nt2 * 2 + 1], ah[mt], bh[1], bh[3]);
                    mma16816(acc[mt][nt2 * 2 + 1], ah[mt], bl[1], bl[3]);
                    mma16816(acc[mt][nt2 * 2 + 1], al[mt], bh[1], bh[3]);
                }
            }
        }
        __syncthreads();
    }

    // epilogue
    int g = lane >> 2, tig = lane & 3;
#pragma unroll
    for (int mt = 0; mt < 2; mt++) {
#pragma unroll
        for (int nt = 0; nt < 8; nt++) {
            int row0 = mBase + warpM * 32 + mt * 16 + g;
            int col  = nBase + warpN * 64 + nt * 8 + tig * 2;
            float v0 = acc[mt][nt][0], v1 = acc[mt][nt][1];
            float v2 = acc[mt][nt][2], v3 = acc[mt][nt][3];
            if (MODE >= 1) {
                float bb0 = bias[col], bb1 = bias[col + 1];
                v0 += bb0; v1 += bb1; v2 += bb0; v3 += bb1;
            }
            if (MODE == 2) {
                v0 = gelu_tanh(v0); v1 = gelu_tanh(v1);
                v2 = gelu_tanh(v2); v3 = gelu_tanh(v3);
            }
            *reinterpret_cast<float2*>(C + (size_t)row0 * 256 + col) = make_float2(v0, v1);
            *reinterpret_cast<float2*>(C + (size_t)(row0 + 8) * 256 + col) = make_float2(v2, v3);
        }
    }
}

// ---------------------------------------------------------------------------
// Split-KV attention partials: grid (NQ/64, H, B*4), 64 threads.
// Part p handles keys [p*256, p*256+256); writes unnormalized acc + (m,l).
// ---------------------------------------------------------------------------
__global__ __launch_bounds__(64)
void attn_partial_kernel(const float* __restrict__ Q, const float* __restrict__ K,
                         const float* __restrict__ V, const float* __restrict__ mask,
                         float* __restrict__ pacc, float2* __restrict__ pml) {
    __shared__ float Ks[64][64];
    __shared__ float Vs[64][64];
    __shared__ unsigned char Ms[64][65];
    int t    = threadIdx.x;
    int q0   = blockIdx.x * 64;
    int h    = blockIdx.y;
    int b    = blockIdx.z >> 2;
    int part = blockIdx.z & 3;

    float qreg[DH];
    const float* qrow = Q + ((size_t)(b * NQ + q0 + t)) * D + h * DH;
#pragma unroll
    for (int d4 = 0; d4 < DH / 4; d4++) {
        float4 v = reinterpret_cast<const float4*>(qrow)[d4];
        qreg[d4 * 4 + 0] = v.x; qreg[d4 * 4 + 1] = v.y;
        qreg[d4 * 4 + 2] = v.z; qreg[d4 * 4 + 3] = v.w;
    }

    float m = -1e30f, l = 0.f;
    float acc[DH];
#pragma unroll
    for (int d = 0; d < DH; d++) acc[d] = 0.f;

    for (int cc = 0; cc < 4; cc++) {
        int c = part * 256 + cc * 64;
        const float* Kb = K + ((size_t)(b * NK + c)) * D + h * DH;
        const float* Vb = V + ((size_t)(b * NK + c)) * D + h * DH;
#pragma unroll 8
        for (int r = 0; r < 64; r++) {
            Ks[r][t] = Kb[(size_t)r * D + t];
            Vs[r][t] = Vb[(size_t)r * D + t];
            Ms[r][t] = (mask[((size_t)(q0 + r)) * NK + c + t] > 0.5f) ? 1 : 0;
        }
        __syncthreads();

        for (int kk = 0; kk < 64; kk++) {
            const float4* kr = reinterpret_cast<const float4*>(Ks[kk]);
            float s0 = 0.f, s1 = 0.f, s2 = 0.f, s3 = 0.f;
#pragma unroll
            for (int d4 = 0; d4 < DH / 4; d4++) {
                float4 kv = kr[d4];
                s0 += qreg[d4 * 4 + 0] * kv.x;
                s1 += qreg[d4 * 4 + 1] * kv.y;
                s2 += qreg[d4 * 4 + 2] * kv.z;
                s3 += qreg[d4 * 4 + 3] * kv.w;
            }
            float s = (s0 + s1) + (s2 + s3);
            s *= ATTN_SCALE;
            s = Ms[t][kk] ? s : -1e9f;
            if (s > m) {
                float corr = __expf(m - s);
                l *= corr;
#pragma unroll
                for (int d = 0; d < DH; d++) acc[d] *= corr;
                m = s;
            }
            float p = __expf(s - m);
            l += p;
            const float4* vr = reinterpret_cast<const float4*>(Vs[kk]);
#pragma unroll
            for (int d4 = 0; d4 < DH / 4; d4++) {
                float4 vv = vr[d4];
                acc[d4 * 4 + 0] += p * vv.x;
                acc[d4 * 4 + 1] += p * vv.y;
                acc[d4 * 4 + 2] += p * vv.z;
                acc[d4 * 4 + 3] += p * vv.w;
            }
        }
        __syncthreads();
    }

    float* prow = pacc + (size_t)part * (B * NQ * D) +
                  ((size_t)(b * NQ + q0 + t)) * D + h * DH;
#pragma unroll
    for (int d4 = 0; d4 < DH / 4; d4++) {
        float4 o;
        o.x = acc[d4 * 4 + 0]; o.y = acc[d4 * 4 + 1];
        o.z = acc[d4 * 4 + 2]; o.w = acc[d4 * 4 + 3];
        reinterpret_cast<float4*>(prow)[d4] = o;
    }
    pml[(((size_t)part * B + b) * NQ + q0 + t) * H + h] = make_float2(m, l);
}

// merge the 4 partials -> ctx. grid B*NQ, 256 threads (t: h = t/64, d = t%64)
__global__ void attn_merge_kernel(const float* __restrict__ pacc,
                                  const float2* __restrict__ pml,
                                  float* __restrict__ ctx) {
    int bq = blockIdx.x;
    int t = threadIdx.x;
    int h = t >> 6;
    int b = bq / NQ, q = bq % NQ;
    float2 ml[4];
    float M = -1e30f;
#pragma unroll
    for (int p = 0; p < 4; p++) {
        ml[p] = pml[(((size_t)p * B + b) * NQ + q) * H + h];
        M = fmaxf(M, ml[p].x);
    }
    float L = 0.f;
#pragma unroll
    for (int p = 0; p < 4; p++) L += ml[p].y * __expf(ml[p].x - M);
    float inv = 1.0f / L;
    float s = 0.f;
#pragma unroll
    for (int p = 0; p < 4; p++)
        s += __expf(ml[p].x - M) * pacc[(size_t)p * (B * NQ * D) + (size_t)bq * D + t];
    ctx[(size_t)bq * D + t] = s * inv;
}

// ---------------------------------------------------------------------------
// Plain row-LayerNorm
// ---------------------------------------------------------------------------
__global__ void ln_rows_kernel(const float* __restrict__ x,
                               const float* __restrict__ scale,
                               const float* __restrict__ bias,
                               float* __restrict__ out) {
    __shared__ float red[18];
    size_t idx = (size_t)blockIdx.x * D + threadIdx.x;
    float v = x[idx];
    float2 st = ln_stats256(v, red);
    out[idx] = (v - st.x) * st.y * scale[threadIdx.x] + bias[threadIdx.x];
}

// ---------------------------------------------------------------------------
// res = LN_eff( LN_outer( h + ffn ) )
// ---------------------------------------------------------------------------
__global__ void res_ln_kernel(const float* __restrict__ hbuf,
                              const float* __restrict__ ffn,
                              const float* __restrict__ os, const float* __restrict__ ob,
                              const float* __restrict__ es, const float* __restrict__ eb,
                              float* __restrict__ res) {
    __shared__ float red[18];
    size_t idx = (size_t)blockIdx.x * D + threadIdx.x;
    int t = threadIdx.x;
    float x = hbuf[idx] + ffn[idx];
    float2 st1 = ln_stats256(x, red);
    float y = (x - st1.x) * st1.y * os[t] + ob[t];
    float2 st2 = ln_stats256(y, red);
    res[idx] = (y - st2.x) * st2.y * es[t] + eb[t];
}

// ---------------------------------------------------------------------------
// scatter-add res into working copy and output
// ---------------------------------------------------------------------------
__global__ void scatter_kernel(const float* __restrict__ res,
                               const int* __restrict__ qidx,
                               float* __restrict__ upd,
                               float* __restrict__ outp) {
    int bi = blockIdx.x;
    int b = bi / NQ, i = bi % NQ;
    int s = qidx[i];
    float v = res[(size_t)bi * D + threadIdx.x];
    size_t off = ((size_t)b * NS + s) * D + threadIdx.x;
    atomicAdd(&upd[off], v);
    atomicAdd(&outp[off], v);
}

// ---------------------------------------------------------------------------
// launch
// ---------------------------------------------------------------------------
extern "C" void kernel_launch(void* const* d_in, const int* in_sizes, int n_in,
                              void* d_out, int out_size) {
    const float* update_tensor = (const float*)d_in[0];
    const float* emb   = (const float*)d_in[1];
    const float* mask  = (const float*)d_in[2];
    const float* Wq    = (const float*)d_in[3];
    const float* Wk    = (const float*)d_in[4];
    const float* Wv    = (const float*)d_in[5];
    const float* Wo    = (const float*)d_in[6];
    const float* W1    = (const float*)d_in[7];
    const float* b1    = (const float*)d_in[8];
    const float* W2    = (const float*)d_in[9];
    const float* b2    = (const float*)d_in[10];
    const float* sys_s = (const float*)d_in[11];
    const float* sys_b = (const float*)d_in[12];
    const float* eff_s = (const float*)d_in[13];
    const float* eff_b = (const float*)d_in[14];
    const float* in_s  = (const float*)d_in[15];
    const float* in_b  = (const float*)d_in[16];
    const float* out_s = (const float*)d_in[17];
    const float* out_b = (const float*)d_in[18];
    const int*   qidx  = (const int*)d_in[19];
    const int*   kidx  = (const int*)d_in[20];
    float* outp = (float*)d_out;

    float *p_upd, *p_qn, *p_kn, *p_Q, *p_K, *p_V, *p_ctx, *p_hraw, *p_h, *p_g, *p_ffn, *p_res;
    float *p_pacc;
    float2 *p_pml;
    __nv_bfloat16 *p_wh, *p_wl;
    cudaGetSymbolAddress((void**)&p_upd,  g_upd);
    cudaGetSymbolAddress((void**)&p_qn,   g_qn);
    cudaGetSymbolAddress((void**)&p_kn,   g_kn);
    cudaGetSymbolAddress((void**)&p_Q,    g_Q);
    cudaGetSymbolAddress((void**)&p_K,    g_K);
    cudaGetSymbolAddress((void**)&p_V,    g_V);
    cudaGetSymbolAddress((void**)&p_ctx,  g_ctx);
    cudaGetSymbolAddress((void**)&p_hraw, g_hraw);
    cudaGetSymbolAddress((void**)&p_h,    g_h);
    cudaGetSymbolAddress((void**)&p_g,    g_gact);
    cudaGetSymbolAddress((void**)&p_ffn,  g_ffn);
    cudaGetSymbolAddress((void**)&p_res,  g_res);
    cudaGetSymbolAddress((void**)&p_pacc, g_pacc);
    cudaGetSymbolAddress((void**)&p_pml,  g_pml);
    cudaGetSymbolAddress((void**)&p_wh,   g_Wt_hi);
    cudaGetSymbolAddress((void**)&p_wl,   g_Wt_lo);

    cudaFuncSetAttribute(gemm_mma_kernel<0>, cudaFuncAttributeMaxDynamicSharedMemorySize, GEMM_SMEM_BYTES);
    cudaFuncSetAttribute(gemm_mma_kernel<1>, cudaFuncAttributeMaxDynamicSharedMemorySize, GEMM_SMEM_BYTES);
    cudaFuncSetAttribute(gemm_mma_kernel<2>, cudaFuncAttributeMaxDynamicSharedMemorySize, GEMM_SMEM_BYTES);

    // copy mutable state + zero output
    {
        int n4 = (B * NS * D) / 4;
        init_kernel<<<n4 / 256, 256>>>(update_tensor, p_upd, outp);
    }

    // prep weights: transpose + bf16 hi/lo decompose
    {
        dim3 g(8, 8), blk(32, 8);
        const float* Ws[6] = {Wq, Wk, Wv, Wo, W1, W2};
        for (int w = 0; w < 6; w++)
            prep_w_kernel<<<g, blk>>>(Ws[w], p_wh + (size_t)w * 65536, p_wl + (size_t)w * 65536);
    }

    for (int l = 0; l < LVL; l++) {
        const int*   qi = qidx + l * NQ;
        const int*   ki = kidx + l * NK;
        const float* ml = mask + (size_t)l * NQ * NK;

        gather_ln_kernel<<<B * (NQ + NK), 256>>>(emb, p_upd, sys_s, sys_b, qi, ki, p_qn, p_kn);

        gemm_mma_kernel<0><<<dim3(B * NQ / 128, 2), 256, GEMM_SMEM_BYTES>>>(
            p_qn, p_wh + 0 * 65536, p_wl + 0 * 65536, nullptr, p_Q);
        gemm_mma_kernel<0><<<dim3(B * NK / 128, 2), 256, GEMM_SMEM_BYTES>>>(
            p_kn, p_wh + 1 * 65536, p_wl + 1 * 65536, nullptr, p_K);
        gemm_mma_kernel<0><<<dim3(B * NK / 128, 2), 256, GEMM_SMEM_BYTES>>>(
            p_kn, p_wh + 2 * 65536, p_wl + 2 * 65536, nullptr, p_V);

        attn_partial_kernel<<<dim3(NQ / 64, H, B * 4), 64>>>(p_Q, p_K, p_V, ml, p_pacc, p_pml);
        attn_merge_kernel<<<B * NQ, 256>>>(p_pacc, p_pml, p_ctx);

        gemm_mma_kernel<0><<<dim3(B * NQ / 128, 2), 256, GEMM_SMEM_BYTES>>>(
            p_ctx, p_wh + 3 * 65536, p_wl + 3 * 65536, nullptr, p_hraw);
        ln_rows_kernel<<<B * NQ, 256>>>(p_hraw, in_s, in_b, p_h);

        gemm_mma_kernel<2><<<dim3(B * NQ / 128, 2), 256, GEMM_SMEM_BYTES>>>(
            p_h, p_wh + 4 * 65536, p_wl + 4 * 65536, b1, p_g);
        gemm_mma_kernel<1><<<dim3(B * NQ / 128, 2), 256, GEMM_SMEM_BYTES>>>(
            p_g, p_wh + 5 * 65536, p_wl + 5 * 65536, b2, p_ffn);

        res_ln_kernel<<<B * NQ, 256>>>(p_h, p_ffn, out_s, out_b, eff_s, eff_b, p_res);

        scatter_kernel<<<B * NQ, 256>>>(p_res, qi, p_upd, outp);
    }
}

// round 4
// speedup vs baseline: 2.0722x; 1.5158x over previous
#include <cuda_runtime.h>
#include <cuda_bf16.h>
#include <math.h>
#include <stdint.h>

// Problem constants
#define B    32
#define NS   4096
#define D    256
#define H    4
#define LVL  6
#define NQ   512
#define NK   1024
#define DH   64
#define ATTN_SCALE 0.125f   // 1/sqrt(64)

// ---------------------------------------------------------------------------
// Scratch (no allocations allowed -> device globals)
// ---------------------------------------------------------------------------
__device__ float g_upd [(size_t)B * NS * D];   // working copy of update_tensor
__device__ float g_qn  [(size_t)B * NQ * D];
__device__ float g_kn  [(size_t)B * NK * D];
__device__ float g_ctx [(size_t)B * NQ * D];
__device__ float g_hraw[(size_t)B * NQ * D];
__device__ float g_h   [(size_t)B * NQ * D];
__device__ float g_gact[(size_t)B * NQ * D];
__device__ float g_ffn [(size_t)B * NQ * D];
__device__ float g_res [(size_t)B * NQ * D];

// bf16 hi/lo Q/K/V (written directly by the projection GEMM epilogues)
__device__ __nv_bfloat16 g_Qh[(size_t)B * NQ * D];
__device__ __nv_bfloat16 g_Ql[(size_t)B * NQ * D];
__device__ __nv_bfloat16 g_Kh[(size_t)B * NK * D];
__device__ __nv_bfloat16 g_Kl[(size_t)B * NK * D];
__device__ __nv_bfloat16 g_Vh[(size_t)B * NK * D];
__device__ __nv_bfloat16 g_Vl[(size_t)B * NK * D];

// transposed + bf16 hi/lo decomposed weights: [6][N=256][K=256]
__device__ __nv_bfloat16 g_Wt_hi[6 * 256 * 256];
__device__ __nv_bfloat16 g_Wt_lo[6 * 256 * 256];

// ---------------------------------------------------------------------------
// Helpers
// ---------------------------------------------------------------------------
__device__ __forceinline__ uint32_t smem_u32(const void* p) {
    uint32_t a;
    asm("{ .reg .u64 t; cvta.to.shared.u64 t, %1; cvt.u32.u64 %0, t; }" : "=r"(a) : "l"(p));
    return a;
}

__device__ __forceinline__ float gelu_tanh(float x) {
    float x3 = x * x * x;
    return 0.5f * x * (1.0f + tanhf(0.7978845608028654f * (x + 0.044715f * x3)));
}

__device__ __forceinline__ float2 ln_stats256(float v, float* red) {
    float a = v, b2 = v * v;
#pragma unroll
    for (int o = 16; o > 0; o >>= 1) {
        a  += __shfl_down_sync(0xffffffffu, a,  o);
        b2 += __shfl_down_sync(0xffffffffu, b2, o);
    }
    int w = threadIdx.x >> 5;
    if ((threadIdx.x & 31) == 0) { red[w] = a; red[8 + w] = b2; }
    __syncthreads();
    if (threadIdx.x == 0) {
        float s1 = 0.f, s2 = 0.f;
#pragma unroll
        for (int k = 0; k < 8; k++) { s1 += red[k]; s2 += red[8 + k]; }
        float mean = s1 * (1.0f / D);
        float var  = s2 * (1.0f / D) - mean * mean;
        red[16] = mean;
        red[17] = rsqrtf(var + 1e-5f);
    }
    __syncthreads();
    float2 r = make_float2(red[16], red[17]);
    __syncthreads();
    return r;
}

// mma.sync m16n8k16 bf16 (base-target legal; runs on HMMA pipe)
__device__ __forceinline__ void mma16816(float* c, const uint32_t* a, uint32_t b0, uint32_t b1) {
    asm volatile(
        "mma.sync.aligned.m16n8k16.row.col.f32.bf16.bf16.f32 "
        "{%0,%1,%2,%3}, {%4,%5,%6,%7}, {%8,%9}, {%0,%1,%2,%3};"
        : "+f"(c[0]), "+f"(c[1]), "+f"(c[2]), "+f"(c[3])
        : "r"(a[0]), "r"(a[1]), "r"(a[2]), "r"(a[3]), "r"(b0), "r"(b1));
}

__device__ __forceinline__ void ldmatrix_x4(uint32_t* r, uint32_t addr) {
    asm volatile("ldmatrix.sync.aligned.m8n8.x4.shared.b16 {%0,%1,%2,%3}, [%4];"
                 : "=r"(r[0]), "=r"(r[1]), "=r"(r[2]), "=r"(r[3]) : "r"(addr));
}
__device__ __forceinline__ void ldmatrix_x4_t(uint32_t* r, uint32_t addr) {
    asm volatile("ldmatrix.sync.aligned.m8n8.x4.trans.shared.b16 {%0,%1,%2,%3}, [%4];"
                 : "=r"(r[0]), "=r"(r[1]), "=r"(r[2]), "=r"(r[3]) : "r"(addr));
}

__device__ __forceinline__ uint32_t packbf2(float x, float y) {
    __nv_bfloat162 h = __floats2bfloat162_rn(x, y);
    return *reinterpret_cast<uint32_t*>(&h);
}

// ---------------------------------------------------------------------------
// init: copy update_tensor into working buffer, zero output
// ---------------------------------------------------------------------------
__global__ void init_kernel(const float* __restrict__ src, float* __restrict__ upd,
                            float* __restrict__ outp) {
    size_t i = (size_t)blockIdx.x * blockDim.x + threadIdx.x;
    float4 v = reinterpret_cast<const float4*>(src)[i];
    reinterpret_cast<float4*>(upd)[i]  = v;
    reinterpret_cast<float4*>(outp)[i] = make_float4(0.f, 0.f, 0.f, 0.f);
}

// ---------------------------------------------------------------------------
// weight prep: Wt[n][k] = W[k][n], decomposed into bf16 hi + lo
// ---------------------------------------------------------------------------
__global__ void prep_w_kernel(const float* __restrict__ W,
                              __nv_bfloat16* __restrict__ Th,
                              __nv_bfloat16* __restrict__ Tl) {
    __shared__ float t[32][33];
    int bx = blockIdx.x * 32;   // n tile
    int by = blockIdx.y * 32;   // k tile
#pragma unroll
    for (int i = threadIdx.y; i < 32; i += 8)
        t[i][threadIdx.x] = W[(size_t)(by + i) * 256 + bx + threadIdx.x];  // t[k][n]
    __syncthreads();
#pragma unroll
    for (int i = threadIdx.y; i < 32; i += 8) {
        float v = t[threadIdx.x][i];        // k = by+tx, n = bx+i
        __nv_bfloat16 h = __float2bfloat16(v);
        float r = v - __bfloat162float(h);
        size_t o = (size_t)(bx + i) * 256 + by + threadIdx.x;
        Th[o] = h;
        Tl[o] = __float2bfloat16(r);
    }
}

// ---------------------------------------------------------------------------
// gather + LayerNorm(sys)
// ---------------------------------------------------------------------------
__global__ void gather_ln_kernel(const float* __restrict__ emb,
                                 const float* __restrict__ upd,
                                 const float* __restrict__ sscale,
                                 const float* __restrict__ sbias,
                                 const int* __restrict__ qidx,
                                 const int* __restrict__ kidx,
                                 float* __restrict__ qn,
                                 float* __restrict__ kn) {
    __shared__ float red[18];
    int r = blockIdx.x;
    int t = threadIdx.x;
    int b, s;
    float* dst;
    if (r < B * NQ) {
        b = r / NQ;
        s = qidx[r % NQ];
        dst = qn + (size_t)r * D;
    } else {
        int r2 = r - B * NQ;
        b = r2 / NK;
        s = kidx[r2 % NK];
        dst = kn + (size_t)r2 * D;
    }
    float v = emb[(size_t)s * D + t] + upd[((size_t)b * NS + s) * D + t];
    float2 st = ln_stats256(v, red);
    dst[t] = (v - st.x) * st.y * sscale[t] + sbias[t];
}

// ---------------------------------------------------------------------------
// mma.sync GEMM: C[M,256] = A[M,256] @ W[256,256]
// split-3: D = Ah*Bh + Ah*Bl + Al*Bh   (~fp32 precision)
// CTA: 128(M) x 128(N), 8 warps (4 x 2), warp tile 32 x 64; K chunks of 64.
// MODE: 0 = plain, 1 = +bias, 2 = +bias+gelu
// OUT:  0 = fp32 C, 1 = bf16 hi/lo pair (Ch, Cl)
// ---------------------------------------------------------------------------
#define GPAD 72                                      // bf16 elems per smem row
#define GEMM_SMEM_BYTES (4 * 128 * GPAD * 2)         // 73728

template <int MODE, int OUT>
__global__ __launch_bounds__(256)
void gemm_mma_kernel(const float* __restrict__ A,
                     const __nv_bfloat16* __restrict__ Bth,
                     const __nv_bfloat16* __restrict__ Btl,
                     const float* __restrict__ bias,
                     float* __restrict__ C,
                     __nv_bfloat16* __restrict__ Ch,
                     __nv_bfloat16* __restrict__ Cl) {
    extern __shared__ char smem[];
    const uint32_t sb = smem_u32(smem);
    const int OFF_AH = 0;
    const int OFF_AL = 128 * GPAD * 2;
    const int OFF_BH = 2 * 128 * GPAD * 2;
    const int OFF_BL = 3 * 128 * GPAD * 2;

    int tid  = threadIdx.x;
    int wid  = tid >> 5, lane = tid & 31;
    int warpM = wid & 3;
    int warpN = wid >> 2;
    int mBase = blockIdx.x * 128;
    int nBase = blockIdx.y * 128;

    float acc[2][8][4];
#pragma unroll
    for (int i = 0; i < 2; i++)
#pragma unroll
        for (int j = 0; j < 8; j++)
#pragma unroll
            for (int k = 0; k < 4; k++) acc[i][j][k] = 0.f;

    for (int kc = 0; kc < 4; kc++) {
        int k0 = kc * 64;
#pragma unroll
        for (int it = 0; it < 16; it++) {
            int p = tid + it * 256;
            int m = p >> 5, j = p & 31;
            float2 v = *reinterpret_cast<const float2*>(
                A + (size_t)(mBase + m) * 256 + k0 + 2 * j);
            __nv_bfloat16 h0 = __float2bfloat16(v.x);
            __nv_bfloat16 h1 = __float2bfloat16(v.y);
            __nv_bfloat16 l0 = __float2bfloat16(v.x - __bfloat162float(h0));
            __nv_bfloat16 l1 = __float2bfloat16(v.y - __bfloat162float(h1));
            uint32_t hp = ((uint32_t)__bfloat16_as_ushort(h1) << 16) | __bfloat16_as_ushort(h0);
            uint32_t lp = ((uint32_t)__bfloat16_as_ushort(l1) << 16) | __bfloat16_as_ushort(l0);
            int off = (m * GPAD + 2 * j) * 2;
            *reinterpret_cast<uint32_t*>(smem + OFF_AH + off) = hp;
            *reinterpret_cast<uint32_t*>(smem + OFF_AL + off) = lp;
        }
#pragma unroll
        for (int it = 0; it < 16; it++) {
            int p = tid + it * 256;
            int n = p >> 5, j = p & 31;
            size_t go = (size_t)(nBase + n) * 256 + k0 + 2 * j;
            int off = (n * GPAD + 2 * j) * 2;
            *reinterpret_cast<uint32_t*>(smem + OFF_BH + off) =
                *reinterpret_cast<const uint32_t*>(Bth + go);
            *reinterpret_cast<uint32_t*>(smem + OFF_BL + off) =
                *reinterpret_cast<const uint32_t*>(Btl + go);
        }
        __syncthreads();

        for (int ks = 0; ks < 4; ks++) {
            int lrow = lane & 15;
            int lcol = ks * 16 + (lane >> 4) * 8;
            uint32_t ah[2][4], al[2][4];
#pragma unroll
            for (int mt = 0; mt < 2; mt++) {
                int row = warpM * 32 + mt * 16 + lrow;
                uint32_t ad = sb + (uint32_t)((row * GPAD + lcol) * 2);
                ldmatrix_x4(ah[mt], ad + OFF_AH);
                ldmatrix_x4(al[mt], ad + OFF_AL);
            }
#pragma unroll
            for (int nt2 = 0; nt2 < 4; nt2++) {
                int row = warpN * 64 + nt2 * 16 + lrow;
                uint32_t bd = sb + (uint32_t)((row * GPAD + lcol) * 2);
                uint32_t bh[4], bl[4];
                ldmatrix_x4(bh, bd + OFF_BH);
                ldmatrix_x4(bl, bd + OFF_BL);
#pragma unroll
                for (int mt = 0; mt < 2; mt++) {
                    mma16816(acc[mt][nt2 * 2 + 0], ah[mt], bh[0], bh[2]);
                    mma16816(acc[mt][nt2 * 2 + 0], ah[mt], bl[0], bl[2]);
                    mma16816(acc[mt][nt2 * 2 + 0], al[mt], bh[0], bh[2]);
                    mma16816(acc[mt][nt2 * 2 + 1], ah[mt], bh[1], bh[3]);
                    mma16816(acc[mt][nt2 * 2 + 1], ah[mt], bl[1], bl[3]);
                    mma16816(acc[mt][nt2 * 2 + 1], al[mt], bh[1], bh[3]);
                }
            }
        }
        __syncthreads();
    }

    // epilogue
    int g = lane >> 2, tig = lane & 3;
#pragma unroll
    for (int mt = 0; mt < 2; mt++) {
#pragma unroll
        for (int nt = 0; nt < 8; nt++) {
            int row0 = mBase + warpM * 32 + mt * 16 + g;
            int col  = nBase + warpN * 64 + nt * 8 + tig * 2;
            float v0 = acc[mt][nt][0], v1 = acc[mt][nt][1];
            float v2 = acc[mt][nt][2], v3 = acc[mt][nt][3];
            if (MODE >= 1) {
                float bb0 = bias[col], bb1 = bias[col + 1];
                v0 += bb0; v1 += bb1; v2 += bb0; v3 += bb1;
            }
            if (MODE == 2) {
                v0 = gelu_tanh(v0); v1 = gelu_tanh(v1);
                v2 = gelu_tanh(v2); v3 = gelu_tanh(v3);
            }
            if (OUT == 0) {
                *reinterpret_cast<float2*>(C + (size_t)row0 * 256 + col) = make_float2(v0, v1);
                *reinterpret_cast<float2*>(C + (size_t)(row0 + 8) * 256 + col) = make_float2(v2, v3);
            } else {
                __nv_bfloat16 h0 = __float2bfloat16(v0);
                __nv_bfloat16 h1 = __float2bfloat16(v1);
                __nv_bfloat16 h2 = __float2bfloat16(v2);
                __nv_bfloat16 h3 = __float2bfloat16(v3);
                uint32_t hp01 = ((uint32_t)__bfloat16_as_ushort(h1) << 16) | __bfloat16_as_ushort(h0);
                uint32_t hp23 = ((uint32_t)__bfloat16_as_ushort(h3) << 16) | __bfloat16_as_ushort(h2);
                uint32_t lp01 = packbf2(v0 - __bfloat162float(h0), v1 - __bfloat162float(h1));
                uint32_t lp23 = packbf2(v2 - __bfloat162float(h2), v3 - __bfloat162float(h3));
                *reinterpret_cast<uint32_t*>(Ch + (size_t)row0 * 256 + col) = hp01;
                *reinterpret_cast<uint32_t*>(Ch + (size_t)(row0 + 8) * 256 + col) = hp23;
                *reinterpret_cast<uint32_t*>(Cl + (size_t)row0 * 256 + col) = lp01;
                *reinterpret_cast<uint32_t*>(Cl + (size_t)(row0 + 8) * 256 + col) = lp23;
            }
        }
    }
}

// ---------------------------------------------------------------------------
// Fused flash attention on HMMA pipe.
// grid (NQ/64, H, B), 128 threads (4 warps); warp owns 16 query rows.
// QK^T: split-3 bf16 (Qh*Kh + Qh*Kl + Ql*Kh); PV: P(bf16) x V hi/lo split-2.
// ---------------------------------------------------------------------------
#define APAD 72
__global__ __launch_bounds__(128)
void attn_mma_kernel(const __nv_bfloat16* __restrict__ Qh, const __nv_bfloat16* __restrict__ Ql,
                     const __nv_bfloat16* __restrict__ Kh, const __nv_bfloat16* __restrict__ Kl,
                     const __nv_bfloat16* __restrict__ Vh, const __nv_bfloat16* __restrict__ Vl,
                     const float* __restrict__ mask, float* __restrict__ ctx) {
    __shared__ __align__(16) uint16_t Ksh[64][APAD];
    __shared__ __align__(16) uint16_t Ksl[64][APAD];
    __shared__ __align__(16) uint16_t Vsh[64][APAD];
    __shared__ __align__(16) uint16_t Vsl[64][APAD];
    __shared__ unsigned char Ms[64][68];

    int tid = threadIdx.x, wid = tid >> 5, lane = tid & 31;
    int q0 = blockIdx.x * 64, h = blockIdx.y, b = blockIdx.z;
    int g = lane >> 2, tig = lane & 3;
    int lrow = lane & 15, lco = (lane >> 4) * 8;

    // stage Q into K smem, pull A-fragments to registers
#pragma unroll
    for (int it = 0; it < 16; it++) {
        int p = tid + it * 128;
        int r = p >> 5, j = p & 31;
        size_t go = ((size_t)(b * NQ + q0 + r)) * D + h * DH + 2 * j;
        *reinterpret_cast<uint32_t*>(&Ksh[r][2 * j]) = *reinterpret_cast<const uint32_t*>(Qh + go);
        *reinterpret_cast<uint32_t*>(&Ksl[r][2 * j]) = *reinterpret_cast<const uint32_t*>(Ql + go);
    }
    __syncthreads();
    uint32_t qah[4][4], qal[4][4];
#pragma unroll
    for (int ks = 0; ks < 4; ks++) {
        uint32_t ah = smem_u32(&Ksh[wid * 16 + lrow][ks * 16 + lco]);
        uint32_t al = smem_u32(&Ksl[wid * 16 + lrow][ks * 16 + lco]);
        ldmatrix_x4(qah[ks], ah);
        ldmatrix_x4(qal[ks], al);
    }
    __syncthreads();

    float m0 = -1e30f, m1 = -1e30f, l0 = 0.f, l1 = 0.f;
    float oacc[8][4];
#pragma unroll
    for (int j = 0; j < 8; j++)
#pragma unroll
        for (int k = 0; k < 4; k++) oacc[j][k] = 0.f;

    for (int c = 0; c < 16; c++) {
        int kb = c * 64;
        // stage K/V hi/lo
#pragma unroll
        for (int it = 0; it < 16; it++) {
            int p = tid + it * 128;
            int r = p >> 5, j = p & 31;
            size_t go = ((size_t)(b * NK + kb + r)) * D + h * DH + 2 * j;
            *reinterpret_cast<uint32_t*>(&Ksh[r][2 * j]) = *reinterpret_cast<const uint32_t*>(Kh + go);
            *reinterpret_cast<uint32_t*>(&Ksl[r][2 * j]) = *reinterpret_cast<const uint32_t*>(Kl + go);
            *reinterpret_cast<uint32_t*>(&Vsh[r][2 * j]) = *reinterpret_cast<const uint32_t*>(Vh + go);
            *reinterpret_cast<uint32_t*>(&Vsl[r][2 * j]) = *reinterpret_cast<const uint32_t*>(Vl + go);
        }
        // stage mask as bytes
#pragma unroll
        for (int it = 0; it < 8; it++) {
            int p = tid + it * 128;
            int r = p >> 4, c4 = (p & 15) * 4;
            float4 mv = *reinterpret_cast<const float4*>(mask + (size_t)(q0 + r) * NK + kb + c4);
            uchar4 u;
            u.x = mv.x > 0.5f; u.y = mv.y > 0.5f; u.z = mv.z > 0.5f; u.w = mv.w > 0.5f;
            *reinterpret_cast<uchar4*>(&Ms[r][c4]) = u;
        }
        __syncthreads();

        // S = Q K^T  (split-3)
        float sacc[8][4];
#pragma unroll
        for (int j = 0; j < 8; j++)
#pragma unroll
            for (int k = 0; k < 4; k++) sacc[j][k] = 0.f;
#pragma unroll
        for (int ks = 0; ks < 4; ks++) {
#pragma unroll
            for (int nt = 0; nt < 4; nt++) {
                uint32_t bh[4], bl[4];
                uint32_t adh = smem_u32(&Ksh[nt * 16 + lrow][ks * 16 + lco]);
                uint32_t adl = smem_u32(&Ksl[nt * 16 + lrow][ks * 16 + lco]);
                ldmatrix_x4(bh, adh);
                ldmatrix_x4(bl, adl);
                mma16816(sacc[nt * 2 + 0], qah[ks], bh[0], bh[2]);
                mma16816(sacc[nt * 2 + 0], qah[ks], bl[0], bl[2]);
                mma16816(sacc[nt * 2 + 0], qal[ks], bh[0], bh[2]);
                mma16816(sacc[nt * 2 + 1], qah[ks], bh[1], bh[3]);
                mma16816(sacc[nt * 2 + 1], qah[ks], bl[1], bl[3]);
                mma16816(sacc[nt * 2 + 1], qal[ks], bh[1], bh[3]);
            }
        }

        // scale + mask
        int qr0 = wid * 16 + g, qr1 = qr0 + 8;
#pragma unroll
        for (int j = 0; j < 8; j++) {
            int col = j * 8 + 2 * tig;
            sacc[j][0] = Ms[qr0][col]     ? sacc[j][0] * ATTN_SCALE : -1e9f;
            sacc[j][1] = Ms[qr0][col + 1] ? sacc[j][1] * ATTN_SCALE : -1e9f;
            sacc[j][2] = Ms[qr1][col]     ? sacc[j][2] * ATTN_SCALE : -1e9f;
            sacc[j][3] = Ms[qr1][col + 1] ? sacc[j][3] * ATTN_SCALE : -1e9f;
        }

        // online softmax
        float mr0 = -1e30f, mr1 = -1e30f;
#pragma unroll
        for (int j = 0; j < 8; j++) {
            mr0 = fmaxf(mr0, fmaxf(sacc[j][0], sacc[j][1]));
            mr1 = fmaxf(mr1, fmaxf(sacc[j][2], sacc[j][3]));
        }
        mr0 = fmaxf(mr0, __shfl_xor_sync(0xffffffffu, mr0, 1));
        mr0 = fmaxf(mr0, __shfl_xor_sync(0xffffffffu, mr0, 2));
        mr1 = fmaxf(mr1, __shfl_xor_sync(0xffffffffu, mr1, 1));
        mr1 = fmaxf(mr1, __shfl_xor_sync(0xffffffffu, mr1, 2));
        float nm0 = fmaxf(m0, mr0), nm1 = fmaxf(m1, mr1);
        float cor0 = __expf(m0 - nm0), cor1 = __expf(m1 - nm1);
        m0 = nm0; m1 = nm1;

        float ps0 = 0.f, ps1 = 0.f;
        uint32_t pa[4][4];
#pragma unroll
        for (int j = 0; j < 8; j++) {
            float p0 = __expf(sacc[j][0] - m0);
            float p1 = __expf(sacc[j][1] - m0);
            float p2 = __expf(sacc[j][2] - m1);
            float p3 = __expf(sacc[j][3] - m1);
            ps0 += p0 + p1; ps1 += p2 + p3;
            int kc = j >> 1, o2 = (j & 1) * 2;
            pa[kc][o2 + 0] = packbf2(p0, p1);
            pa[kc][o2 + 1] = packbf2(p2, p3);
        }
        ps0 += __shfl_xor_sync(0xffffffffu, ps0, 1);
        ps0 += __shfl_xor_sync(0xffffffffu, ps0, 2);
        ps1 += __shfl_xor_sync(0xffffffffu, ps1, 1);
        ps1 += __shfl_xor_sync(0xffffffffu, ps1, 2);
        l0 = l0 * cor0 + ps0;
        l1 = l1 * cor1 + ps1;
#pragma unroll
        for (int j = 0; j < 8; j++) {
            oacc[j][0] *= cor0; oacc[j][1] *= cor0;
            oacc[j][2] *= cor1; oacc[j][3] *= cor1;
        }

        // O += P V   (V hi/lo via ldmatrix.trans)
        int vro = ((lane >> 4) << 3) + (lane & 7);
        int vcb = ((lane >> 3) & 1) << 3;
#pragma unroll
        for (int kc = 0; kc < 4; kc++) {
            int vr = 16 * kc + vro;
#pragma unroll
            for (int vt = 0; vt < 4; vt++) {
                uint32_t vh[4], vl[4];
                uint32_t adh = smem_u32(&Vsh[vr][vt * 16 + vcb]);
                uint32_t adl = smem_u32(&Vsl[vr][vt * 16 + vcb]);
                ldmatrix_x4_t(vh, adh);
                ldmatrix_x4_t(vl, adl);
                mma16816(oacc[vt * 2 + 0], pa[kc], vh[0], vh[2]);
                mma16816(oacc[vt * 2 + 0], pa[kc], vl[0], vl[2]);
                mma16816(oacc[vt * 2 + 1], pa[kc], vh[1], vh[3]);
                mma16816(oacc[vt * 2 + 1], pa[kc], vl[1], vl[3]);
            }
        }
        __syncthreads();
    }

    float inv0 = 1.0f / l0, inv1 = 1.0f / l1;
#pragma unroll
    for (int j = 0; j < 8; j++) {
        int col = h * DH + j * 8 + 2 * tig;
        size_t r0 = ((size_t)(b * NQ + q0 + wid * 16 + g)) * D + col;
        *reinterpret_cast<float2*>(ctx + r0) = make_float2(oacc[j][0] * inv0, oacc[j][1] * inv0);
        *reinterpret_cast<float2*>(ctx + r0 + 8 * D) = make_float2(oacc[j][2] * inv1, oacc[j][3] * inv1);
    }
}

// ---------------------------------------------------------------------------
// Plain row-LayerNorm
// ---------------------------------------------------------------------------
__global__ void ln_rows_kernel(const float* __restrict__ x,
                               const float* __restrict__ scale,
                               const float* __restrict__ bias,
                               float* __restrict__ out) {
    __shared__ float red[18];
    size_t idx = (size_t)blockIdx.x * D + threadIdx.x;
    float v = x[idx];
    float2 st = ln_stats256(v, red);
    out[idx] = (v - st.x) * st.y * scale[threadIdx.x] + bias[threadIdx.x];
}

// ---------------------------------------------------------------------------
// res = LN_eff( LN_outer( h + ffn ) )
// ---------------------------------------------------------------------------
__global__ void res_ln_kernel(const float* __restrict__ hbuf,
                              const float* __restrict__ ffn,
                              const float* __restrict__ os, const float* __restrict__ ob,
                              const float* __restrict__ es, const float* __restrict__ eb,
                              float* __restrict__ res) {
    __shared__ float red[18];
    size_t idx = (size_t)blockIdx.x * D + threadIdx.x;
    int t = threadIdx.x;
    float x = hbuf[idx] + ffn[idx];
    float2 st1 = ln_stats256(x, red);
    float y = (x - st1.x) * st1.y * os[t] + ob[t];
    float2 st2 = ln_stats256(y, red);
    res[idx] = (y - st2.x) * st2.y * es[t] + eb[t];
}

// ---------------------------------------------------------------------------
// scatter-add res into working copy and output
// ---------------------------------------------------------------------------
__global__ void scatter_kernel(const float* __restrict__ res,
                               const int* __restrict__ qidx,
                               float* __restrict__ upd,
                               float* __restrict__ outp) {
    int bi = blockIdx.x;
    int b = bi / NQ, i = bi % NQ;
    int s = qidx[i];
    float v = res[(size_t)bi * D + threadIdx.x];
    size_t off = ((size_t)b * NS + s) * D + threadIdx.x;
    atomicAdd(&upd[off], v);
    atomicAdd(&outp[off], v);
}

// ---------------------------------------------------------------------------
// launch
// ---------------------------------------------------------------------------
extern "C" void kernel_launch(void* const* d_in, const int* in_sizes, int n_in,
                              void* d_out, int out_size) {
    const float* update_tensor = (const float*)d_in[0];
    const float* emb   = (const float*)d_in[1];
    const float* mask  = (const float*)d_in[2];
    const float* Wq    = (const float*)d_in[3];
    const float* Wk    = (const float*)d_in[4];
    const float* Wv    = (const float*)d_in[5];
    const float* Wo    = (const float*)d_in[6];
    const float* W1    = (const float*)d_in[7];
    const float* b1    = (const float*)d_in[8];
    const float* W2    = (const float*)d_in[9];
    const float* b2    = (const float*)d_in[10];
    const float* sys_s = (const float*)d_in[11];
    const float* sys_b = (const float*)d_in[12];
    const float* eff_s = (const float*)d_in[13];
    const float* eff_b = (const float*)d_in[14];
    const float* in_s  = (const float*)d_in[15];
    const float* in_b  = (const float*)d_in[16];
    const float* out_s = (const float*)d_in[17];
    const float* out_b = (const float*)d_in[18];
    const int*   qidx  = (const int*)d_in[19];
    const int*   kidx  = (const int*)d_in[20];
    float* outp = (float*)d_out;

    float *p_upd, *p_qn, *p_kn, *p_ctx, *p_hraw, *p_h, *p_g, *p_ffn, *p_res;
    __nv_bfloat16 *p_wh, *p_wl, *p_Qh, *p_Ql, *p_Kh, *p_Kl, *p_Vh, *p_Vl;
    cudaGetSymbolAddress((void**)&p_upd,  g_upd);
    cudaGetSymbolAddress((void**)&p_qn,   g_qn);
    cudaGetSymbolAddress((void**)&p_kn,   g_kn);
    cudaGetSymbolAddress((void**)&p_ctx,  g_ctx);
    cudaGetSymbolAddress((void**)&p_hraw, g_hraw);
    cudaGetSymbolAddress((void**)&p_h,    g_h);
    cudaGetSymbolAddress((void**)&p_g,    g_gact);
    cudaGetSymbolAddress((void**)&p_ffn,  g_ffn);
    cudaGetSymbolAddress((void**)&p_res,  g_res);
    cudaGetSymbolAddress((void**)&p_wh,   g_Wt_hi);
    cudaGetSymbolAddress((void**)&p_wl,   g_Wt_lo);
    cudaGetSymbolAddress((void**)&p_Qh,   g_Qh);
    cudaGetSymbolAddress((void**)&p_Ql,   g_Ql);
    cudaGetSymbolAddress((void**)&p_Kh,   g_Kh);
    cudaGetSymbolAddress((void**)&p_Kl,   g_Kl);
    cudaGetSymbolAddress((void**)&p_Vh,   g_Vh);
    cudaGetSymbolAddress((void**)&p_Vl,   g_Vl);

    cudaFuncSetAttribute(gemm_mma_kernel<0,0>, cudaFuncAttributeMaxDynamicSharedMemorySize, GEMM_SMEM_BYTES);
    cudaFuncSetAttribute(gemm_mma_kernel<0,1>, cudaFuncAttributeMaxDynamicSharedMemorySize, GEMM_SMEM_BYTES);
    cudaFuncSetAttribute(gemm_mma_kernel<1,0>, cudaFuncAttributeMaxDynamicSharedMemorySize, GEMM_SMEM_BYTES);
    cudaFuncSetAttribute(gemm_mma_kernel<2,0>, cudaFuncAttributeMaxDynamicSharedMemorySize, GEMM_SMEM_BYTES);

    // copy mutable state + zero output
    {
        int n4 = (B * NS * D) / 4;
        init_kernel<<<n4 / 256, 256>>>(update_tensor, p_upd, outp);
    }

    // prep weights: transpose + bf16 hi/lo decompose
    {
        dim3 g(8, 8), blk(32, 8);
        const float* Ws[6] = {Wq, Wk, Wv, Wo, W1, W2};
        for (int w = 0; w < 6; w++)
            prep_w_kernel<<<g, blk>>>(Ws[w], p_wh + (size_t)w * 65536, p_wl + (size_t)w * 65536);
    }

    for (int l = 0; l < LVL; l++) {
        const int*   qi = qidx + l * NQ;
        const int*   ki = kidx + l * NK;
        const float* ml = mask + (size_t)l * NQ * NK;

        gather_ln_kernel<<<B * (NQ + NK), 256>>>(emb, p_upd, sys_s, sys_b, qi, ki, p_qn, p_kn);

        gemm_mma_kernel<0,1><<<dim3(B * NQ / 128, 2), 256, GEMM_SMEM_BYTES>>>(
            p_qn, p_wh + 0 * 65536, p_wl + 0 * 65536, nullptr, nullptr, p_Qh, p_Ql);
        gemm_mma_kernel<0,1><<<dim3(B * NK / 128, 2), 256, GEMM_SMEM_BYTES>>>(
            p_kn, p_wh + 1 * 65536, p_wl + 1 * 65536, nullptr, nullptr, p_Kh, p_Kl);
        gemm_mma_kernel<0,1><<<dim3(B * NK / 128, 2), 256, GEMM_SMEM_BYTES>>>(
            p_kn, p_wh + 2 * 65536, p_wl + 2 * 65536, nullptr, nullptr, p_Vh, p_Vl);

        attn_mma_kernel<<<dim3(NQ / 64, H, B), 128>>>(
            p_Qh, p_Ql, p_Kh, p_Kl, p_Vh, p_Vl, ml, p_ctx);

        gemm_mma_kernel<0,0><<<dim3(B * NQ / 128, 2), 256, GEMM_SMEM_BYTES>>>(
            p_ctx, p_wh + 3 * 65536, p_wl + 3 * 65536, nullptr, p_hraw, nullptr, nullptr);
        ln_rows_kernel<<<B * NQ, 256>>>(p_hraw, in_s, in_b, p_h);

        gemm_mma_kernel<2,0><<<dim3(B * NQ / 128, 2), 256, GEMM_SMEM_BYTES>>>(
            p_h, p_wh + 4 * 65536, p_wl + 4 * 65536, b1, p_g, nullptr, nullptr);
        gemm_mma_kernel<1,0><<<dim3(B * NQ / 128, 2), 256, GEMM_SMEM_BYTES>>>(
            p_g, p_wh + 5 * 65536, p_wl + 5 * 65536, b2, p_ffn, nullptr, nullptr);

        res_ln_kernel<<<B * NQ, 256>>>(p_h, p_ffn, out_s, out_b, eff_s, eff_b, p_res);

        scatter_kernel<<<B * NQ, 256>>>(p_res, qi, p_upd, outp);
    }
}

// round 5
// speedup vs baseline: 2.4089x; 1.1625x over previous
#include <cuda_runtime.h>
#include <cuda_bf16.h>
#include <math.h>
#include <stdint.h>

// Problem constants
#define B    32
#define NS   4096
#define D    256
#define H    4
#define LVL  6
#define NQ   512
#define NK   1024
#define DH   64
#define ATTN_SCALE 0.125f   // 1/sqrt(64)

// ---------------------------------------------------------------------------
// Scratch (no allocations allowed -> device globals)
// ---------------------------------------------------------------------------
__device__ float g_upd [(size_t)B * NS * D];   // working copy of update_tensor
__device__ float g_hraw[(size_t)B * NQ * D];
__device__ float g_ffn [(size_t)B * NQ * D];

// bf16 hi/lo activations
__device__ __nv_bfloat16 g_qnh[(size_t)B * NQ * D];
__device__ __nv_bfloat16 g_qnl[(size_t)B * NQ * D];
__device__ __nv_bfloat16 g_knh[(size_t)B * NK * D];
__device__ __nv_bfloat16 g_knl[(size_t)B * NK * D];
__device__ __nv_bfloat16 g_Qh [(size_t)B * NQ * D];
__device__ __nv_bfloat16 g_Ql [(size_t)B * NQ * D];
__device__ __nv_bfloat16 g_Kh [(size_t)B * NK * D];
__device__ __nv_bfloat16 g_Kl [(size_t)B * NK * D];
__device__ __nv_bfloat16 g_Vh [(size_t)B * NK * D];
__device__ __nv_bfloat16 g_Vl [(size_t)B * NK * D];
__device__ __nv_bfloat16 g_ctxh[(size_t)B * NQ * D];
__device__ __nv_bfloat16 g_ctxl[(size_t)B * NQ * D];
__device__ __nv_bfloat16 g_hh [(size_t)B * NQ * D];
__device__ __nv_bfloat16 g_hl [(size_t)B * NQ * D];
__device__ __nv_bfloat16 g_gh [(size_t)B * NQ * D];
__device__ __nv_bfloat16 g_gl [(size_t)B * NQ * D];

// transposed + bf16 hi/lo decomposed weights: [6][N=256][K=256]
__device__ __nv_bfloat16 g_Wt_hi[6 * 256 * 256];
__device__ __nv_bfloat16 g_Wt_lo[6 * 256 * 256];

// mask as bytes, all levels
__device__ unsigned char g_maskb[(size_t)LVL * NQ * NK];

// ---------------------------------------------------------------------------
// Helpers
// ---------------------------------------------------------------------------
__device__ __forceinline__ uint32_t smem_u32(const void* p) {
    uint32_t a;
    asm("{ .reg .u64 t; cvta.to.shared.u64 t, %1; cvt.u32.u64 %0, t; }" : "=r"(a) : "l"(p));
    return a;
}

__device__ __forceinline__ float gelu_tanh(float x) {
    float x3 = x * x * x;
    return 0.5f * x * (1.0f + tanhf(0.7978845608028654f * (x + 0.044715f * x3)));
}

__device__ __forceinline__ float2 ln_stats256(float v, float* red) {
    float a = v, b2 = v * v;
#pragma unroll
    for (int o = 16; o > 0; o >>= 1) {
        a  += __shfl_down_sync(0xffffffffu, a,  o);
        b2 += __shfl_down_sync(0xffffffffu, b2, o);
    }
    int w = threadIdx.x >> 5;
    if ((threadIdx.x & 31) == 0) { red[w] = a; red[8 + w] = b2; }
    __syncthreads();
    if (threadIdx.x == 0) {
        float s1 = 0.f, s2 = 0.f;
#pragma unroll
        for (int k = 0; k < 8; k++) { s1 += red[k]; s2 += red[8 + k]; }
        float mean = s1 * (1.0f / D);
        float var  = s2 * (1.0f / D) - mean * mean;
        red[16] = mean;
        red[17] = rsqrtf(var + 1e-5f);
    }
    __syncthreads();
    float2 r = make_float2(red[16], red[17]);
    __syncthreads();
    return r;
}

// mma.sync m16n8k16 bf16 (HMMA pipe)
__device__ __forceinline__ void mma16816(float* c, const uint32_t* a, uint32_t b0, uint32_t b1) {
    asm volatile(
        "mma.sync.aligned.m16n8k16.row.col.f32.bf16.bf16.f32 "
        "{%0,%1,%2,%3}, {%4,%5,%6,%7}, {%8,%9}, {%0,%1,%2,%3};"
        : "+f"(c[0]), "+f"(c[1]), "+f"(c[2]), "+f"(c[3])
        : "r"(a[0]), "r"(a[1]), "r"(a[2]), "r"(a[3]), "r"(b0), "r"(b1));
}

__device__ __forceinline__ void ldmatrix_x4(uint32_t* r, uint32_t addr) {
    asm volatile("ldmatrix.sync.aligned.m8n8.x4.shared.b16 {%0,%1,%2,%3}, [%4];"
                 : "=r"(r[0]), "=r"(r[1]), "=r"(r[2]), "=r"(r[3]) : "r"(addr));
}
__device__ __forceinline__ void ldmatrix_x4_t(uint32_t* r, uint32_t addr) {
    asm volatile("ldmatrix.sync.aligned.m8n8.x4.trans.shared.b16 {%0,%1,%2,%3}, [%4];"
                 : "=r"(r[0]), "=r"(r[1]), "=r"(r[2]), "=r"(r[3]) : "r"(addr));
}

__device__ __forceinline__ uint32_t packbf2(float x, float y) {
    __nv_bfloat162 h = __floats2bfloat162_rn(x, y);
    return *reinterpret_cast<uint32_t*>(&h);
}

// split a float pair into packed hi + lo bf16x2
__device__ __forceinline__ void split2(float x, float y, uint32_t& hp, uint32_t& lp) {
    __nv_bfloat16 h0 = __float2bfloat16(x);
    __nv_bfloat16 h1 = __float2bfloat16(y);
    hp = ((uint32_t)__bfloat16_as_ushort(h1) << 16) | __bfloat16_as_ushort(h0);
    lp = packbf2(x - __bfloat162float(h0), y - __bfloat162float(h1));
}

#define CP_ASYNC16(dst, src) \
    asm volatile("cp.async.cg.shared.global [%0], [%1], 16;" :: "r"(dst), "l"(src))
#define CP_COMMIT() asm volatile("cp.async.commit_group;" ::: "memory")
#define CP_WAIT1()  asm volatile("cp.async.wait_group 1;" ::: "memory")
#define CP_WAIT0()  asm volatile("cp.async.wait_group 0;" ::: "memory")

// ---------------------------------------------------------------------------
// init: copy update_tensor into working buffer, zero output
// ---------------------------------------------------------------------------
__global__ void init_kernel(const float* __restrict__ src, float* __restrict__ upd,
                            float* __restrict__ outp) {
    size_t i = (size_t)blockIdx.x * blockDim.x + threadIdx.x;
    float4 v = reinterpret_cast<const float4*>(src)[i];
    reinterpret_cast<float4*>(upd)[i]  = v;
    reinterpret_cast<float4*>(outp)[i] = make_float4(0.f, 0.f, 0.f, 0.f);
}

// ---------------------------------------------------------------------------
// mask -> bytes, all levels at once
// ---------------------------------------------------------------------------
__global__ void maskb_kernel(const float* __restrict__ mask, unsigned char* __restrict__ mb) {
    size_t i = (size_t)blockIdx.x * 256 + threadIdx.x;
    float4 v = reinterpret_cast<const float4*>(mask)[i];
    uchar4 u;
    u.x = v.x > 0.5f; u.y = v.y > 0.5f; u.z = v.z > 0.5f; u.w = v.w > 0.5f;
    reinterpret_cast<uchar4*>(mb)[i] = u;
}

// ---------------------------------------------------------------------------
// weight prep (all 6 weights in one launch): Wt[n][k] = W[k][n], bf16 hi/lo
// grid (8, 8, 6), block (32, 8)
// ---------------------------------------------------------------------------
struct WPtrs { const float* w[6]; };

__global__ void prep_w_all_kernel(WPtrs ws,
                                  __nv_bfloat16* __restrict__ Th,
                                  __nv_bfloat16* __restrict__ Tl) {
    __shared__ float t[32][33];
    int wsel = blockIdx.z;
    const float* W = ws.w[wsel];
    __nv_bfloat16* Thw = Th + (size_t)wsel * 65536;
    __nv_bfloat16* Tlw = Tl + (size_t)wsel * 65536;
    int bx = blockIdx.x * 32;   // n tile
    int by = blockIdx.y * 32;   // k tile
#pragma unroll
    for (int i = threadIdx.y; i < 32; i += 8)
        t[i][threadIdx.x] = W[(size_t)(by + i) * 256 + bx + threadIdx.x];
    __syncthreads();
#pragma unroll
    for (int i = threadIdx.y; i < 32; i += 8) {
        float v = t[threadIdx.x][i];
        __nv_bfloat16 h = __float2bfloat16(v);
        float r = v - __bfloat162float(h);
        size_t o = (size_t)(bx + i) * 256 + by + threadIdx.x;
        Thw[o] = h;
        Tlw[o] = __float2bfloat16(r);
    }
}

// ---------------------------------------------------------------------------
// gather + LayerNorm(sys) -> bf16 hi/lo
// ---------------------------------------------------------------------------
__global__ void gather_ln_kernel(const float* __restrict__ emb,
                                 const float* __restrict__ upd,
                                 const float* __restrict__ sscale,
                                 const float* __restrict__ sbias,
                                 const int* __restrict__ qidx,
                                 const int* __restrict__ kidx,
                                 __nv_bfloat16* __restrict__ qnh,
                                 __nv_bfloat16* __restrict__ qnl,
                                 __nv_bfloat16* __restrict__ knh,
                                 __nv_bfloat16* __restrict__ knl) {
    __shared__ float red[18];
    int r = blockIdx.x;
    int t = threadIdx.x;
    int b, s;
    __nv_bfloat16 *dh, *dl;
    size_t off;
    if (r < B * NQ) {
        b = r / NQ;
        s = qidx[r % NQ];
        off = (size_t)r * D;
        dh = qnh; dl = qnl;
    } else {
        int r2 = r - B * NQ;
        b = r2 / NK;
        s = kidx[r2 % NK];
        off = (size_t)r2 * D;
        dh = knh; dl = knl;
    }
    float v = emb[(size_t)s * D + t] + upd[((size_t)b * NS + s) * D + t];
    float2 st = ln_stats256(v, red);
    float y = (v - st.x) * st.y * sscale[t] + sbias[t];
    __nv_bfloat16 h = __float2bfloat16(y);
    dh[off + t] = h;
    dl[off + t] = __float2bfloat16(y - __bfloat162float(h));
}

// ---------------------------------------------------------------------------
// mma.sync GEMM, bf16 hi/lo A operand, cp.async 2-stage pipeline.
// C[M,256] = A[M,256] @ W[256,256];  split-3: Ah*Bh + Ah*Bl + Al*Bh
// CTA 128x128, 8 warps (4x2), warp tile 32x64; K chunks of 64.
// MODE: 0 plain, 1 +bias, 2 +bias+gelu.  OUT: 0 fp32 C, 1 bf16 hi/lo.
// ---------------------------------------------------------------------------
#define GPAD 72
#define TILE_B (128 * GPAD * 2)      // 18432
#define STAGE_B (4 * TILE_B)         // 73728
#define GEMM_SMEM_BYTES (2 * STAGE_B)

__device__ __forceinline__ void gemm_issue_chunk(
    uint32_t stage, int tid,
    const __nv_bfloat16* Ah, const __nv_bfloat16* Al,
    const __nv_bfloat16* Bh, const __nv_bfloat16* Bl,
    int mBase, int nBase, int k0)
{
    const __nv_bfloat16* srcs[4] = {Ah, Al, Bh, Bl};
#pragma unroll
    for (int t4 = 0; t4 < 4; t4++) {
        int base = (t4 < 2) ? mBase : nBase;
#pragma unroll
        for (int it = 0; it < 4; it++) {
            int seg = tid + it * 256;
            int row = seg >> 3, j = seg & 7;
            const void* gp = srcs[t4] + (size_t)(base + row) * 256 + k0 + j * 8;
            uint32_t d = stage + t4 * TILE_B + (uint32_t)((row * GPAD + j * 8) * 2);
            CP_ASYNC16(d, gp);
        }
    }
    CP_COMMIT();
}

template <int MODE, int OUT>
__global__ __launch_bounds__(256)
void gemm_bf16_kernel(const __nv_bfloat16* __restrict__ Ah,
                      const __nv_bfloat16* __restrict__ Al,
                      const __nv_bfloat16* __restrict__ Bth,
                      const __nv_bfloat16* __restrict__ Btl,
                      const float* __restrict__ bias,
                      float* __restrict__ C,
                      __nv_bfloat16* __restrict__ Ch,
                      __nv_bfloat16* __restrict__ Cl) {
    extern __shared__ char smem[];
    const uint32_t sb = smem_u32(smem);

    int tid  = threadIdx.x;
    int wid  = tid >> 5, lane = tid & 31;
    int warpM = wid & 3;
    int warpN = wid >> 2;
    int mBase = blockIdx.x * 128;
    int nBase = blockIdx.y * 128;

    float acc[2][8][4];
#pragma unroll
    for (int i = 0; i < 2; i++)
#pragma unroll
        for (int j = 0; j < 8; j++)
#pragma unroll
            for (int k = 0; k < 4; k++) acc[i][j][k] = 0.f;

    gemm_issue_chunk(sb, tid, Ah, Al, Bth, Btl, mBase, nBase, 0);

    for (int kc = 0; kc < 4; kc++) {
        if (kc < 3)
            gemm_issue_chunk(sb + ((kc + 1) & 1) * STAGE_B, tid, Ah, Al, Bth, Btl,
                             mBase, nBase, (kc + 1) * 64);
        if (kc < 3) { CP_WAIT1(); } else { CP_WAIT0(); }
        __syncthreads();

        uint32_t st = sb + (kc & 1) * STAGE_B;
        for (int ks = 0; ks < 4; ks++) {
            int lrow = lane & 15;
            int lcol = ks * 16 + (lane >> 4) * 8;
            uint32_t ah[2][4], al[2][4];
#pragma unroll
            for (int mt = 0; mt < 2; mt++) {
                int row = warpM * 32 + mt * 16 + lrow;
                uint32_t ad = st + (uint32_t)((row * GPAD + lcol) * 2);
                ldmatrix_x4(ah[mt], ad);
                ldmatrix_x4(al[mt], ad + TILE_B);
            }
#pragma unroll
            for (int nt2 = 0; nt2 < 4; nt2++) {
                int row = warpN * 64 + nt2 * 16 + lrow;
                uint32_t bd = st + 2 * TILE_B + (uint32_t)((row * GPAD + lcol) * 2);
                uint32_t bh[4], bl[4];
                ldmatrix_x4(bh, bd);
                ldmatrix_x4(bl, bd + TILE_B);
#pragma unroll
                for (int mt = 0; mt < 2; mt++) {
                    mma16816(acc[mt][nt2 * 2 + 0], ah[mt], bh[0], bh[2]);
                    mma16816(acc[mt][nt2 * 2 + 0], ah[mt], bl[0], bl[2]);
                    mma16816(acc[mt][nt2 * 2 + 0], al[mt], bh[0], bh[2]);
                    mma16816(acc[mt][nt2 * 2 + 1], ah[mt], bh[1], bh[3]);
                    mma16816(acc[mt][nt2 * 2 + 1], ah[mt], bl[1], bl[3]);
                    mma16816(acc[mt][nt2 * 2 + 1], al[mt], bh[1], bh[3]);
                }
            }
        }
        __syncthreads();
    }

    // epilogue
    int g = lane >> 2, tig = lane & 3;
#pragma unroll
    for (int mt = 0; mt < 2; mt++) {
#pragma unroll
        for (int nt = 0; nt < 8; nt++) {
            int row0 = mBase + warpM * 32 + mt * 16 + g;
            int col  = nBase + warpN * 64 + nt * 8 + tig * 2;
            float v0 = acc[mt][nt][0], v1 = acc[mt][nt][1];
            float v2 = acc[mt][nt][2], v3 = acc[mt][nt][3];
            if (MODE >= 1) {
                float bb0 = bias[col], bb1 = bias[col + 1];
                v0 += bb0; v1 += bb1; v2 += bb0; v3 += bb1;
            }
            if (MODE == 2) {
                v0 = gelu_tanh(v0); v1 = gelu_tanh(v1);
                v2 = gelu_tanh(v2); v3 = gelu_tanh(v3);
            }
            if (OUT == 0) {
                *reinterpret_cast<float2*>(C + (size_t)row0 * 256 + col) = make_float2(v0, v1);
                *reinterpret_cast<float2*>(C + (size_t)(row0 + 8) * 256 + col) = make_float2(v2, v3);
            } else {
                uint32_t hp01, lp01, hp23, lp23;
                split2(v0, v1, hp01, lp01);
                split2(v2, v3, hp23, lp23);
                *reinterpret_cast<uint32_t*>(Ch + (size_t)row0 * 256 + col) = hp01;
                *reinterpret_cast<uint32_t*>(Ch + (size_t)(row0 + 8) * 256 + col) = hp23;
                *reinterpret_cast<uint32_t*>(Cl + (size_t)row0 * 256 + col) = lp01;
                *reinterpret_cast<uint32_t*>(Cl + (size_t)(row0 + 8) * 256 + col) = lp23;
            }
        }
    }
}

// ---------------------------------------------------------------------------
// Fused flash attention on HMMA pipe.
// grid (NQ/128, H, B), 256 threads (8 warps); warp owns 16 query rows.
// QK^T: split-3; PV: P hi/lo split-3 style (Ph*Vh + Ph*Vl + Pl*Vh).
// ctx written as bf16 hi/lo.
// ---------------------------------------------------------------------------
#define APAD 72
__global__ __launch_bounds__(256)
void attn_mma_kernel(const __nv_bfloat16* __restrict__ Qh, const __nv_bfloat16* __restrict__ Ql,
                     const __nv_bfloat16* __restrict__ Kh, const __nv_bfloat16* __restrict__ Kl,
                     const __nv_bfloat16* __restrict__ Vh, const __nv_bfloat16* __restrict__ Vl,
                     const unsigned char* __restrict__ maskb,
                     __nv_bfloat16* __restrict__ ctxh, __nv_bfloat16* __restrict__ ctxl) {
    __shared__ __align__(16) uint16_t Ksh[64][APAD];
    __shared__ __align__(16) uint16_t Ksl[64][APAD];
    __shared__ __align__(16) uint16_t Vsh[64][APAD];
    __shared__ __align__(16) uint16_t Vsl[64][APAD];
    __shared__ __align__(16) unsigned char Ms[128][80];

    int tid = threadIdx.x, wid = tid >> 5, lane = tid & 31;
    int q0 = blockIdx.x * 128, h = blockIdx.y, b = blockIdx.z;
    int g = lane >> 2, tig = lane & 3;
    int lrow = lane & 15, lco = (lane >> 4) * 8;

    // Q fragments directly from gmem
    uint32_t qah[4][4], qal[4][4];
#pragma unroll
    for (int ks = 0; ks < 4; ks++) {
#pragma unroll
        for (int i = 0; i < 4; i++) {
            int row = q0 + wid * 16 + g + (i & 1) * 8;
            int col = h * DH + ks * 16 + tig * 2 + (i >> 1) * 8;
            size_t o = ((size_t)(b * NQ + row)) * D + col;
            qah[ks][i] = *reinterpret_cast<const uint32_t*>(Qh + o);
            qal[ks][i] = *reinterpret_cast<const uint32_t*>(Ql + o);
        }
    }

    float m0 = -1e30f, m1 = -1e30f, l0 = 0.f, l1 = 0.f;
    float oacc[8][4];
#pragma unroll
    for (int j = 0; j < 8; j++)
#pragma unroll
        for (int k = 0; k < 4; k++) oacc[j][k] = 0.f;

    for (int c = 0; c < 16; c++) {
        int kb = c * 64;
        // stage K/V hi/lo: 2 x uint4 per array per thread
#pragma unroll
        for (int it = 0; it < 2; it++) {
            int seg = tid + it * 256;       // 512 segments
            int r = seg >> 3, j = seg & 7;
            size_t go = ((size_t)(b * NK + kb + r)) * D + h * DH + j * 8;
            *reinterpret_cast<uint4*>(&Ksh[r][j * 8]) = *reinterpret_cast<const uint4*>(Kh + go);
            *reinterpret_cast<uint4*>(&Ksl[r][j * 8]) = *reinterpret_cast<const uint4*>(Kl + go);
            *reinterpret_cast<uint4*>(&Vsh[r][j * 8]) = *reinterpret_cast<const uint4*>(Vh + go);
            *reinterpret_cast<uint4*>(&Vsl[r][j * 8]) = *reinterpret_cast<const uint4*>(Vl + go);
        }
        // stage mask bytes: 128 rows x 64 cols
#pragma unroll
        for (int it = 0; it < 2; it++) {
            int seg = tid + it * 256;       // 512 segments of 16B
            int r = seg >> 2, j = seg & 3;
            *reinterpret_cast<uint4*>(&Ms[r][j * 16]) =
                *reinterpret_cast<const uint4*>(maskb + (size_t)(q0 + r) * NK + kb + j * 16);
        }
        __syncthreads();

        // S = Q K^T (split-3)
        float sacc[8][4];
#pragma unroll
        for (int j = 0; j < 8; j++)
#pragma unroll
            for (int k = 0; k < 4; k++) sacc[j][k] = 0.f;
#pragma unroll
        for (int ks = 0; ks < 4; ks++) {
#pragma unroll
            for (int nt = 0; nt < 4; nt++) {
                uint32_t bh[4], bl[4];
                uint32_t adh = smem_u32(&Ksh[nt * 16 + lrow][ks * 16 + lco]);
                uint32_t adl = smem_u32(&Ksl[nt * 16 + lrow][ks * 16 + lco]);
                ldmatrix_x4(bh, adh);
                ldmatrix_x4(bl, adl);
                mma16816(sacc[nt * 2 + 0], qah[ks], bh[0], bh[2]);
                mma16816(sacc[nt * 2 + 0], qah[ks], bl[0], bl[2]);
                mma16816(sacc[nt * 2 + 0], qal[ks], bh[0], bh[2]);
                mma16816(sacc[nt * 2 + 1], qah[ks], bh[1], bh[3]);
                mma16816(sacc[nt * 2 + 1], qah[ks], bl[1], bl[3]);
                mma16816(sacc[nt * 2 + 1], qal[ks], bh[1], bh[3]);
            }
        }

        // scale + mask
        int qr0 = wid * 16 + g, qr1 = qr0 + 8;
#pragma unroll
        for (int j = 0; j < 8; j++) {
            int col = j * 8 + 2 * tig;
            sacc[j][0] = Ms[qr0][col]     ? sacc[j][0] * ATTN_SCALE : -1e9f;
            sacc[j][1] = Ms[qr0][col + 1] ? sacc[j][1] * ATTN_SCALE : -1e9f;
            sacc[j][2] = Ms[qr1][col]     ? sacc[j][2] * ATTN_SCALE : -1e9f;
            sacc[j][3] = Ms[qr1][col + 1] ? sacc[j][3] * ATTN_SCALE : -1e9f;
        }

        // online softmax
        float mr0 = -1e30f, mr1 = -1e30f;
#pragma unroll
        for (int j = 0; j < 8; j++) {
            mr0 = fmaxf(mr0, fmaxf(sacc[j][0], sacc[j][1]));
            mr1 = fmaxf(mr1, fmaxf(sacc[j][2], sacc[j][3]));
        }
        mr0 = fmaxf(mr0, __shfl_xor_sync(0xffffffffu, mr0, 1));
        mr0 = fmaxf(mr0, __shfl_xor_sync(0xffffffffu, mr0, 2));
        mr1 = fmaxf(mr1, __shfl_xor_sync(0xffffffffu, mr1, 1));
        mr1 = fmaxf(mr1, __shfl_xor_sync(0xffffffffu, mr1, 2));
        float nm0 = fmaxf(m0, mr0), nm1 = fmaxf(m1, mr1);
        float cor0 = __expf(m0 - nm0), cor1 = __expf(m1 - nm1);
        m0 = nm0; m1 = nm1;

        float ps0 = 0.f, ps1 = 0.f;
        uint32_t pa[4][4], pl[4][4];
#pragma unroll
        for (int j = 0; j < 8; j++) {
            float p0 = __expf(sacc[j][0] - m0);
            float p1 = __expf(sacc[j][1] - m0);
            float p2 = __expf(sacc[j][2] - m1);
            float p3 = __expf(sacc[j][3] - m1);
            ps0 += p0 + p1; ps1 += p2 + p3;
            int kc = j >> 1, o2 = (j & 1) * 2;
            uint32_t hp, lp;
            split2(p0, p1, hp, lp);
            pa[kc][o2 + 0] = hp; pl[kc][o2 + 0] = lp;
            split2(p2, p3, hp, lp);
            pa[kc][o2 + 1] = hp; pl[kc][o2 + 1] = lp;
        }
        ps0 += __shfl_xor_sync(0xffffffffu, ps0, 1);
        ps0 += __shfl_xor_sync(0xffffffffu, ps0, 2);
        ps1 += __shfl_xor_sync(0xffffffffu, ps1, 1);
        ps1 += __shfl_xor_sync(0xffffffffu, ps1, 2);
        l0 = l0 * cor0 + ps0;
        l1 = l1 * cor1 + ps1;
#pragma unroll
        for (int j = 0; j < 8; j++) {
            oacc[j][0] *= cor0; oacc[j][1] *= cor0;
            oacc[j][2] *= cor1; oacc[j][3] *= cor1;
        }

        // O += P V  (P hi/lo, V hi/lo; three-term split)
        int vro = ((lane >> 4) << 3) + (lane & 7);
        int vcb = ((lane >> 3) & 1) << 3;
#pragma unroll
        for (int kc = 0; kc < 4; kc++) {
            int vr = 16 * kc + vro;
#pragma unroll
            for (int vt = 0; vt < 4; vt++) {
                uint32_t vh[4], vl[4];
                uint32_t adh = smem_u32(&Vsh[vr][vt * 16 + vcb]);
                uint32_t adl = smem_u32(&Vsl[vr][vt * 16 + vcb]);
                ldmatrix_x4_t(vh, adh);
                ldmatrix_x4_t(vl, adl);
                mma16816(oacc[vt * 2 + 0], pa[kc], vh[0], vh[2]);
                mma16816(oacc[vt * 2 + 0], pa[kc], vl[0], vl[2]);
                mma16816(oacc[vt * 2 + 0], pl[kc], vh[0], vh[2]);
                mma16816(oacc[vt * 2 + 1], pa[kc], vh[1], vh[3]);
                mma16816(oacc[vt * 2 + 1], pa[kc], vl[1], vl[3]);
                mma16816(oacc[vt * 2 + 1], pl[kc], vh[1], vh[3]);
            }
        }
        __syncthreads();
    }

    float inv0 = 1.0f / l0, inv1 = 1.0f / l1;
#pragma unroll
    for (int j = 0; j < 8; j++) {
        int col = h * DH + j * 8 + 2 * tig;
        size_t r0 = ((size_t)(b * NQ + q0 + wid * 16 + g)) * D + col;
        uint32_t hp, lp;
        split2(oacc[j][0] * inv0, oacc[j][1] * inv0, hp, lp);
        *reinterpret_cast<uint32_t*>(ctxh + r0) = hp;
        *reinterpret_cast<uint32_t*>(ctxl + r0) = lp;
        split2(oacc[j][2] * inv1, oacc[j][3] * inv1, hp, lp);
        *reinterpret_cast<uint32_t*>(ctxh + r0 + 8 * D) = hp;
        *reinterpret_cast<uint32_t*>(ctxl + r0 + 8 * D) = lp;
    }
}

// ---------------------------------------------------------------------------
// row LayerNorm -> bf16 hi/lo
// ---------------------------------------------------------------------------
__global__ void ln_rows_kernel(const float* __restrict__ x,
                               const float* __restrict__ scale,
                               const float* __restrict__ bias,
                               __nv_bfloat16* __restrict__ oh,
                               __nv_bfloat16* __restrict__ ol) {
    __shared__ float red[18];
    size_t idx = (size_t)blockIdx.x * D + threadIdx.x;
    float v = x[idx];
    float2 st = ln_stats256(v, red);
    float y = (v - st.x) * st.y * scale[threadIdx.x] + bias[threadIdx.x];
    __nv_bfloat16 h = __float2bfloat16(y);
    oh[idx] = h;
    ol[idx] = __float2bfloat16(y - __bfloat162float(h));
}

// ---------------------------------------------------------------------------
// res = LN_eff( LN_outer( h + ffn ) ); scatter-add into upd and outp
// ---------------------------------------------------------------------------
__global__ void res_scatter_kernel(const __nv_bfloat16* __restrict__ hh,
                                   const __nv_bfloat16* __restrict__ hl,
                                   const float* __restrict__ ffn,
                                   const float* __restrict__ os, const float* __restrict__ ob,
                                   const float* __restrict__ es, const float* __restrict__ eb,
                                   const int* __restrict__ qidx,
                                   float* __restrict__ upd,
                                   float* __restrict__ outp) {
    __shared__ float red[18];
    int bi = blockIdx.x;
    int t = threadIdx.x;
    size_t idx = (size_t)bi * D + t;
    float x = __bfloat162float(hh[idx]) + __bfloat162float(hl[idx]) + ffn[idx];
    float2 st1 = ln_stats256(x, red);
    float y = (x - st1.x) * st1.y * os[t] + ob[t];
    float2 st2 = ln_stats256(y, red);
    float z = (y - st2.x) * st2.y * es[t] + eb[t];

    int b = bi / NQ, i = bi % NQ;
    int s = qidx[i];
    size_t off = ((size_t)b * NS + s) * D + t;
    atomicAdd(&upd[off], z);
    atomicAdd(&outp[off], z);
}

// ---------------------------------------------------------------------------
// launch
// ---------------------------------------------------------------------------
extern "C" void kernel_launch(void* const* d_in, const int* in_sizes, int n_in,
                              void* d_out, int out_size) {
    const float* update_tensor = (const float*)d_in[0];
    const float* emb   = (const float*)d_in[1];
    const float* mask  = (const float*)d_in[2];
    const float* Wq    = (const float*)d_in[3];
    const float* Wk    = (const float*)d_in[4];
    const float* Wv    = (const float*)d_in[5];
    const float* Wo    = (const float*)d_in[6];
    const float* W1    = (const float*)d_in[7];
    const float* b1    = (const float*)d_in[8];
    const float* W2    = (const float*)d_in[9];
    const float* b2    = (const float*)d_in[10];
    const float* sys_s = (const float*)d_in[11];
    const float* sys_b = (const float*)d_in[12];
    const float* eff_s = (const float*)d_in[13];
    const float* eff_b = (const float*)d_in[14];
    const float* in_s  = (const float*)d_in[15];
    const float* in_b  = (const float*)d_in[16];
    const float* out_s = (const float*)d_in[17];
    const float* out_b = (const float*)d_in[18];
    const int*   qidx  = (const int*)d_in[19];
    const int*   kidx  = (const int*)d_in[20];
    float* outp = (float*)d_out;

    float *p_upd, *p_hraw, *p_ffn;
    __nv_bfloat16 *p_wh, *p_wl, *p_qnh, *p_qnl, *p_knh, *p_knl;
    __nv_bfloat16 *p_Qh, *p_Ql, *p_Kh, *p_Kl, *p_Vh, *p_Vl;
    __nv_bfloat16 *p_ctxh, *p_ctxl, *p_hh, *p_hl, *p_gh, *p_gl;
    unsigned char* p_mb;
    cudaGetSymbolAddress((void**)&p_upd,  g_upd);
    cudaGetSymbolAddress((void**)&p_hraw, g_hraw);
    cudaGetSymbolAddress((void**)&p_ffn,  g_ffn);
    cudaGetSymbolAddress((void**)&p_wh,   g_Wt_hi);
    cudaGetSymbolAddress((void**)&p_wl,   g_Wt_lo);
    cudaGetSymbolAddress((void**)&p_qnh,  g_qnh);
    cudaGetSymbolAddress((void**)&p_qnl,  g_qnl);
    cudaGetSymbolAddress((void**)&p_knh,  g_knh);
    cudaGetSymbolAddress((void**)&p_knl,  g_knl);
    cudaGetSymbolAddress((void**)&p_Qh,   g_Qh);
    cudaGetSymbolAddress((void**)&p_Ql,   g_Ql);
    cudaGetSymbolAddress((void**)&p_Kh,   g_Kh);
    cudaGetSymbolAddress((void**)&p_Kl,   g_Kl);
    cudaGetSymbolAddress((void**)&p_Vh,   g_Vh);
    cudaGetSymbolAddress((void**)&p_Vl,   g_Vl);
    cudaGetSymbolAddress((void**)&p_ctxh, g_ctxh);
    cudaGetSymbolAddress((void**)&p_ctxl, g_ctxl);
    cudaGetSymbolAddress((void**)&p_hh,   g_hh);
    cudaGetSymbolAddress((void**)&p_hl,   g_hl);
    cudaGetSymbolAddress((void**)&p_gh,   g_gh);
    cudaGetSymbolAddress((void**)&p_gl,   g_gl);
    cudaGetSymbolAddress((void**)&p_mb,   g_maskb);

    cudaFuncSetAttribute(gemm_bf16_kernel<0,0>, cudaFuncAttributeMaxDynamicSharedMemorySize, GEMM_SMEM_BYTES);
    cudaFuncSetAttribute(gemm_bf16_kernel<0,1>, cudaFuncAttributeMaxDynamicSharedMemorySize, GEMM_SMEM_BYTES);
    cudaFuncSetAttribute(gemm_bf16_kernel<1,0>, cudaFuncAttributeMaxDynamicSharedMemorySize, GEMM_SMEM_BYTES);
    cudaFuncSetAttribute(gemm_bf16_kernel<2,1>, cudaFuncAttributeMaxDynamicSharedMemorySize, GEMM_SMEM_BYTES);

    // 1: copy mutable state + zero output
    {
        int n4 = (B * NS * D) / 4;
        init_kernel<<<n4 / 256, 256>>>(update_tensor, p_upd, outp);
    }
    // 2: mask -> bytes (all levels)
    maskb_kernel<<<(LVL * NQ * NK / 4) / 256, 256>>>(mask, p_mb);
    // 3: weight prep (one launch)
    {
        WPtrs ws;
        ws.w[0] = Wq; ws.w[1] = Wk; ws.w[2] = Wv;
        ws.w[3] = Wo; ws.w[4] = W1; ws.w[5] = W2;
        prep_w_all_kernel<<<dim3(8, 8, 6), dim3(32, 8)>>>(ws, p_wh, p_wl);
    }

    for (int l = 0; l < LVL; l++) {
        const int* qi = qidx + l * NQ;
        const int* ki = kidx + l * NK;
        const unsigned char* mb = p_mb + (size_t)l * NQ * NK;

        gather_ln_kernel<<<B * (NQ + NK), 256>>>(emb, p_upd, sys_s, sys_b, qi, ki,
                                                 p_qnh, p_qnl, p_knh, p_knl);

        gemm_bf16_kernel<0,1><<<dim3(B * NQ / 128, 2), 256, GEMM_SMEM_BYTES>>>(
            p_qnh, p_qnl, p_wh + 0 * 65536, p_wl + 0 * 65536, nullptr, nullptr, p_Qh, p_Ql);
        gemm_bf16_kernel<0,1><<<dim3(B * NK / 128, 2), 256, GEMM_SMEM_BYTES>>>(
            p_knh, p_knl, p_wh + 1 * 65536, p_wl + 1 * 65536, nullptr, nullptr, p_Kh, p_Kl);
        gemm_bf16_kernel<0,1><<<dim3(B * NK / 128, 2), 256, GEMM_SMEM_BYTES>>>(
            p_knh, p_knl, p_wh + 2 * 65536, p_wl + 2 * 65536, nullptr, nullptr, p_Vh, p_Vl);

        attn_mma_kernel<<<dim3(NQ / 128, H, B), 256>>>(
            p_Qh, p_Ql, p_Kh, p_Kl, p_Vh, p_Vl, mb, p_ctxh, p_ctxl);

        gemm_bf16_kernel<0,0><<<dim3(B * NQ / 128, 2), 256, GEMM_SMEM_BYTES>>>(
            p_ctxh, p_ctxl, p_wh + 3 * 65536, p_wl + 3 * 65536, nullptr, p_hraw, nullptr, nullptr);
        ln_rows_kernel<<<B * NQ, 256>>>(p_hraw, in_s, in_b, p_hh, p_hl);

        gemm_bf16_kernel<2,1><<<dim3(B * NQ / 128, 2), 256, GEMM_SMEM_BYTES>>>(
            p_hh, p_hl, p_wh + 4 * 65536, p_wl + 4 * 65536, b1, nullptr, p_gh, p_gl);
        gemm_bf16_kernel<1,0><<<dim3(B * NQ / 128, 2), 256, GEMM_SMEM_BYTES>>>(
            p_gh, p_gl, p_wh + 5 * 65536, p_wl + 5 * 65536, b2, p_ffn, nullptr, nullptr);

        res_scatter_kernel<<<B * NQ, 256>>>(p_hh, p_hl, p_ffn, out_s, out_b, eff_s, eff_b,
                                            qi, p_upd, outp);
    }
}

// round 6
// speedup vs baseline: 2.5858x; 1.0734x over previous
#include <cuda_runtime.h>
#include <cuda_bf16.h>
#include <math.h>
#include <stdint.h>

// Problem constants
#define B    32
#define NS   4096
#define D    256
#define H    4
#define LVL  6
#define NQ   512
#define NK   1024
#define DH   64
#define ATTN_SCALE 0.125f   // 1/sqrt(64)

// ---------------------------------------------------------------------------
// Scratch (no allocations allowed -> device globals)
// ---------------------------------------------------------------------------
__device__ float g_upd [(size_t)B * NS * D];   // working copy of update_tensor
__device__ float g_hraw[(size_t)B * NQ * D];
__device__ float g_ffn [(size_t)B * NQ * D];

// bf16 hi/lo activations
__device__ __nv_bfloat16 g_qnh[(size_t)B * NQ * D];
__device__ __nv_bfloat16 g_qnl[(size_t)B * NQ * D];
__device__ __nv_bfloat16 g_knh[(size_t)B * NK * D];
__device__ __nv_bfloat16 g_knl[(size_t)B * NK * D];
__device__ __nv_bfloat16 g_Qh [(size_t)B * NQ * D];
__device__ __nv_bfloat16 g_Ql [(size_t)B * NQ * D];
__device__ __nv_bfloat16 g_Kh [(size_t)B * NK * D];
__device__ __nv_bfloat16 g_Kl [(size_t)B * NK * D];
__device__ __nv_bfloat16 g_Vh [(size_t)B * NK * D];
__device__ __nv_bfloat16 g_Vl [(size_t)B * NK * D];
__device__ __nv_bfloat16 g_ctxh[(size_t)B * NQ * D];
__device__ __nv_bfloat16 g_ctxl[(size_t)B * NQ * D];
__device__ __nv_bfloat16 g_hh [(size_t)B * NQ * D];
__device__ __nv_bfloat16 g_hl [(size_t)B * NQ * D];
__device__ __nv_bfloat16 g_gh [(size_t)B * NQ * D];
__device__ __nv_bfloat16 g_gl [(size_t)B * NQ * D];

// transposed + bf16 hi/lo decomposed weights: [6][N=256][K=256]
__device__ __nv_bfloat16 g_Wt_hi[6 * 256 * 256];
__device__ __nv_bfloat16 g_Wt_lo[6 * 256 * 256];

// mask as bytes, all levels
__device__ unsigned char g_maskb[(size_t)LVL * NQ * NK];

// ---------------------------------------------------------------------------
// Helpers
// ---------------------------------------------------------------------------
__device__ __forceinline__ uint32_t smem_u32(const void* p) {
    uint32_t a;
    asm("{ .reg .u64 t; cvta.to.shared.u64 t, %1; cvt.u32.u64 %0, t; }" : "=r"(a) : "l"(p));
    return a;
}

__device__ __forceinline__ float gelu_tanh(float x) {
    float x3 = x * x * x;
    return 0.5f * x * (1.0f + tanhf(0.7978845608028654f * (x + 0.044715f * x3)));
}

// mma.sync m16n8k16 bf16 (HMMA pipe)
__device__ __forceinline__ void mma16816(float* c, const uint32_t* a, uint32_t b0, uint32_t b1) {
    asm volatile(
        "mma.sync.aligned.m16n8k16.row.col.f32.bf16.bf16.f32 "
        "{%0,%1,%2,%3}, {%4,%5,%6,%7}, {%8,%9}, {%0,%1,%2,%3};"
        : "+f"(c[0]), "+f"(c[1]), "+f"(c[2]), "+f"(c[3])
        : "r"(a[0]), "r"(a[1]), "r"(a[2]), "r"(a[3]), "r"(b0), "r"(b1));
}

__device__ __forceinline__ void ldmatrix_x4(uint32_t* r, uint32_t addr) {
    asm volatile("ldmatrix.sync.aligned.m8n8.x4.shared.b16 {%0,%1,%2,%3}, [%4];"
                 : "=r"(r[0]), "=r"(r[1]), "=r"(r[2]), "=r"(r[3]) : "r"(addr));
}
__device__ __forceinline__ void ldmatrix_x4_t(uint32_t* r, uint32_t addr) {
    asm volatile("ldmatrix.sync.aligned.m8n8.x4.trans.shared.b16 {%0,%1,%2,%3}, [%4];"
                 : "=r"(r[0]), "=r"(r[1]), "=r"(r[2]), "=r"(r[3]) : "r"(addr));
}

__device__ __forceinline__ uint32_t packbf2(float x, float y) {
    __nv_bfloat162 h = __floats2bfloat162_rn(x, y);
    return *reinterpret_cast<uint32_t*>(&h);
}

// split a float pair into packed hi + lo bf16x2
__device__ __forceinline__ void split2(float x, float y, uint32_t& hp, uint32_t& lp) {
    __nv_bfloat16 h0 = __float2bfloat16(x);
    __nv_bfloat16 h1 = __float2bfloat16(y);
    hp = ((uint32_t)__bfloat16_as_ushort(h1) << 16) | __bfloat16_as_ushort(h0);
    lp = packbf2(x - __bfloat162float(h0), y - __bfloat162float(h1));
}

#define CP_ASYNC16(dst, src) \
    asm volatile("cp.async.cg.shared.global [%0], [%1], 16;" :: "r"(dst), "l"(src))
#define CP_COMMIT() asm volatile("cp.async.commit_group;" ::: "memory")
#define CP_WAIT1()  asm volatile("cp.async.wait_group 1;" ::: "memory")
#define CP_WAIT0()  asm volatile("cp.async.wait_group 0;" ::: "memory")

// warp-wide mean/rstd over 8 values per lane (row width 256)
__device__ __forceinline__ float2 warp_ln_stats(const float* v) {
    float s = 0.f, s2 = 0.f;
#pragma unroll
    for (int i = 0; i < 8; i++) { s += v[i]; s2 += v[i] * v[i]; }
#pragma unroll
    for (int o = 16; o > 0; o >>= 1) {
        s  += __shfl_xor_sync(0xffffffffu, s,  o);
        s2 += __shfl_xor_sync(0xffffffffu, s2, o);
    }
    float mean = s * (1.0f / D);
    float var  = s2 * (1.0f / D) - mean * mean;
    return make_float2(mean, rsqrtf(var + 1e-5f));
}

// ---------------------------------------------------------------------------
// init: copy update_tensor into working buffer, zero output
// ---------------------------------------------------------------------------
__global__ void init_kernel(const float* __restrict__ src, float* __restrict__ upd,
                            float* __restrict__ outp) {
    size_t i = (size_t)blockIdx.x * blockDim.x + threadIdx.x;
    float4 v = reinterpret_cast<const float4*>(src)[i];
    reinterpret_cast<float4*>(upd)[i]  = v;
    reinterpret_cast<float4*>(outp)[i] = make_float4(0.f, 0.f, 0.f, 0.f);
}

// ---------------------------------------------------------------------------
// mask -> bytes, all levels at once
// ---------------------------------------------------------------------------
__global__ void maskb_kernel(const float* __restrict__ mask, unsigned char* __restrict__ mb) {
    size_t i = (size_t)blockIdx.x * 256 + threadIdx.x;
    float4 v = reinterpret_cast<const float4*>(mask)[i];
    uchar4 u;
    u.x = v.x > 0.5f; u.y = v.y > 0.5f; u.z = v.z > 0.5f; u.w = v.w > 0.5f;
    reinterpret_cast<uchar4*>(mb)[i] = u;
}

// ---------------------------------------------------------------------------
// weight prep (all 6 weights): Wt[n][k] = W[k][n], bf16 hi/lo
// grid (8, 8, 6), block (32, 8)
// ---------------------------------------------------------------------------
struct WPtrs { const float* w[6]; };

__global__ void prep_w_all_kernel(WPtrs ws,
                                  __nv_bfloat16* __restrict__ Th,
                                  __nv_bfloat16* __restrict__ Tl) {
    __shared__ float t[32][33];
    int wsel = blockIdx.z;
    const float* W = ws.w[wsel];
    __nv_bfloat16* Thw = Th + (size_t)wsel * 65536;
    __nv_bfloat16* Tlw = Tl + (size_t)wsel * 65536;
    int bx = blockIdx.x * 32;
    int by = blockIdx.y * 32;
#pragma unroll
    for (int i = threadIdx.y; i < 32; i += 8)
        t[i][threadIdx.x] = W[(size_t)(by + i) * 256 + bx + threadIdx.x];
    __syncthreads();
#pragma unroll
    for (int i = threadIdx.y; i < 32; i += 8) {
        float v = t[threadIdx.x][i];
        __nv_bfloat16 h = __float2bfloat16(v);
        float r = v - __bfloat162float(h);
        size_t o = (size_t)(bx + i) * 256 + by + threadIdx.x;
        Thw[o] = h;
        Tlw[o] = __float2bfloat16(r);
    }
}

// ---------------------------------------------------------------------------
// gather + LayerNorm(sys) -> bf16 hi/lo.  Warp per row; 8 rows per block.
// grid = B*(NQ+NK)/8, block 256.
// ---------------------------------------------------------------------------
__global__ __launch_bounds__(256)
void gather_ln_kernel(const float* __restrict__ emb,
                      const float* __restrict__ upd,
                      const float* __restrict__ sscale,
                      const float* __restrict__ sbias,
                      const int* __restrict__ qidx,
                      const int* __restrict__ kidx,
                      __nv_bfloat16* __restrict__ qnh,
                      __nv_bfloat16* __restrict__ qnl,
                      __nv_bfloat16* __restrict__ knh,
                      __nv_bfloat16* __restrict__ knl) {
    int r = blockIdx.x * 8 + (threadIdx.x >> 5);
    int lane = threadIdx.x & 31;
    int col = lane * 8;
    int b, s;
    __nv_bfloat16 *dh, *dl;
    size_t off;
    if (r < B * NQ) {
        b = r / NQ;
        s = qidx[r % NQ];
        off = (size_t)r * D;
        dh = qnh; dl = qnl;
    } else {
        int r2 = r - B * NQ;
        b = r2 / NK;
        s = kidx[r2 % NK];
        off = (size_t)r2 * D;
        dh = knh; dl = knl;
    }
    float v[8];
    {
        const float4* e4 = reinterpret_cast<const float4*>(emb + (size_t)s * D + col);
        const float4* u4 = reinterpret_cast<const float4*>(upd + ((size_t)b * NS + s) * D + col);
        float4 a0 = e4[0], a1 = e4[1], b0 = u4[0], b1 = u4[1];
        v[0] = a0.x + b0.x; v[1] = a0.y + b0.y; v[2] = a0.z + b0.z; v[3] = a0.w + b0.w;
        v[4] = a1.x + b1.x; v[5] = a1.y + b1.y; v[6] = a1.z + b1.z; v[7] = a1.w + b1.w;
    }
    float2 st = warp_ln_stats(v);
    float4 sc0 = reinterpret_cast<const float4*>(sscale + col)[0];
    float4 sc1 = reinterpret_cast<const float4*>(sscale + col)[1];
    float4 bi0 = reinterpret_cast<const float4*>(sbias + col)[0];
    float4 bi1 = reinterpret_cast<const float4*>(sbias + col)[1];
    float sc[8] = {sc0.x, sc0.y, sc0.z, sc0.w, sc1.x, sc1.y, sc1.z, sc1.w};
    float bi[8] = {bi0.x, bi0.y, bi0.z, bi0.w, bi1.x, bi1.y, bi1.z, bi1.w};
    uint32_t hp[4], lp[4];
#pragma unroll
    for (int i = 0; i < 4; i++) {
        float y0 = (v[2*i]   - st.x) * st.y * sc[2*i]   + bi[2*i];
        float y1 = (v[2*i+1] - st.x) * st.y * sc[2*i+1] + bi[2*i+1];
        split2(y0, y1, hp[i], lp[i]);
    }
    *reinterpret_cast<uint4*>(dh + off + col) = *reinterpret_cast<uint4*>(hp);
    *reinterpret_cast<uint4*>(dl + off + col) = *reinterpret_cast<uint4*>(lp);
}

// ---------------------------------------------------------------------------
// mma.sync GEMM, bf16 hi/lo A operand, cp.async 2-stage pipeline.
// C[M,256] = A[M,256] @ W[256,256];  split-3: Ah*Bh + Ah*Bl + Al*Bh
// CTA 128x128, 8 warps (4x2), warp tile 32x64; K chunks of 64.
// MODE: 0 plain, 1 +bias, 2 +bias+gelu.  OUT: 0 fp32 C, 1 bf16 hi/lo.
// ---------------------------------------------------------------------------
#define GPAD 72
#define TILE_B (128 * GPAD * 2)      // 18432
#define STAGE_B (4 * TILE_B)         // 73728
#define GEMM_SMEM_BYTES (2 * STAGE_B)

__device__ __forceinline__ void gemm_issue_chunk(
    uint32_t stage, int tid,
    const __nv_bfloat16* Ah, const __nv_bfloat16* Al,
    const __nv_bfloat16* Bh, const __nv_bfloat16* Bl,
    int mBase, int nBase, int k0)
{
    const __nv_bfloat16* srcs[4] = {Ah, Al, Bh, Bl};
#pragma unroll
    for (int t4 = 0; t4 < 4; t4++) {
        int base = (t4 < 2) ? mBase : nBase;
#pragma unroll
        for (int it = 0; it < 4; it++) {
            int seg = tid + it * 256;
            int row = seg >> 3, j = seg & 7;
            const void* gp = srcs[t4] + (size_t)(base + row) * 256 + k0 + j * 8;
            uint32_t d = stage + t4 * TILE_B + (uint32_t)((row * GPAD + j * 8) * 2);
            CP_ASYNC16(d, gp);
        }
    }
    CP_COMMIT();
}

template <int MODE, int OUT>
__global__ __launch_bounds__(256)
void gemm_bf16_kernel(const __nv_bfloat16* __restrict__ Ah,
                      const __nv_bfloat16* __restrict__ Al,
                      const __nv_bfloat16* __restrict__ Bth,
                      const __nv_bfloat16* __restrict__ Btl,
                      const float* __restrict__ bias,
                      float* __restrict__ C,
                      __nv_bfloat16* __restrict__ Ch,
                      __nv_bfloat16* __restrict__ Cl) {
    extern __shared__ char smem[];
    const uint32_t sb = smem_u32(smem);

    int tid  = threadIdx.x;
    int wid  = tid >> 5, lane = tid & 31;
    int warpM = wid & 3;
    int warpN = wid >> 2;
    int mBase = blockIdx.x * 128;
    int nBase = blockIdx.y * 128;

    float acc[2][8][4];
#pragma unroll
    for (int i = 0; i < 2; i++)
#pragma unroll
        for (int j = 0; j < 8; j++)
#pragma unroll
            for (int k = 0; k < 4; k++) acc[i][j][k] = 0.f;

    gemm_issue_chunk(sb, tid, Ah, Al, Bth, Btl, mBase, nBase, 0);

    for (int kc = 0; kc < 4; kc++) {
        if (kc < 3)
            gemm_issue_chunk(sb + ((kc + 1) & 1) * STAGE_B, tid, Ah, Al, Bth, Btl,
                             mBase, nBase, (kc + 1) * 64);
        if (kc < 3) { CP_WAIT1(); } else { CP_WAIT0(); }
        __syncthreads();

        uint32_t st = sb + (kc & 1) * STAGE_B;
        for (int ks = 0; ks < 4; ks++) {
            int lrow = lane & 15;
            int lcol = ks * 16 + (lane >> 4) * 8;
            uint32_t ah[2][4], al[2][4];
#pragma unroll
            for (int mt = 0; mt < 2; mt++) {
                int row = warpM * 32 + mt * 16 + lrow;
                uint32_t ad = st + (uint32_t)((row * GPAD + lcol) * 2);
                ldmatrix_x4(ah[mt], ad);
                ldmatrix_x4(al[mt], ad + TILE_B);
            }
#pragma unroll
            for (int nt2 = 0; nt2 < 4; nt2++) {
                int row = warpN * 64 + nt2 * 16 + lrow;
                uint32_t bd = st + 2 * TILE_B + (uint32_t)((row * GPAD + lcol) * 2);
                uint32_t bh[4], bl[4];
                ldmatrix_x4(bh, bd);
                ldmatrix_x4(bl, bd + TILE_B);
#pragma unroll
                for (int mt = 0; mt < 2; mt++) {
                    mma16816(acc[mt][nt2 * 2 + 0], ah[mt], bh[0], bh[2]);
                    mma16816(acc[mt][nt2 * 2 + 0], ah[mt], bl[0], bl[2]);
                    mma16816(acc[mt][nt2 * 2 + 0], al[mt], bh[0], bh[2]);
                    mma16816(acc[mt][nt2 * 2 + 1], ah[mt], bh[1], bh[3]);
                    mma16816(acc[mt][nt2 * 2 + 1], ah[mt], bl[1], bl[3]);
                    mma16816(acc[mt][nt2 * 2 + 1], al[mt], bh[1], bh[3]);
                }
            }
        }
        __syncthreads();
    }

    // epilogue
    int g = lane >> 2, tig = lane & 3;
#pragma unroll
    for (int mt = 0; mt < 2; mt++) {
#pragma unroll
        for (int nt = 0; nt < 8; nt++) {
            int row0 = mBase + warpM * 32 + mt * 16 + g;
            int col  = nBase + warpN * 64 + nt * 8 + tig * 2;
            float v0 = acc[mt][nt][0], v1 = acc[mt][nt][1];
            float v2 = acc[mt][nt][2], v3 = acc[mt][nt][3];
            if (MODE >= 1) {
                float bb0 = bias[col], bb1 = bias[col + 1];
                v0 += bb0; v1 += bb1; v2 += bb0; v3 += bb1;
            }
            if (MODE == 2) {
                v0 = gelu_tanh(v0); v1 = gelu_tanh(v1);
                v2 = gelu_tanh(v2); v3 = gelu_tanh(v3);
            }
            if (OUT == 0) {
                *reinterpret_cast<float2*>(C + (size_t)row0 * 256 + col) = make_float2(v0, v1);
                *reinterpret_cast<float2*>(C + (size_t)(row0 + 8) * 256 + col) = make_float2(v2, v3);
            } else {
                uint32_t hp01, lp01, hp23, lp23;
                split2(v0, v1, hp01, lp01);
                split2(v2, v3, hp23, lp23);
                *reinterpret_cast<uint32_t*>(Ch + (size_t)row0 * 256 + col) = hp01;
                *reinterpret_cast<uint32_t*>(Ch + (size_t)(row0 + 8) * 256 + col) = hp23;
                *reinterpret_cast<uint32_t*>(Cl + (size_t)row0 * 256 + col) = lp01;
                *reinterpret_cast<uint32_t*>(Cl + (size_t)(row0 + 8) * 256 + col) = lp23;
            }
        }
    }
}

// ---------------------------------------------------------------------------
// Fused flash attention on HMMA pipe, cp.async double-buffered K/V/mask.
// grid (NQ/128, H, B), 256 threads (8 warps); warp owns 16 query rows.
// QK^T: split-3; PV: Ph*Vh + Ph*Vl + Pl*Vh. ctx written bf16 hi/lo.
// ---------------------------------------------------------------------------
#define APAD 72
#define A_KH 0
#define A_KL 9216
#define A_VH 18432
#define A_VL 27648
#define A_MS 36864                 // 128 rows x 80 bytes
#define A_STAGE 47104
#define ATTN_SMEM_BYTES (2 * A_STAGE)   // 94208

__device__ __forceinline__ void attn_stage(
    uint32_t st, char* smem_ms_unused, int tid,
    const __nv_bfloat16* Kh, const __nv_bfloat16* Kl,
    const __nv_bfloat16* Vh, const __nv_bfloat16* Vl,
    const unsigned char* maskb, int b, int h, int q0, int kb)
{
#pragma unroll
    for (int it = 0; it < 2; it++) {
        int seg = tid + it * 256;        // 512 segments
        int r = seg >> 3, j = seg & 7;
        size_t go = ((size_t)(b * NK + kb + r)) * D + h * DH + j * 8;
        uint32_t off = (uint32_t)((r * APAD + j * 8) * 2);
        CP_ASYNC16(st + A_KH + off, Kh + go);
        CP_ASYNC16(st + A_KL + off, Kl + go);
        CP_ASYNC16(st + A_VH + off, Vh + go);
        CP_ASYNC16(st + A_VL + off, Vl + go);
    }
#pragma unroll
    for (int it = 0; it < 2; it++) {
        int seg = tid + it * 256;        // 512 segments of 16B
        int r = seg >> 2, j = seg & 3;
        CP_ASYNC16(st + A_MS + (uint32_t)(r * 80 + j * 16),
                   maskb + (size_t)(q0 + r) * NK + kb + j * 16);
    }
    CP_COMMIT();
}

__global__ __launch_bounds__(256)
void attn_mma_kernel(const __nv_bfloat16* __restrict__ Qh, const __nv_bfloat16* __restrict__ Ql,
                     const __nv_bfloat16* __restrict__ Kh, const __nv_bfloat16* __restrict__ Kl,
                     const __nv_bfloat16* __restrict__ Vh, const __nv_bfloat16* __restrict__ Vl,
                     const unsigned char* __restrict__ maskb,
                     __nv_bfloat16* __restrict__ ctxh, __nv_bfloat16* __restrict__ ctxl) {
    extern __shared__ char smem[];
    const uint32_t sb = smem_u32(smem);

    int tid = threadIdx.x, wid = tid >> 5, lane = tid & 31;
    int q0 = blockIdx.x * 128, h = blockIdx.y, b = blockIdx.z;
    int g = lane >> 2, tig = lane & 3;
    int lrow = lane & 15, lco = (lane >> 4) * 8;

    // Q fragments directly from gmem
    uint32_t qah[4][4], qal[4][4];
#pragma unroll
    for (int ks = 0; ks < 4; ks++) {
#pragma unroll
        for (int i = 0; i < 4; i++) {
            int row = q0 + wid * 16 + g + (i & 1) * 8;
            int col = h * DH + ks * 16 + tig * 2 + (i >> 1) * 8;
            size_t o = ((size_t)(b * NQ + row)) * D + col;
            qah[ks][i] = *reinterpret_cast<const uint32_t*>(Qh + o);
            qal[ks][i] = *reinterpret_cast<const uint32_t*>(Ql + o);
        }
    }

    float m0 = -1e30f, m1 = -1e30f, l0 = 0.f, l1 = 0.f;
    float oacc[8][4];
#pragma unroll
    for (int j = 0; j < 8; j++)
#pragma unroll
        for (int k = 0; k < 4; k++) oacc[j][k] = 0.f;

    attn_stage(sb, smem, tid, Kh, Kl, Vh, Vl, maskb, b, h, q0, 0);

    for (int c = 0; c < 16; c++) {
        if (c < 15)
            attn_stage(sb + ((c + 1) & 1) * A_STAGE, smem, tid, Kh, Kl, Vh, Vl,
                       maskb, b, h, q0, (c + 1) * 64);
        if (c < 15) { CP_WAIT1(); } else { CP_WAIT0(); }
        __syncthreads();

        uint32_t st = sb + (c & 1) * A_STAGE;
        const unsigned char* msp = reinterpret_cast<const unsigned char*>(
            smem + (c & 1) * A_STAGE + A_MS);

        // S = Q K^T (split-3)
        float sacc[8][4];
#pragma unroll
        for (int j = 0; j < 8; j++)
#pragma unroll
            for (int k = 0; k < 4; k++) sacc[j][k] = 0.f;
#pragma unroll
        for (int ks = 0; ks < 4; ks++) {
#pragma unroll
            for (int nt = 0; nt < 4; nt++) {
                uint32_t bh[4], bl[4];
                uint32_t off = (uint32_t)(((nt * 16 + lrow) * APAD + ks * 16 + lco) * 2);
                ldmatrix_x4(bh, st + A_KH + off);
                ldmatrix_x4(bl, st + A_KL + off);
                mma16816(sacc[nt * 2 + 0], qah[ks], bh[0], bh[2]);
                mma16816(sacc[nt * 2 + 0], qah[ks], bl[0], bl[2]);
                mma16816(sacc[nt * 2 + 0], qal[ks], bh[0], bh[2]);
                mma16816(sacc[nt * 2 + 1], qah[ks], bh[1], bh[3]);
                mma16816(sacc[nt * 2 + 1], qah[ks], bl[1], bl[3]);
                mma16816(sacc[nt * 2 + 1], qal[ks], bh[1], bh[3]);
            }
        }

        // scale + mask
        int qr0 = wid * 16 + g, qr1 = qr0 + 8;
#pragma unroll
        for (int j = 0; j < 8; j++) {
            int col = j * 8 + 2 * tig;
            sacc[j][0] = msp[qr0 * 80 + col]     ? sacc[j][0] * ATTN_SCALE : -1e9f;
            sacc[j][1] = msp[qr0 * 80 + col + 1] ? sacc[j][1] * ATTN_SCALE : -1e9f;
            sacc[j][2] = msp[qr1 * 80 + col]     ? sacc[j][2] * ATTN_SCALE : -1e9f;
            sacc[j][3] = msp[qr1 * 80 + col + 1] ? sacc[j][3] * ATTN_SCALE : -1e9f;
        }

        // online softmax
        float mr0 = -1e30f, mr1 = -1e30f;
#pragma unroll
        for (int j = 0; j < 8; j++) {
            mr0 = fmaxf(mr0, fmaxf(sacc[j][0], sacc[j][1]));
            mr1 = fmaxf(mr1, fmaxf(sacc[j][2], sacc[j][3]));
        }
        mr0 = fmaxf(mr0, __shfl_xor_sync(0xffffffffu, mr0, 1));
        mr0 = fmaxf(mr0, __shfl_xor_sync(0xffffffffu, mr0, 2));
        mr1 = fmaxf(mr1, __shfl_xor_sync(0xffffffffu, mr1, 1));
        mr1 = fmaxf(mr1, __shfl_xor_sync(0xffffffffu, mr1, 2));
        float nm0 = fmaxf(m0, mr0), nm1 = fmaxf(m1, mr1);
        float cor0 = __expf(m0 - nm0), cor1 = __expf(m1 - nm1);
        m0 = nm0; m1 = nm1;

        float ps0 = 0.f, ps1 = 0.f;
        uint32_t pa[4][4], pl[4][4];
#pragma unroll
        for (int j = 0; j < 8; j++) {
            float p0 = __expf(sacc[j][0] - m0);
            float p1 = __expf(sacc[j][1] - m0);
            float p2 = __expf(sacc[j][2] - m1);
            float p3 = __expf(sacc[j][3] - m1);
            ps0 += p0 + p1; ps1 += p2 + p3;
            int kc = j >> 1, o2 = (j & 1) * 2;
            uint32_t hp, lp;
            split2(p0, p1, hp, lp);
            pa[kc][o2 + 0] = hp; pl[kc][o2 + 0] = lp;
            split2(p2, p3, hp, lp);
            pa[kc][o2 + 1] = hp; pl[kc][o2 + 1] = lp;
        }
        ps0 += __shfl_xor_sync(0xffffffffu, ps0, 1);
        ps0 += __shfl_xor_sync(0xffffffffu, ps0, 2);
        ps1 += __shfl_xor_sync(0xffffffffu, ps1, 1);
        ps1 += __shfl_xor_sync(0xffffffffu, ps1, 2);
        l0 = l0 * cor0 + ps0;
        l1 = l1 * cor1 + ps1;
#pragma unroll
        for (int j = 0; j < 8; j++) {
            oacc[j][0] *= cor0; oacc[j][1] *= cor0;
            oacc[j][2] *= cor1; oacc[j][3] *= cor1;
        }

        // O += P V  (P hi/lo, V hi/lo; three-term split)
        int vro = ((lane >> 4) << 3) + (lane & 7);
        int vcb = ((lane >> 3) & 1) << 3;
#pragma unroll
        for (int kc = 0; kc < 4; kc++) {
            int vr = 16 * kc + vro;
#pragma unroll
            for (int vt = 0; vt < 4; vt++) {
                uint32_t vh[4], vl[4];
                uint32_t off = (uint32_t)((vr * APAD + vt * 16 + vcb) * 2);
                ldmatrix_x4_t(vh, st + A_VH + off);
                ldmatrix_x4_t(vl, st + A_VL + off);
                mma16816(oacc[vt * 2 + 0], pa[kc], vh[0], vh[2]);
                mma16816(oacc[vt * 2 + 0], pa[kc], vl[0], vl[2]);
                mma16816(oacc[vt * 2 + 0], pl[kc], vh[0], vh[2]);
                mma16816(oacc[vt * 2 + 1], pa[kc], vh[1], vh[3]);
                mma16816(oacc[vt * 2 + 1], pa[kc], vl[1], vl[3]);
                mma16816(oacc[vt * 2 + 1], pl[kc], vh[1], vh[3]);
            }
        }
        __syncthreads();
    }

    float inv0 = 1.0f / l0, inv1 = 1.0f / l1;
#pragma unroll
    for (int j = 0; j < 8; j++) {
        int col = h * DH + j * 8 + 2 * tig;
        size_t r0 = ((size_t)(b * NQ + q0 + wid * 16 + g)) * D + col;
        uint32_t hp, lp;
        split2(oacc[j][0] * inv0, oacc[j][1] * inv0, hp, lp);
        *reinterpret_cast<uint32_t*>(ctxh + r0) = hp;
        *reinterpret_cast<uint32_t*>(ctxl + r0) = lp;
        split2(oacc[j][2] * inv1, oacc[j][3] * inv1, hp, lp);
        *reinterpret_cast<uint32_t*>(ctxh + r0 + 8 * D) = hp;
        *reinterpret_cast<uint32_t*>(ctxl + r0 + 8 * D) = lp;
    }
}

// ---------------------------------------------------------------------------
// row LayerNorm -> bf16 hi/lo. Warp per row, 8 rows per block.
// ---------------------------------------------------------------------------
__global__ __launch_bounds__(256)
void ln_rows_kernel(const float* __restrict__ x,
                    const float* __restrict__ scale,
                    const float* __restrict__ bias,
                    __nv_bfloat16* __restrict__ oh,
                    __nv_bfloat16* __restrict__ ol) {
    int r = blockIdx.x * 8 + (threadIdx.x >> 5);
    int lane = threadIdx.x & 31;
    int col = lane * 8;
    size_t base = (size_t)r * D + col;
    float v[8];
    {
        float4 a0 = reinterpret_cast<const float4*>(x + base)[0];
        float4 a1 = reinterpret_cast<const float4*>(x + base)[1];
        v[0] = a0.x; v[1] = a0.y; v[2] = a0.z; v[3] = a0.w;
        v[4] = a1.x; v[5] = a1.y; v[6] = a1.z; v[7] = a1.w;
    }
    float2 st = warp_ln_stats(v);
    float4 sc0 = reinterpret_cast<const float4*>(scale + col)[0];
    float4 sc1 = reinterpret_cast<const float4*>(scale + col)[1];
    float4 bi0 = reinterpret_cast<const float4*>(bias + col)[0];
    float4 bi1 = reinterpret_cast<const float4*>(bias + col)[1];
    float sc[8] = {sc0.x, sc0.y, sc0.z, sc0.w, sc1.x, sc1.y, sc1.z, sc1.w};
    float bi[8] = {bi0.x, bi0.y, bi0.z, bi0.w, bi1.x, bi1.y, bi1.z, bi1.w};
    uint32_t hp[4], lp[4];
#pragma unroll
    for (int i = 0; i < 4; i++) {
        float y0 = (v[2*i]   - st.x) * st.y * sc[2*i]   + bi[2*i];
        float y1 = (v[2*i+1] - st.x) * st.y * sc[2*i+1] + bi[2*i+1];
        split2(y0, y1, hp[i], lp[i]);
    }
    *reinterpret_cast<uint4*>(oh + base) = *reinterpret_cast<uint4*>(hp);
    *reinterpret_cast<uint4*>(ol + base) = *reinterpret_cast<uint4*>(lp);
}

// ---------------------------------------------------------------------------
// res = LN_eff( LN_outer( h + ffn ) ); scatter-add. Warp per row.
// ---------------------------------------------------------------------------
__global__ __launch_bounds__(256)
void res_scatter_kernel(const __nv_bfloat16* __restrict__ hh,
                        const __nv_bfloat16* __restrict__ hl,
                        const float* __restrict__ ffn,
                        const float* __restrict__ os, const float* __restrict__ ob,
                        const float* __restrict__ es, const float* __restrict__ eb,
                        const int* __restrict__ qidx,
                        float* __restrict__ upd,
                        float* __restrict__ outp) {
    int bi = blockIdx.x * 8 + (threadIdx.x >> 5);
    int lane = threadIdx.x & 31;
    int col = lane * 8;
    size_t base = (size_t)bi * D + col;

    float v[8];
    {
        uint4 hh4 = *reinterpret_cast<const uint4*>(hh + base);
        uint4 hl4 = *reinterpret_cast<const uint4*>(hl + base);
        const uint32_t* hhp = reinterpret_cast<const uint32_t*>(&hh4);
        const uint32_t* hlp = reinterpret_cast<const uint32_t*>(&hl4);
        float4 f0 = reinterpret_cast<const float4*>(ffn + base)[0];
        float4 f1 = reinterpret_cast<const float4*>(ffn + base)[1];
        float f[8] = {f0.x, f0.y, f0.z, f0.w, f1.x, f1.y, f1.z, f1.w};
#pragma unroll
        for (int i = 0; i < 4; i++) {
            __nv_bfloat162 h2 = *reinterpret_cast<const __nv_bfloat162*>(&hhp[i]);
            __nv_bfloat162 l2 = *reinterpret_cast<const __nv_bfloat162*>(&hlp[i]);
            v[2*i]   = __bfloat162float(h2.x) + __bfloat162float(l2.x) + f[2*i];
            v[2*i+1] = __bfloat162float(h2.y) + __bfloat162float(l2.y) + f[2*i+1];
        }
    }
    float2 st1 = warp_ln_stats(v);
    float4 a0 = reinterpret_cast<const float4*>(os + col)[0];
    float4 a1 = reinterpret_cast<const float4*>(os + col)[1];
    float4 c0 = reinterpret_cast<const float4*>(ob + col)[0];
    float4 c1 = reinterpret_cast<const float4*>(ob + col)[1];
    float osv[8] = {a0.x, a0.y, a0.z, a0.w, a1.x, a1.y, a1.z, a1.w};
    float obv[8] = {c0.x, c0.y, c0.z, c0.w, c1.x, c1.y, c1.z, c1.w};
    float y[8];
#pragma unroll
    for (int i = 0; i < 8; i++) y[i] = (v[i] - st1.x) * st1.y * osv[i] + obv[i];
    float2 st2 = warp_ln_stats(y);
    float4 e0 = reinterpret_cast<const float4*>(es + col)[0];
    float4 e1 = reinterpret_cast<const float4*>(es + col)[1];
    float4 d0 = reinterpret_cast<const float4*>(eb + col)[0];
    float4 d1 = reinterpret_cast<const float4*>(eb + col)[1];
    float esv[8] = {e0.x, e0.y, e0.z, e0.w, e1.x, e1.y, e1.z, e1.w};
    float ebv[8] = {d0.x, d0.y, d0.z, d0.w, d1.x, d1.y, d1.z, d1.w};

    int b = bi / NQ, i = bi % NQ;
    int s = qidx[i];
    size_t off = ((size_t)b * NS + s) * D + col;
#pragma unroll
    for (int k = 0; k < 8; k++) {
        float z = (y[k] - st2.x) * st2.y * esv[k] + ebv[k];
        atomicAdd(&upd[off + k], z);
        atomicAdd(&outp[off + k], z);
    }
}

// ---------------------------------------------------------------------------
// launch
// ---------------------------------------------------------------------------
extern "C" void kernel_launch(void* const* d_in, const int* in_sizes, int n_in,
                              void* d_out, int out_size) {
    const float* update_tensor = (const float*)d_in[0];
    const float* emb   = (const float*)d_in[1];
    const float* mask  = (const float*)d_in[2];
    const float* Wq    = (const float*)d_in[3];
    const float* Wk    = (const float*)d_in[4];
    const float* Wv    = (const float*)d_in[5];
    const float* Wo    = (const float*)d_in[6];
    const float* W1    = (const float*)d_in[7];
    const float* b1    = (const float*)d_in[8];
    const float* W2    = (const float*)d_in[9];
    const float* b2    = (const float*)d_in[10];
    const float* sys_s = (const float*)d_in[11];
    const float* sys_b = (const float*)d_in[12];
    const float* eff_s = (const float*)d_in[13];
    const float* eff_b = (const float*)d_in[14];
    const float* in_s  = (const float*)d_in[15];
    const float* in_b  = (const float*)d_in[16];
    const float* out_s = (const float*)d_in[17];
    const float* out_b = (const float*)d_in[18];
    const int*   qidx  = (const int*)d_in[19];
    const int*   kidx  = (const int*)d_in[20];
    float* outp = (float*)d_out;

    float *p_upd, *p_hraw, *p_ffn;
    __nv_bfloat16 *p_wh, *p_wl, *p_qnh, *p_qnl, *p_knh, *p_knl;
    __nv_bfloat16 *p_Qh, *p_Ql, *p_Kh, *p_Kl, *p_Vh, *p_Vl;
    __nv_bfloat16 *p_ctxh, *p_ctxl, *p_hh, *p_hl, *p_gh, *p_gl;
    unsigned char* p_mb;
    cudaGetSymbolAddress((void**)&p_upd,  g_upd);
    cudaGetSymbolAddress((void**)&p_hraw, g_hraw);
    cudaGetSymbolAddress((void**)&p_ffn,  g_ffn);
    cudaGetSymbolAddress((void**)&p_wh,   g_Wt_hi);
    cudaGetSymbolAddress((void**)&p_wl,   g_Wt_lo);
    cudaGetSymbolAddress((void**)&p_qnh,  g_qnh);
    cudaGetSymbolAddress((void**)&p_qnl,  g_qnl);
    cudaGetSymbolAddress((void**)&p_knh,  g_knh);
    cudaGetSymbolAddress((void**)&p_knl,  g_knl);
    cudaGetSymbolAddress((void**)&p_Qh,   g_Qh);
    cudaGetSymbolAddress((void**)&p_Ql,   g_Ql);
    cudaGetSymbolAddress((void**)&p_Kh,   g_Kh);
    cudaGetSymbolAddress((void**)&p_Kl,   g_Kl);
    cudaGetSymbolAddress((void**)&p_Vh,   g_Vh);
    cudaGetSymbolAddress((void**)&p_Vl,   g_Vl);
    cudaGetSymbolAddress((void**)&p_ctxh, g_ctxh);
    cudaGetSymbolAddress((void**)&p_ctxl, g_ctxl);
    cudaGetSymbolAddress((void**)&p_hh,   g_hh);
    cudaGetSymbolAddress((void**)&p_hl,   g_hl);
    cudaGetSymbolAddress((void**)&p_gh,   g_gh);
    cudaGetSymbolAddress((void**)&p_gl,   g_gl);
    cudaGetSymbolAddress((void**)&p_mb,   g_maskb);

    cudaFuncSetAttribute(gemm_bf16_kernel<0,0>, cudaFuncAttributeMaxDynamicSharedMemorySize, GEMM_SMEM_BYTES);
    cudaFuncSetAttribute(gemm_bf16_kernel<0,1>, cudaFuncAttributeMaxDynamicSharedMemorySize, GEMM_SMEM_BYTES);
    cudaFuncSetAttribute(gemm_bf16_kernel<1,0>, cudaFuncAttributeMaxDynamicSharedMemorySize, GEMM_SMEM_BYTES);
    cudaFuncSetAttribute(gemm_bf16_kernel<2,1>, cudaFuncAttributeMaxDynamicSharedMemorySize, GEMM_SMEM_BYTES);
    cudaFuncSetAttribute(attn_mma_kernel, cudaFuncAttributeMaxDynamicSharedMemorySize, ATTN_SMEM_BYTES);

    // 1: copy mutable state + zero output
    {
        int n4 = (B * NS * D) / 4;
        init_kernel<<<n4 / 256, 256>>>(update_tensor, p_upd, outp);
    }
    // 2: mask -> bytes (all levels)
    maskb_kernel<<<(LVL * NQ * NK / 4) / 256, 256>>>(mask, p_mb);
    // 3: weight prep
    {
        WPtrs ws;
        ws.w[0] = Wq; ws.w[1] = Wk; ws.w[2] = Wv;
        ws.w[3] = Wo; ws.w[4] = W1; ws.w[5] = W2;
        prep_w_all_kernel<<<dim3(8, 8, 6), dim3(32, 8)>>>(ws, p_wh, p_wl);
    }

    for (int l = 0; l < LVL; l++) {
        const int* qi = qidx + l * NQ;
        const int* ki = kidx + l * NK;
        const unsigned char* mb = p_mb + (size_t)l * NQ * NK;

        gather_ln_kernel<<<B * (NQ + NK) / 8, 256>>>(emb, p_upd, sys_s, sys_b, qi, ki,
                                                     p_qnh, p_qnl, p_knh, p_knl);

        gemm_bf16_kernel<0,1><<<dim3(B * NQ / 128, 2), 256, GEMM_SMEM_BYTES>>>(
            p_qnh, p_qnl, p_wh + 0 * 65536, p_wl + 0 * 65536, nullptr, nullptr, p_Qh, p_Ql);
        gemm_bf16_kernel<0,1><<<dim3(B * NK / 128, 2), 256, GEMM_SMEM_BYTES>>>(
            p_knh, p_knl, p_wh + 1 * 65536, p_wl + 1 * 65536, nullptr, nullptr, p_Kh, p_Kl);
        gemm_bf16_kernel<0,1><<<dim3(B * NK / 128, 2), 256, GEMM_SMEM_BYTES>>>(
            p_knh, p_knl, p_wh + 2 * 65536, p_wl + 2 * 65536, nullptr, nullptr, p_Vh, p_Vl);

        attn_mma_kernel<<<dim3(NQ / 128, H, B), 256, ATTN_SMEM_BYTES>>>(
            p_Qh, p_Ql, p_Kh, p_Kl, p_Vh, p_Vl, mb, p_ctxh, p_ctxl);

        gemm_bf16_kernel<0,0><<<dim3(B * NQ / 128, 2), 256, GEMM_SMEM_BYTES>>>(
            p_ctxh, p_ctxl, p_wh + 3 * 65536, p_wl + 3 * 65536, nullptr, p_hraw, nullptr, nullptr);
        ln_rows_kernel<<<B * NQ / 8, 256>>>(p_hraw, in_s, in_b, p_hh, p_hl);

        gemm_bf16_kernel<2,1><<<dim3(B * NQ / 128, 2), 256, GEMM_SMEM_BYTES>>>(
            p_hh, p_hl, p_wh + 4 * 65536, p_wl + 4 * 65536, b1, nullptr, p_gh, p_gl);
        gemm_bf16_kernel<1,0><<<dim3(B * NQ / 128, 2), 256, GEMM_SMEM_BYTES>>>(
            p_gh, p_gl, p_wh + 5 * 65536, p_wl + 5 * 65536, b2, p_ffn, nullptr, nullptr);

        res_scatter_kernel<<<B * NQ / 8, 256>>>(p_hh, p_hl, p_ffn, out_s, out_b, eff_s, eff_b,
                                                qi, p_upd, outp);
    }
}

// round 7
// speedup vs baseline: 2.7963x; 1.0814x over previous
#include <cuda_runtime.h>
#include <cuda_bf16.h>
#include <math.h>
#include <stdint.h>

// Problem constants
#define B    32
#define NS   4096
#define D    256
#define H    4
#define LVL  6
#define NQ   512
#define NK   1024
#define DH   64
#define ATTN_SCALE 0.125f   // 1/sqrt(64)

// ---------------------------------------------------------------------------
// Scratch (no allocations allowed -> device globals)
// ---------------------------------------------------------------------------
__device__ float g_upd [(size_t)B * NS * D];   // working copy of update_tensor
__device__ float g_hraw[(size_t)B * NQ * D];
__device__ float g_ffn [(size_t)B * NQ * D];

// bf16 hi/lo activations
__device__ __nv_bfloat16 g_qnh[(size_t)B * NQ * D];
__device__ __nv_bfloat16 g_qnl[(size_t)B * NQ * D];
__device__ __nv_bfloat16 g_knh[(size_t)B * NK * D];
__device__ __nv_bfloat16 g_knl[(size_t)B * NK * D];
__device__ __nv_bfloat16 g_Qh [(size_t)B * NQ * D];
__device__ __nv_bfloat16 g_Ql [(size_t)B * NQ * D];
__device__ __nv_bfloat16 g_Kh [(size_t)B * NK * D];
__device__ __nv_bfloat16 g_Kl [(size_t)B * NK * D];
__device__ __nv_bfloat16 g_Vh [(size_t)B * NK * D];
__device__ __nv_bfloat16 g_Vl [(size_t)B * NK * D];
__device__ __nv_bfloat16 g_ctxh[(size_t)B * NQ * D];
__device__ __nv_bfloat16 g_ctxl[(size_t)B * NQ * D];
__device__ __nv_bfloat16 g_hh [(size_t)B * NQ * D];
__device__ __nv_bfloat16 g_hl [(size_t)B * NQ * D];
__device__ __nv_bfloat16 g_gh [(size_t)B * NQ * D];
__device__ __nv_bfloat16 g_gl [(size_t)B * NQ * D];

// transposed + bf16 hi/lo decomposed weights: [6][N=256][K=256]
__device__ __nv_bfloat16 g_Wt_hi[6 * 256 * 256];
__device__ __nv_bfloat16 g_Wt_lo[6 * 256 * 256];

// mask as bytes, all levels
__device__ unsigned char g_maskb[(size_t)LVL * NQ * NK];

// ---------------------------------------------------------------------------
// Helpers
// ---------------------------------------------------------------------------
__device__ __forceinline__ uint32_t smem_u32(const void* p) {
    uint32_t a;
    asm("{ .reg .u64 t; cvta.to.shared.u64 t, %1; cvt.u32.u64 %0, t; }" : "=r"(a) : "l"(p));
    return a;
}

__device__ __forceinline__ float gelu_tanh(float x) {
    float x3 = x * x * x;
    return 0.5f * x * (1.0f + tanhf(0.7978845608028654f * (x + 0.044715f * x3)));
}

// mma.sync m16n8k16 bf16 (HMMA pipe)
__device__ __forceinline__ void mma16816(float* c, const uint32_t* a, uint32_t b0, uint32_t b1) {
    asm volatile(
        "mma.sync.aligned.m16n8k16.row.col.f32.bf16.bf16.f32 "
        "{%0,%1,%2,%3}, {%4,%5,%6,%7}, {%8,%9}, {%0,%1,%2,%3};"
        : "+f"(c[0]), "+f"(c[1]), "+f"(c[2]), "+f"(c[3])
        : "r"(a[0]), "r"(a[1]), "r"(a[2]), "r"(a[3]), "r"(b0), "r"(b1));
}

__device__ __forceinline__ void ldmatrix_x4(uint32_t* r, uint32_t addr) {
    asm volatile("ldmatrix.sync.aligned.m8n8.x4.shared.b16 {%0,%1,%2,%3}, [%4];"
                 : "=r"(r[0]), "=r"(r[1]), "=r"(r[2]), "=r"(r[3]) : "r"(addr));
}
__device__ __forceinline__ void ldmatrix_x4_t(uint32_t* r, uint32_t addr) {
    asm volatile("ldmatrix.sync.aligned.m8n8.x4.trans.shared.b16 {%0,%1,%2,%3}, [%4];"
                 : "=r"(r[0]), "=r"(r[1]), "=r"(r[2]), "=r"(r[3]) : "r"(addr));
}

__device__ __forceinline__ uint32_t packbf2(float x, float y) {
    __nv_bfloat162 h = __floats2bfloat162_rn(x, y);
    return *reinterpret_cast<uint32_t*>(&h);
}

// split a float pair into packed hi + lo bf16x2
__device__ __forceinline__ void split2(float x, float y, uint32_t& hp, uint32_t& lp) {
    __nv_bfloat16 h0 = __float2bfloat16(x);
    __nv_bfloat16 h1 = __float2bfloat16(y);
    hp = ((uint32_t)__bfloat16_as_ushort(h1) << 16) | __bfloat16_as_ushort(h0);
    lp = packbf2(x - __bfloat162float(h0), y - __bfloat162float(h1));
}

#define CP_ASYNC16(dst, src) \
    asm volatile("cp.async.cg.shared.global [%0], [%1], 16;" :: "r"(dst), "l"(src))
#define CP_COMMIT() asm volatile("cp.async.commit_group;" ::: "memory")
#define CP_WAIT1()  asm volatile("cp.async.wait_group 1;" ::: "memory")
#define CP_WAIT0()  asm volatile("cp.async.wait_group 0;" ::: "memory")

// warp-wide mean/rstd over 8 values per lane (row width 256)
__device__ __forceinline__ float2 warp_ln_stats(const float* v) {
    float s = 0.f, s2 = 0.f;
#pragma unroll
    for (int i = 0; i < 8; i++) { s += v[i]; s2 += v[i] * v[i]; }
#pragma unroll
    for (int o = 16; o > 0; o >>= 1) {
        s  += __shfl_xor_sync(0xffffffffu, s,  o);
        s2 += __shfl_xor_sync(0xffffffffu, s2, o);
    }
    float mean = s * (1.0f / D);
    float var  = s2 * (1.0f / D) - mean * mean;
    return make_float2(mean, rsqrtf(var + 1e-5f));
}

// ---------------------------------------------------------------------------
// init: copy update_tensor into working buffer, zero output
// ---------------------------------------------------------------------------
__global__ void init_kernel(const float* __restrict__ src, float* __restrict__ upd,
                            float* __restrict__ outp) {
    size_t i = (size_t)blockIdx.x * blockDim.x + threadIdx.x;
    float4 v = reinterpret_cast<const float4*>(src)[i];
    reinterpret_cast<float4*>(upd)[i]  = v;
    reinterpret_cast<float4*>(outp)[i] = make_float4(0.f, 0.f, 0.f, 0.f);
}

// ---------------------------------------------------------------------------
// mask -> bytes, all levels at once
// ---------------------------------------------------------------------------
__global__ void maskb_kernel(const float* __restrict__ mask, unsigned char* __restrict__ mb) {
    size_t i = (size_t)blockIdx.x * 256 + threadIdx.x;
    float4 v = reinterpret_cast<const float4*>(mask)[i];
    uchar4 u;
    u.x = v.x > 0.5f; u.y = v.y > 0.5f; u.z = v.z > 0.5f; u.w = v.w > 0.5f;
    reinterpret_cast<uchar4*>(mb)[i] = u;
}

// ---------------------------------------------------------------------------
// weight prep (all 6 weights): Wt[n][k] = W[k][n], bf16 hi/lo
// grid (8, 8, 6), block (32, 8)
// ---------------------------------------------------------------------------
struct WPtrs { const float* w[6]; };

__global__ void prep_w_all_kernel(WPtrs ws,
                                  __nv_bfloat16* __restrict__ Th,
                                  __nv_bfloat16* __restrict__ Tl) {
    __shared__ float t[32][33];
    int wsel = blockIdx.z;
    const float* W = ws.w[wsel];
    __nv_bfloat16* Thw = Th + (size_t)wsel * 65536;
    __nv_bfloat16* Tlw = Tl + (size_t)wsel * 65536;
    int bx = blockIdx.x * 32;
    int by = blockIdx.y * 32;
#pragma unroll
    for (int i = threadIdx.y; i < 32; i += 8)
        t[i][threadIdx.x] = W[(size_t)(by + i) * 256 + bx + threadIdx.x];
    __syncthreads();
#pragma unroll
    for (int i = threadIdx.y; i < 32; i += 8) {
        float v = t[threadIdx.x][i];
        __nv_bfloat16 h = __float2bfloat16(v);
        float r = v - __bfloat162float(h);
        size_t o = (size_t)(bx + i) * 256 + by + threadIdx.x;
        Thw[o] = h;
        Tlw[o] = __float2bfloat16(r);
    }
}

// ---------------------------------------------------------------------------
// gather + LayerNorm(sys) -> bf16 hi/lo.  Warp per row; 8 rows per block.
// ---------------------------------------------------------------------------
__global__ __launch_bounds__(256)
void gather_ln_kernel(const float* __restrict__ emb,
                      const float* __restrict__ upd,
                      const float* __restrict__ sscale,
                      const float* __restrict__ sbias,
                      const int* __restrict__ qidx,
                      const int* __restrict__ kidx,
                      __nv_bfloat16* __restrict__ qnh,
                      __nv_bfloat16* __restrict__ qnl,
                      __nv_bfloat16* __restrict__ knh,
                      __nv_bfloat16* __restrict__ knl) {
    int r = blockIdx.x * 8 + (threadIdx.x >> 5);
    int lane = threadIdx.x & 31;
    int col = lane * 8;
    int b, s;
    __nv_bfloat16 *dh, *dl;
    size_t off;
    if (r < B * NQ) {
        b = r / NQ;
        s = qidx[r % NQ];
        off = (size_t)r * D;
        dh = qnh; dl = qnl;
    } else {
        int r2 = r - B * NQ;
        b = r2 / NK;
        s = kidx[r2 % NK];
        off = (size_t)r2 * D;
        dh = knh; dl = knl;
    }
    float v[8];
    {
        const float4* e4 = reinterpret_cast<const float4*>(emb + (size_t)s * D + col);
        const float4* u4 = reinterpret_cast<const float4*>(upd + ((size_t)b * NS + s) * D + col);
        float4 a0 = e4[0], a1 = e4[1], b0 = u4[0], b1 = u4[1];
        v[0] = a0.x + b0.x; v[1] = a0.y + b0.y; v[2] = a0.z + b0.z; v[3] = a0.w + b0.w;
        v[4] = a1.x + b1.x; v[5] = a1.y + b1.y; v[6] = a1.z + b1.z; v[7] = a1.w + b1.w;
    }
    float2 st = warp_ln_stats(v);
    float4 sc0 = reinterpret_cast<const float4*>(sscale + col)[0];
    float4 sc1 = reinterpret_cast<const float4*>(sscale + col)[1];
    float4 bi0 = reinterpret_cast<const float4*>(sbias + col)[0];
    float4 bi1 = reinterpret_cast<const float4*>(sbias + col)[1];
    float sc[8] = {sc0.x, sc0.y, sc0.z, sc0.w, sc1.x, sc1.y, sc1.z, sc1.w};
    float bi[8] = {bi0.x, bi0.y, bi0.z, bi0.w, bi1.x, bi1.y, bi1.z, bi1.w};
    uint32_t hp[4], lp[4];
#pragma unroll
    for (int i = 0; i < 4; i++) {
        float y0 = (v[2*i]   - st.x) * st.y * sc[2*i]   + bi[2*i];
        float y1 = (v[2*i+1] - st.x) * st.y * sc[2*i+1] + bi[2*i+1];
        split2(y0, y1, hp[i], lp[i]);
    }
    *reinterpret_cast<uint4*>(dh + off + col) = *reinterpret_cast<uint4*>(hp);
    *reinterpret_cast<uint4*>(dl + off + col) = *reinterpret_cast<uint4*>(lp);
}

// ---------------------------------------------------------------------------
// mma.sync GEMM, bf16 hi/lo A operand, cp.async 2-stage pipeline.
// C[M,256] = A[M,256] @ W[256,256];  split-3: Ah*Bh + Ah*Bl + Al*Bh
// CTA 128x128, 8 warps (4x2), warp tile 32x64; K chunks of 32 (8 chunks).
// Stage = 40 KB -> 2 stages = 80 KB -> 2 CTAs/SM.
// MODE: 0 plain, 1 +bias, 2 +bias+gelu.  OUT: 0 fp32 C, 1 bf16 hi/lo.
// ---------------------------------------------------------------------------
#define GPAD 40                           // bf16 elems per smem row (80 B, 16B-aligned)
#define TILE_B (128 * GPAD * 2)           // 10240
#define STAGE_B (4 * TILE_B)              // 40960
#define GEMM_SMEM_BYTES (2 * STAGE_B)     // 81920

__device__ __forceinline__ void gemm_issue_chunk(
    uint32_t stage, int tid,
    const __nv_bfloat16* Ah, const __nv_bfloat16* Al,
    const __nv_bfloat16* Bh, const __nv_bfloat16* Bl,
    int mBase, int nBase, int k0)
{
    const __nv_bfloat16* srcs[4] = {Ah, Al, Bh, Bl};
#pragma unroll
    for (int t4 = 0; t4 < 4; t4++) {
        int base = (t4 < 2) ? mBase : nBase;
#pragma unroll
        for (int it = 0; it < 2; it++) {
            int seg = tid + it * 256;          // 512 segments of 16B
            int row = seg >> 2, j = seg & 3;   // 4 segs (64B) per row
            const void* gp = srcs[t4] + (size_t)(base + row) * 256 + k0 + j * 8;
            uint32_t d = stage + t4 * TILE_B + (uint32_t)((row * GPAD + j * 8) * 2);
            CP_ASYNC16(d, gp);
        }
    }
    CP_COMMIT();
}

template <int MODE, int OUT>
__global__ __launch_bounds__(256, 2)
void gemm_bf16_kernel(const __nv_bfloat16* __restrict__ Ah,
                      const __nv_bfloat16* __restrict__ Al,
                      const __nv_bfloat16* __restrict__ Bth,
                      const __nv_bfloat16* __restrict__ Btl,
                      const float* __restrict__ bias,
                      float* __restrict__ C,
                      __nv_bfloat16* __restrict__ Ch,
                      __nv_bfloat16* __restrict__ Cl) {
    extern __shared__ char smem[];
    const uint32_t sb = smem_u32(smem);

    int tid  = threadIdx.x;
    int wid  = tid >> 5, lane = tid & 31;
    int warpM = wid & 3;
    int warpN = wid >> 2;
    int mBase = blockIdx.x * 128;
    int nBase = blockIdx.y * 128;

    float acc[2][8][4];
#pragma unroll
    for (int i = 0; i < 2; i++)
#pragma unroll
        for (int j = 0; j < 8; j++)
#pragma unroll
            for (int k = 0; k < 4; k++) acc[i][j][k] = 0.f;

    gemm_issue_chunk(sb, tid, Ah, Al, Bth, Btl, mBase, nBase, 0);

    for (int kc = 0; kc < 8; kc++) {
        if (kc < 7)
            gemm_issue_chunk(sb + ((kc + 1) & 1) * STAGE_B, tid, Ah, Al, Bth, Btl,
                             mBase, nBase, (kc + 1) * 32);
        if (kc < 7) { CP_WAIT1(); } else { CP_WAIT0(); }
        __syncthreads();

        uint32_t st = sb + (kc & 1) * STAGE_B;
#pragma unroll
        for (int ks = 0; ks < 2; ks++) {
            int lrow = lane & 15;
            int lcol = ks * 16 + (lane >> 4) * 8;
            uint32_t ah[2][4], al[2][4];
#pragma unroll
            for (int mt = 0; mt < 2; mt++) {
                int row = warpM * 32 + mt * 16 + lrow;
                uint32_t ad = st + (uint32_t)((row * GPAD + lcol) * 2);
                ldmatrix_x4(ah[mt], ad);
                ldmatrix_x4(al[mt], ad + TILE_B);
            }
#pragma unroll
            for (int nt2 = 0; nt2 < 4; nt2++) {
                int row = warpN * 64 + nt2 * 16 + lrow;
                uint32_t bd = st + 2 * TILE_B + (uint32_t)((row * GPAD + lcol) * 2);
                uint32_t bh[4], bl[4];
                ldmatrix_x4(bh, bd);
                ldmatrix_x4(bl, bd + TILE_B);
#pragma unroll
                for (int mt = 0; mt < 2; mt++) {
                    mma16816(acc[mt][nt2 * 2 + 0], ah[mt], bh[0], bh[2]);
                    mma16816(acc[mt][nt2 * 2 + 0], ah[mt], bl[0], bl[2]);
                    mma16816(acc[mt][nt2 * 2 + 0], al[mt], bh[0], bh[2]);
                    mma16816(acc[mt][nt2 * 2 + 1], ah[mt], bh[1], bh[3]);
                    mma16816(acc[mt][nt2 * 2 + 1], ah[mt], bl[1], bl[3]);
                    mma16816(acc[mt][nt2 * 2 + 1], al[mt], bh[1], bh[3]);
                }
            }
        }
        __syncthreads();
    }

    // epilogue
    int g = lane >> 2, tig = lane & 3;
#pragma unroll
    for (int mt = 0; mt < 2; mt++) {
#pragma unroll
        for (int nt = 0; nt < 8; nt++) {
            int row0 = mBase + warpM * 32 + mt * 16 + g;
            int col  = nBase + warpN * 64 + nt * 8 + tig * 2;
            float v0 = acc[mt][nt][0], v1 = acc[mt][nt][1];
            float v2 = acc[mt][nt][2], v3 = acc[mt][nt][3];
            if (MODE >= 1) {
                float bb0 = bias[col], bb1 = bias[col + 1];
                v0 += bb0; v1 += bb1; v2 += bb0; v3 += bb1;
            }
            if (MODE == 2) {
                v0 = gelu_tanh(v0); v1 = gelu_tanh(v1);
                v2 = gelu_tanh(v2); v3 = gelu_tanh(v3);
            }
            if (OUT == 0) {
                *reinterpret_cast<float2*>(C + (size_t)row0 * 256 + col) = make_float2(v0, v1);
                *reinterpret_cast<float2*>(C + (size_t)(row0 + 8) * 256 + col) = make_float2(v2, v3);
            } else {
                uint32_t hp01, lp01, hp23, lp23;
                split2(v0, v1, hp01, lp01);
                split2(v2, v3, hp23, lp23);
                *reinterpret_cast<uint32_t*>(Ch + (size_t)row0 * 256 + col) = hp01;
                *reinterpret_cast<uint32_t*>(Ch + (size_t)(row0 + 8) * 256 + col) = hp23;
                *reinterpret_cast<uint32_t*>(Cl + (size_t)row0 * 256 + col) = lp01;
                *reinterpret_cast<uint32_t*>(Cl + (size_t)(row0 + 8) * 256 + col) = lp23;
            }
        }
    }
}

// ---------------------------------------------------------------------------
// Fused flash attention on HMMA pipe, cp.async double-buffered K/V/mask.
// grid (NQ/128, H, B), 256 threads (8 warps); warp owns 16 query rows.
// __launch_bounds__(256,2) -> 2 CTAs/SM (regs capped at 128).
// ---------------------------------------------------------------------------
#define APAD 72
#define A_KH 0
#define A_KL 9216
#define A_VH 18432
#define A_VL 27648
#define A_MS 36864                 // 128 rows x 80 bytes
#define A_STAGE 47104
#define ATTN_SMEM_BYTES (2 * A_STAGE)   // 94208

__device__ __forceinline__ void attn_stage(
    uint32_t st, int tid,
    const __nv_bfloat16* Kh, const __nv_bfloat16* Kl,
    const __nv_bfloat16* Vh, const __nv_bfloat16* Vl,
    const unsigned char* maskb, int b, int h, int q0, int kb)
{
#pragma unroll
    for (int it = 0; it < 2; it++) {
        int seg = tid + it * 256;        // 512 segments
        int r = seg >> 3, j = seg & 7;
        size_t go = ((size_t)(b * NK + kb + r)) * D + h * DH + j * 8;
        uint32_t off = (uint32_t)((r * APAD + j * 8) * 2);
        CP_ASYNC16(st + A_KH + off, Kh + go);
        CP_ASYNC16(st + A_KL + off, Kl + go);
        CP_ASYNC16(st + A_VH + off, Vh + go);
        CP_ASYNC16(st + A_VL + off, Vl + go);
    }
#pragma unroll
    for (int it = 0; it < 2; it++) {
        int seg = tid + it * 256;        // 512 segments of 16B
        int r = seg >> 2, j = seg & 3;
        CP_ASYNC16(st + A_MS + (uint32_t)(r * 80 + j * 16),
                   maskb + (size_t)(q0 + r) * NK + kb + j * 16);
    }
    CP_COMMIT();
}

__global__ __launch_bounds__(256, 2)
void attn_mma_kernel(const __nv_bfloat16* __restrict__ Qh, const __nv_bfloat16* __restrict__ Ql,
                     const __nv_bfloat16* __restrict__ Kh, const __nv_bfloat16* __restrict__ Kl,
                     const __nv_bfloat16* __restrict__ Vh, const __nv_bfloat16* __restrict__ Vl,
                     const unsigned char* __restrict__ maskb,
                     __nv_bfloat16* __restrict__ ctxh, __nv_bfloat16* __restrict__ ctxl) {
    extern __shared__ char smem[];
    const uint32_t sb = smem_u32(smem);

    int tid = threadIdx.x, wid = tid >> 5, lane = tid & 31;
    int q0 = blockIdx.x * 128, h = blockIdx.y, b = blockIdx.z;
    int g = lane >> 2, tig = lane & 3;
    int lrow = lane & 15, lco = (lane >> 4) * 8;

    // Q fragments directly from gmem
    uint32_t qah[4][4], qal[4][4];
#pragma unroll
    for (int ks = 0; ks < 4; ks++) {
#pragma unroll
        for (int i = 0; i < 4; i++) {
            int row = q0 + wid * 16 + g + (i & 1) * 8;
            int col = h * DH + ks * 16 + tig * 2 + (i >> 1) * 8;
            size_t o = ((size_t)(b * NQ + row)) * D + col;
            qah[ks][i] = *reinterpret_cast<const uint32_t*>(Qh + o);
            qal[ks][i] = *reinterpret_cast<const uint32_t*>(Ql + o);
        }
    }

    float m0 = -1e30f, m1 = -1e30f, l0 = 0.f, l1 = 0.f;
    float oacc[8][4];
#pragma unroll
    for (int j = 0; j < 8; j++)
#pragma unroll
        for (int k = 0; k < 4; k++) oacc[j][k] = 0.f;

    attn_stage(sb, tid, Kh, Kl, Vh, Vl, maskb, b, h, q0, 0);

    for (int c = 0; c < 16; c++) {
        if (c < 15)
            attn_stage(sb + ((c + 1) & 1) * A_STAGE, tid, Kh, Kl, Vh, Vl,
                       maskb, b, h, q0, (c + 1) * 64);
        if (c < 15) { CP_WAIT1(); } else { CP_WAIT0(); }
        __syncthreads();

        uint32_t st = sb + (c & 1) * A_STAGE;
        const unsigned char* msp = reinterpret_cast<const unsigned char*>(
            smem + (c & 1) * A_STAGE + A_MS);

        // S = Q K^T (split-3)
        float sacc[8][4];
#pragma unroll
        for (int j = 0; j < 8; j++)
#pragma unroll
            for (int k = 0; k < 4; k++) sacc[j][k] = 0.f;
#pragma unroll
        for (int ks = 0; ks < 4; ks++) {
#pragma unroll
            for (int nt = 0; nt < 4; nt++) {
                uint32_t bh[4], bl[4];
                uint32_t off = (uint32_t)(((nt * 16 + lrow) * APAD + ks * 16 + lco) * 2);
                ldmatrix_x4(bh, st + A_KH + off);
                ldmatrix_x4(bl, st + A_KL + off);
                mma16816(sacc[nt * 2 + 0], qah[ks], bh[0], bh[2]);
                mma16816(sacc[nt * 2 + 0], qah[ks], bl[0], bl[2]);
                mma16816(sacc[nt * 2 + 0], qal[ks], bh[0], bh[2]);
                mma16816(sacc[nt * 2 + 1], qah[ks], bh[1], bh[3]);
                mma16816(sacc[nt * 2 + 1], qah[ks], bl[1], bl[3]);
                mma16816(sacc[nt * 2 + 1], qal[ks], bh[1], bh[3]);
            }
        }

        // scale + mask
        int qr0 = wid * 16 + g, qr1 = qr0 + 8;
#pragma unroll
        for (int j = 0; j < 8; j++) {
            int col = j * 8 + 2 * tig;
            sacc[j][0] = msp[qr0 * 80 + col]     ? sacc[j][0] * ATTN_SCALE : -1e9f;
            sacc[j][1] = msp[qr0 * 80 + col + 1] ? sacc[j][1] * ATTN_SCALE : -1e9f;
            sacc[j][2] = msp[qr1 * 80 + col]     ? sacc[j][2] * ATTN_SCALE : -1e9f;
            sacc[j][3] = msp[qr1 * 80 + col + 1] ? sacc[j][3] * ATTN_SCALE : -1e9f;
        }

        // online softmax
        float mr0 = -1e30f, mr1 = -1e30f;
#pragma unroll
        for (int j = 0; j < 8; j++) {
            mr0 = fmaxf(mr0, fmaxf(sacc[j][0], sacc[j][1]));
            mr1 = fmaxf(mr1, fmaxf(sacc[j][2], sacc[j][3]));
        }
        mr0 = fmaxf(mr0, __shfl_xor_sync(0xffffffffu, mr0, 1));
        mr0 = fmaxf(mr0, __shfl_xor_sync(0xffffffffu, mr0, 2));
        mr1 = fmaxf(mr1, __shfl_xor_sync(0xffffffffu, mr1, 1));
        mr1 = fmaxf(mr1, __shfl_xor_sync(0xffffffffu, mr1, 2));
        float nm0 = fmaxf(m0, mr0), nm1 = fmaxf(m1, mr1);
        float cor0 = __expf(m0 - nm0), cor1 = __expf(m1 - nm1);
        m0 = nm0; m1 = nm1;

        float ps0 = 0.f, ps1 = 0.f;
        uint32_t pa[4][4], pl[4][4];
#pragma unroll
        for (int j = 0; j < 8; j++) {
            float p0 = __expf(sacc[j][0] - m0);
            float p1 = __expf(sacc[j][1] - m0);
            float p2 = __expf(sacc[j][2] - m1);
            float p3 = __expf(sacc[j][3] - m1);
            ps0 += p0 + p1; ps1 += p2 + p3;
            int kc = j >> 1, o2 = (j & 1) * 2;
            uint32_t hp, lp;
            split2(p0, p1, hp, lp);
            pa[kc][o2 + 0] = hp; pl[kc][o2 + 0] = lp;
            split2(p2, p3, hp, lp);
            pa[kc][o2 + 1] = hp; pl[kc][o2 + 1] = lp;
        }
        ps0 += __shfl_xor_sync(0xffffffffu, ps0, 1);
        ps0 += __shfl_xor_sync(0xffffffffu, ps0, 2);
        ps1 += __shfl_xor_sync(0xffffffffu, ps1, 1);
        ps1 += __shfl_xor_sync(0xffffffffu, ps1, 2);
        l0 = l0 * cor0 + ps0;
        l1 = l1 * cor1 + ps1;
#pragma unroll
        for (int j = 0; j < 8; j++) {
            oacc[j][0] *= cor0; oacc[j][1] *= cor0;
            oacc[j][2] *= cor1; oacc[j][3] *= cor1;
        }

        // O += P V  (P hi/lo, V hi/lo; three-term split)
        int vro = ((lane >> 4) << 3) + (lane & 7);
        int vcb = ((lane >> 3) & 1) << 3;
#pragma unroll
        for (int kc = 0; kc < 4; kc++) {
            int vr = 16 * kc + vro;
#pragma unroll
            for (int vt = 0; vt < 4; vt++) {
                uint32_t vh[4], vl[4];
                uint32_t off = (uint32_t)((vr * APAD + vt * 16 + vcb) * 2);
                ldmatrix_x4_t(vh, st + A_VH + off);
                ldmatrix_x4_t(vl, st + A_VL + off);
                mma16816(oacc[vt * 2 + 0], pa[kc], vh[0], vh[2]);
                mma16816(oacc[vt * 2 + 0], pa[kc], vl[0], vl[2]);
                mma16816(oacc[vt * 2 + 0], pl[kc], vh[0], vh[2]);
                mma16816(oacc[vt * 2 + 1], pa[kc], vh[1], vh[3]);
                mma16816(oacc[vt * 2 + 1], pa[kc], vl[1], vl[3]);
                mma16816(oacc[vt * 2 + 1], pl[kc], vh[1], vh[3]);
            }
        }
        __syncthreads();
    }

    float inv0 = 1.0f / l0, inv1 = 1.0f / l1;
#pragma unroll
    for (int j = 0; j < 8; j++) {
        int col = h * DH + j * 8 + 2 * tig;
        size_t r0 = ((size_t)(b * NQ + q0 + wid * 16 + g)) * D + col;
        uint32_t hp, lp;
        split2(oacc[j][0] * inv0, oacc[j][1] * inv0, hp, lp);
        *reinterpret_cast<uint32_t*>(ctxh + r0) = hp;
        *reinterpret_cast<uint32_t*>(ctxl + r0) = lp;
        split2(oacc[j][2] * inv1, oacc[j][3] * inv1, hp, lp);
        *reinterpret_cast<uint32_t*>(ctxh + r0 + 8 * D) = hp;
        *reinterpret_cast<uint32_t*>(ctxl + r0 + 8 * D) = lp;
    }
}

// ---------------------------------------------------------------------------
// row LayerNorm -> bf16 hi/lo. Warp per row, 8 rows per block.
// ---------------------------------------------------------------------------
__global__ __launch_bounds__(256)
void ln_rows_kernel(const float* __restrict__ x,
                    const float* __restrict__ scale,
                    const float* __restrict__ bias,
                    __nv_bfloat16* __restrict__ oh,
                    __nv_bfloat16* __restrict__ ol) {
    int r = blockIdx.x * 8 + (threadIdx.x >> 5);
    int lane = threadIdx.x & 31;
    int col = lane * 8;
    size_t base = (size_t)r * D + col;
    float v[8];
    {
        float4 a0 = reinterpret_cast<const float4*>(x + base)[0];
        float4 a1 = reinterpret_cast<const float4*>(x + base)[1];
        v[0] = a0.x; v[1] = a0.y; v[2] = a0.z; v[3] = a0.w;
        v[4] = a1.x; v[5] = a1.y; v[6] = a1.z; v[7] = a1.w;
    }
    float2 st = warp_ln_stats(v);
    float4 sc0 = reinterpret_cast<const float4*>(scale + col)[0];
    float4 sc1 = reinterpret_cast<const float4*>(scale + col)[1];
    float4 bi0 = reinterpret_cast<const float4*>(bias + col)[0];
    float4 bi1 = reinterpret_cast<const float4*>(bias + col)[1];
    float sc[8] = {sc0.x, sc0.y, sc0.z, sc0.w, sc1.x, sc1.y, sc1.z, sc1.w};
    float bi[8] = {bi0.x, bi0.y, bi0.z, bi0.w, bi1.x, bi1.y, bi1.z, bi1.w};
    uint32_t hp[4], lp[4];
#pragma unroll
    for (int i = 0; i < 4; i++) {
        float y0 = (v[2*i]   - st.x) * st.y * sc[2*i]   + bi[2*i];
        float y1 = (v[2*i+1] - st.x) * st.y * sc[2*i+1] + bi[2*i+1];
        split2(y0, y1, hp[i], lp[i]);
    }
    *reinterpret_cast<uint4*>(oh + base) = *reinterpret_cast<uint4*>(hp);
    *reinterpret_cast<uint4*>(ol + base) = *reinterpret_cast<uint4*>(lp);
}

// ---------------------------------------------------------------------------
// res = LN_eff( LN_outer( h + ffn ) ); scatter-add. Warp per row.
// ---------------------------------------------------------------------------
__global__ __launch_bounds__(256)
void res_scatter_kernel(const __nv_bfloat16* __restrict__ hh,
                        const __nv_bfloat16* __restrict__ hl,
                        const float* __restrict__ ffn,
                        const float* __restrict__ os, const float* __restrict__ ob,
                        const float* __restrict__ es, const float* __restrict__ eb,
                        const int* __restrict__ qidx,
                        float* __restrict__ upd,
                        float* __restrict__ outp) {
    int bi = blockIdx.x * 8 + (threadIdx.x >> 5);
    int lane = threadIdx.x & 31;
    int col = lane * 8;
    size_t base = (size_t)bi * D + col;

    float v[8];
    {
        uint4 hh4 = *reinterpret_cast<const uint4*>(hh + base);
        uint4 hl4 = *reinterpret_cast<const uint4*>(hl + base);
        const uint32_t* hhp = reinterpret_cast<const uint32_t*>(&hh4);
        const uint32_t* hlp = reinterpret_cast<const uint32_t*>(&hl4);
        float4 f0 = reinterpret_cast<const float4*>(ffn + base)[0];
        float4 f1 = reinterpret_cast<const float4*>(ffn + base)[1];
        float f[8] = {f0.x, f0.y, f0.z, f0.w, f1.x, f1.y, f1.z, f1.w};
#pragma unroll
        for (int i = 0; i < 4; i++) {
            __nv_bfloat162 h2 = *reinterpret_cast<const __nv_bfloat162*>(&hhp[i]);
            __nv_bfloat162 l2 = *reinterpret_cast<const __nv_bfloat162*>(&hlp[i]);
            v[2*i]   = __bfloat162float(h2.x) + __bfloat162float(l2.x) + f[2*i];
            v[2*i+1] = __bfloat162float(h2.y) + __bfloat162float(l2.y) + f[2*i+1];
        }
    }
    float2 st1 = warp_ln_stats(v);
    float4 a0 = reinterpret_cast<const float4*>(os + col)[0];
    float4 a1 = reinterpret_cast<const float4*>(os + col)[1];
    float4 c0 = reinterpret_cast<const float4*>(ob + col)[0];
    float4 c1 = reinterpret_cast<const float4*>(ob + col)[1];
    float osv[8] = {a0.x, a0.y, a0.z, a0.w, a1.x, a1.y, a1.z, a1.w};
    float obv[8] = {c0.x, c0.y, c0.z, c0.w, c1.x, c1.y, c1.z, c1.w};
    float y[8];
#pragma unroll
    for (int i = 0; i < 8; i++) y[i] = (v[i] - st1.x) * st1.y * osv[i] + obv[i];
    float2 st2 = warp_ln_stats(y);
    float4 e0 = reinterpret_cast<const float4*>(es + col)[0];
    float4 e1 = reinterpret_cast<const float4*>(es + col)[1];
    float4 d0 = reinterpret_cast<const float4*>(eb + col)[0];
    float4 d1 = reinterpret_cast<const float4*>(eb + col)[1];
    float esv[8] = {e0.x, e0.y, e0.z, e0.w, e1.x, e1.y, e1.z, e1.w};
    float ebv[8] = {d0.x, d0.y, d0.z, d0.w, d1.x, d1.y, d1.z, d1.w};

    int b = bi / NQ, i = bi % NQ;
    int s = qidx[i];
    size_t off = ((size_t)b * NS + s) * D + col;
#pragma unroll
    for (int k = 0; k < 8; k++) {
        float z = (y[k] - st2.x) * st2.y * esv[k] + ebv[k];
        atomicAdd(&upd[off + k], z);
        atomicAdd(&outp[off + k], z);
    }
}

// ---------------------------------------------------------------------------
// launch
// ---------------------------------------------------------------------------
extern "C" void kernel_launch(void* const* d_in, const int* in_sizes, int n_in,
                              void* d_out, int out_size) {
    const float* update_tensor = (const float*)d_in[0];
    const float* emb   = (const float*)d_in[1];
    const float* mask  = (const float*)d_in[2];
    const float* Wq    = (const float*)d_in[3];
    const float* Wk    = (const float*)d_in[4];
    const float* Wv    = (const float*)d_in[5];
    const float* Wo    = (const float*)d_in[6];
    const float* W1    = (const float*)d_in[7];
    const float* b1    = (const float*)d_in[8];
    const float* W2    = (const float*)d_in[9];
    const float* b2    = (const float*)d_in[10];
    const float* sys_s = (const float*)d_in[11];
    const float* sys_b = (const float*)d_in[12];
    const float* eff_s = (const float*)d_in[13];
    const float* eff_b = (const float*)d_in[14];
    const float* in_s  = (const float*)d_in[15];
    const float* in_b  = (const float*)d_in[16];
    const float* out_s = (const float*)d_in[17];
    const float* out_b = (const float*)d_in[18];
    const int*   qidx  = (const int*)d_in[19];
    const int*   kidx  = (const int*)d_in[20];
    float* outp = (float*)d_out;

    float *p_upd, *p_hraw, *p_ffn;
    __nv_bfloat16 *p_wh, *p_wl, *p_qnh, *p_qnl, *p_knh, *p_knl;
    __nv_bfloat16 *p_Qh, *p_Ql, *p_Kh, *p_Kl, *p_Vh, *p_Vl;
    __nv_bfloat16 *p_ctxh, *p_ctxl, *p_hh, *p_hl, *p_gh, *p_gl;
    unsigned char* p_mb;
    cudaGetSymbolAddress((void**)&p_upd,  g_upd);
    cudaGetSymbolAddress((void**)&p_hraw, g_hraw);
    cudaGetSymbolAddress((void**)&p_ffn,  g_ffn);
    cudaGetSymbolAddress((void**)&p_wh,   g_Wt_hi);
    cudaGetSymbolAddress((void**)&p_wl,   g_Wt_lo);
    cudaGetSymbolAddress((void**)&p_qnh,  g_qnh);
    cudaGetSymbolAddress((void**)&p_qnl,  g_qnl);
    cudaGetSymbolAddress((void**)&p_knh,  g_knh);
    cudaGetSymbolAddress((void**)&p_knl,  g_knl);
    cudaGetSymbolAddress((void**)&p_Qh,   g_Qh);
    cudaGetSymbolAddress((void**)&p_Ql,   g_Ql);
    cudaGetSymbolAddress((void**)&p_Kh,   g_Kh);
    cudaGetSymbolAddress((void**)&p_Kl,   g_Kl);
    cudaGetSymbolAddress((void**)&p_Vh,   g_Vh);
    cudaGetSymbolAddress((void**)&p_Vl,   g_Vl);
    cudaGetSymbolAddress((void**)&p_ctxh, g_ctxh);
    cudaGetSymbolAddress((void**)&p_ctxl, g_ctxl);
    cudaGetSymbolAddress((void**)&p_hh,   g_hh);
    cudaGetSymbolAddress((void**)&p_hl,   g_hl);
    cudaGetSymbolAddress((void**)&p_gh,   g_gh);
    cudaGetSymbolAddress((void**)&p_gl,   g_gl);
    cudaGetSymbolAddress((void**)&p_mb,   g_maskb);

    cudaFuncSetAttribute(gemm_bf16_kernel<0,0>, cudaFuncAttributeMaxDynamicSharedMemorySize, GEMM_SMEM_BYTES);
    cudaFuncSetAttribute(gemm_bf16_kernel<0,1>, cudaFuncAttributeMaxDynamicSharedMemorySize, GEMM_SMEM_BYTES);
    cudaFuncSetAttribute(gemm_bf16_kernel<1,0>, cudaFuncAttributeMaxDynamicSharedMemorySize, GEMM_SMEM_BYTES);
    cudaFuncSetAttribute(gemm_bf16_kernel<2,1>, cudaFuncAttributeMaxDynamicSharedMemorySize, GEMM_SMEM_BYTES);
    cudaFuncSetAttribute(attn_mma_kernel, cudaFuncAttributeMaxDynamicSharedMemorySize, ATTN_SMEM_BYTES);

    // 1: copy mutable state + zero output
    {
        int n4 = (B * NS * D) / 4;
        init_kernel<<<n4 / 256, 256>>>(update_tensor, p_upd, outp);
    }
    // 2: mask -> bytes (all levels)
    maskb_kernel<<<(LVL * NQ * NK / 4) / 256, 256>>>(mask, p_mb);
    // 3: weight prep
    {
        WPtrs ws;
        ws.w[0] = Wq; ws.w[1] = Wk; ws.w[2] = Wv;
        ws.w[3] = Wo; ws.w[4] = W1; ws.w[5] = W2;
        prep_w_all_kernel<<<dim3(8, 8, 6), dim3(32, 8)>>>(ws, p_wh, p_wl);
    }

    for (int l = 0; l < LVL; l++) {
        const int* qi = qidx + l * NQ;
        const int* ki = kidx + l * NK;
        const unsigned char* mb = p_mb + (size_t)l * NQ * NK;

        gather_ln_kernel<<<B * (NQ + NK) / 8, 256>>>(emb, p_upd, sys_s, sys_b, qi, ki,
                                                     p_qnh, p_qnl, p_knh, p_knl);

        gemm_bf16_kernel<0,1><<<dim3(B * NQ / 128, 2), 256, GEMM_SMEM_BYTES>>>(
            p_qnh, p_qnl, p_wh + 0 * 65536, p_wl + 0 * 65536, nullptr, nullptr, p_Qh, p_Ql);
        gemm_bf16_kernel<0,1><<<dim3(B * NK / 128, 2), 256, GEMM_SMEM_BYTES>>>(
            p_knh, p_knl, p_wh + 1 * 65536, p_wl + 1 * 65536, nullptr, nullptr, p_Kh, p_Kl);
        gemm_bf16_kernel<0,1><<<dim3(B * NK / 128, 2), 256, GEMM_SMEM_BYTES>>>(
            p_knh, p_knl, p_wh + 2 * 65536, p_wl + 2 * 65536, nullptr, nullptr, p_Vh, p_Vl);

        attn_mma_kernel<<<dim3(NQ / 128, H, B), 256, ATTN_SMEM_BYTES>>>(
            p_Qh, p_Ql, p_Kh, p_Kl, p_Vh, p_Vl, mb, p_ctxh, p_ctxl);

        gemm_bf16_kernel<0,0><<<dim3(B * NQ / 128, 2), 256, GEMM_SMEM_BYTES>>>(
            p_ctxh, p_ctxl, p_wh + 3 * 65536, p_wl + 3 * 65536, nullptr, p_hraw, nullptr, nullptr);
        ln_rows_kernel<<<B * NQ / 8, 256>>>(p_hraw, in_s, in_b, p_hh, p_hl);

        gemm_bf16_kernel<2,1><<<dim3(B * NQ / 128, 2), 256, GEMM_SMEM_BYTES>>>(
            p_hh, p_hl, p_wh + 4 * 65536, p_wl + 4 * 65536, b1, nullptr, p_gh, p_gl);
        gemm_bf16_kernel<1,0><<<dim3(B * NQ / 128, 2), 256, GEMM_SMEM_BYTES>>>(
            p_gh, p_gl, p_wh + 5 * 65536, p_wl + 5 * 65536, b2, p_ffn, nullptr, nullptr);

        res_scatter_kernel<<<B * NQ / 8, 256>>>(p_hh, p_hl, p_ffn, out_s, out_b, eff_s, eff_b,
                                                qi, p_upd, outp);
    }
}

// round 8
// speedup vs baseline: 3.0708x; 1.0982x over previous
#include <cuda_runtime.h>
#include <cuda_bf16.h>
#include <math.h>
#include <stdint.h>

// Problem constants
#define B    32
#define NS   4096
#define D    256
#define H    4
#define LVL  6
#define NQ   512
#define NK   1024
#define DH   64
#define ATTN_SCALE 0.125f   // 1/sqrt(64)

// ---------------------------------------------------------------------------
// Scratch (no allocations allowed -> device globals)
// ---------------------------------------------------------------------------
__device__ float g_hraw[(size_t)B * NQ * D];
__device__ float g_ffn [(size_t)B * NQ * D];

// bf16 hi/lo activations
__device__ __nv_bfloat16 g_qnh[(size_t)B * NQ * D];
__device__ __nv_bfloat16 g_qnl[(size_t)B * NQ * D];
__device__ __nv_bfloat16 g_knh[(size_t)B * NK * D];
__device__ __nv_bfloat16 g_knl[(size_t)B * NK * D];
__device__ __nv_bfloat16 g_Qh [(size_t)B * NQ * D];
__device__ __nv_bfloat16 g_Ql [(size_t)B * NQ * D];
// interleaved K|V: [B*NK][512]  (K at cols 0..255, V at cols 256..511)
__device__ __nv_bfloat16 g_KVh[(size_t)B * NK * 512];
__device__ __nv_bfloat16 g_KVl[(size_t)B * NK * 512];
__device__ __nv_bfloat16 g_ctxh[(size_t)B * NQ * D];
__device__ __nv_bfloat16 g_ctxl[(size_t)B * NQ * D];
__device__ __nv_bfloat16 g_hh [(size_t)B * NQ * D];
__device__ __nv_bfloat16 g_hl [(size_t)B * NQ * D];
__device__ __nv_bfloat16 g_gh [(size_t)B * NQ * D];
__device__ __nv_bfloat16 g_gl [(size_t)B * NQ * D];

// transposed + bf16 hi/lo decomposed weights: [6][N=256][K=256]
// (Wk at slot 1 and Wv at slot 2 are contiguous -> a [512][256] stacked matrix)
__device__ __nv_bfloat16 g_Wt_hi[6 * 256 * 256];
__device__ __nv_bfloat16 g_Wt_lo[6 * 256 * 256];

// mask as bytes, all levels
__device__ unsigned char g_maskb[(size_t)LVL * NQ * NK];

// ---------------------------------------------------------------------------
// Helpers
// ---------------------------------------------------------------------------
__device__ __forceinline__ uint32_t smem_u32(const void* p) {
    uint32_t a;
    asm("{ .reg .u64 t; cvta.to.shared.u64 t, %1; cvt.u32.u64 %0, t; }" : "=r"(a) : "l"(p));
    return a;
}

__device__ __forceinline__ float gelu_tanh(float x) {
    float x3 = x * x * x;
    return 0.5f * x * (1.0f + tanhf(0.7978845608028654f * (x + 0.044715f * x3)));
}

// mma.sync m16n8k16 bf16 (HMMA pipe)
__device__ __forceinline__ void mma16816(float* c, const uint32_t* a, uint32_t b0, uint32_t b1) {
    asm volatile(
        "mma.sync.aligned.m16n8k16.row.col.f32.bf16.bf16.f32 "
        "{%0,%1,%2,%3}, {%4,%5,%6,%7}, {%8,%9}, {%0,%1,%2,%3};"
        : "+f"(c[0]), "+f"(c[1]), "+f"(c[2]), "+f"(c[3])
        : "r"(a[0]), "r"(a[1]), "r"(a[2]), "r"(a[3]), "r"(b0), "r"(b1));
}

__device__ __forceinline__ void ldmatrix_x4(uint32_t* r, uint32_t addr) {
    asm volatile("ldmatrix.sync.aligned.m8n8.x4.shared.b16 {%0,%1,%2,%3}, [%4];"
                 : "=r"(r[0]), "=r"(r[1]), "=r"(r[2]), "=r"(r[3]) : "r"(addr));
}
__device__ __forceinline__ void ldmatrix_x4_t(uint32_t* r, uint32_t addr) {
    asm volatile("ldmatrix.sync.aligned.m8n8.x4.trans.shared.b16 {%0,%1,%2,%3}, [%4];"
                 : "=r"(r[0]), "=r"(r[1]), "=r"(r[2]), "=r"(r[3]) : "r"(addr));
}

__device__ __forceinline__ uint32_t packbf2(float x, float y) {
    __nv_bfloat162 h = __floats2bfloat162_rn(x, y);
    return *reinterpret_cast<uint32_t*>(&h);
}

// split a float pair into packed hi + lo bf16x2
__device__ __forceinline__ void split2(float x, float y, uint32_t& hp, uint32_t& lp) {
    __nv_bfloat16 h0 = __float2bfloat16(x);
    __nv_bfloat16 h1 = __float2bfloat16(y);
    hp = ((uint32_t)__bfloat16_as_ushort(h1) << 16) | __bfloat16_as_ushort(h0);
    lp = packbf2(x - __bfloat162float(h0), y - __bfloat162float(h1));
}

#define CP_ASYNC16(dst, src) \
    asm volatile("cp.async.cg.shared.global [%0], [%1], 16;" :: "r"(dst), "l"(src))
#define CP_COMMIT() asm volatile("cp.async.commit_group;" ::: "memory")
#define CP_WAIT1()  asm volatile("cp.async.wait_group 1;" ::: "memory")
#define CP_WAIT0()  asm volatile("cp.async.wait_group 0;" ::: "memory")

// warp-wide mean/rstd over 8 values per lane (row width 256)
__device__ __forceinline__ float2 warp_ln_stats(const float* v) {
    float s = 0.f, s2 = 0.f;
#pragma unroll
    for (int i = 0; i < 8; i++) { s += v[i]; s2 += v[i] * v[i]; }
#pragma unroll
    for (int o = 16; o > 0; o >>= 1) {
        s  += __shfl_xor_sync(0xffffffffu, s,  o);
        s2 += __shfl_xor_sync(0xffffffffu, s2, o);
    }
    float mean = s * (1.0f / D);
    float var  = s2 * (1.0f / D) - mean * mean;
    return make_float2(mean, rsqrtf(var + 1e-5f));
}

// ---------------------------------------------------------------------------
// init: zero output (it doubles as the running update delta)
// ---------------------------------------------------------------------------
__global__ void init_kernel(float* __restrict__ outp) {
    size_t i = (size_t)blockIdx.x * blockDim.x + threadIdx.x;
    reinterpret_cast<float4*>(outp)[i] = make_float4(0.f, 0.f, 0.f, 0.f);
}

// ---------------------------------------------------------------------------
// mask -> bytes, all levels at once
// ---------------------------------------------------------------------------
__global__ void maskb_kernel(const float* __restrict__ mask, unsigned char* __restrict__ mb) {
    size_t i = (size_t)blockIdx.x * 256 + threadIdx.x;
    float4 v = reinterpret_cast<const float4*>(mask)[i];
    uchar4 u;
    u.x = v.x > 0.5f; u.y = v.y > 0.5f; u.z = v.z > 0.5f; u.w = v.w > 0.5f;
    reinterpret_cast<uchar4*>(mb)[i] = u;
}

// ---------------------------------------------------------------------------
// weight prep (all 6 weights): Wt[n][k] = W[k][n], bf16 hi/lo
// grid (8, 8, 6), block (32, 8)
// ---------------------------------------------------------------------------
struct WPtrs { const float* w[6]; };

__global__ void prep_w_all_kernel(WPtrs ws,
                                  __nv_bfloat16* __restrict__ Th,
                                  __nv_bfloat16* __restrict__ Tl) {
    __shared__ float t[32][33];
    int wsel = blockIdx.z;
    const float* W = ws.w[wsel];
    __nv_bfloat16* Thw = Th + (size_t)wsel * 65536;
    __nv_bfloat16* Tlw = Tl + (size_t)wsel * 65536;
    int bx = blockIdx.x * 32;
    int by = blockIdx.y * 32;
#pragma unroll
    for (int i = threadIdx.y; i < 32; i += 8)
        t[i][threadIdx.x] = W[(size_t)(by + i) * 256 + bx + threadIdx.x];
    __syncthreads();
#pragma unroll
    for (int i = threadIdx.y; i < 32; i += 8) {
        float v = t[threadIdx.x][i];
        __nv_bfloat16 h = __float2bfloat16(v);
        float r = v - __bfloat162float(h);
        size_t o = (size_t)(bx + i) * 256 + by + threadIdx.x;
        Thw[o] = h;
        Tlw[o] = __float2bfloat16(r);
    }
}

// ---------------------------------------------------------------------------
// gather + LayerNorm(sys) -> bf16 hi/lo.  Warp per row; 8 rows per block.
// current state = upd0 + outp (running delta)
// ---------------------------------------------------------------------------
__global__ __launch_bounds__(256)
void gather_ln_kernel(const float* __restrict__ emb,
                      const float* __restrict__ upd0,
                      const float* __restrict__ outg,
                      const float* __restrict__ sscale,
                      const float* __restrict__ sbias,
                      const int* __restrict__ qidx,
                      const int* __restrict__ kidx,
                      __nv_bfloat16* __restrict__ qnh,
                      __nv_bfloat16* __restrict__ qnl,
                      __nv_bfloat16* __restrict__ knh,
                      __nv_bfloat16* __restrict__ knl) {
    int r = blockIdx.x * 8 + (threadIdx.x >> 5);
    int lane = threadIdx.x & 31;
    int col = lane * 8;
    int b, s;
    __nv_bfloat16 *dh, *dl;
    size_t off;
    if (r < B * NQ) {
        b = r / NQ;
        s = qidx[r % NQ];
        off = (size_t)r * D;
        dh = qnh; dl = qnl;
    } else {
        int r2 = r - B * NQ;
        b = r2 / NK;
        s = kidx[r2 % NK];
        off = (size_t)r2 * D;
        dh = knh; dl = knl;
    }
    float v[8];
    {
        size_t ub = ((size_t)b * NS + s) * D + col;
        const float4* e4 = reinterpret_cast<const float4*>(emb + (size_t)s * D + col);
        const float4* u4 = reinterpret_cast<const float4*>(upd0 + ub);
        const float4* o4 = reinterpret_cast<const float4*>(outg + ub);
        float4 a0 = e4[0], a1 = e4[1], b0 = u4[0], b1 = u4[1], c0 = o4[0], c1 = o4[1];
        v[0] = a0.x + b0.x + c0.x; v[1] = a0.y + b0.y + c0.y;
        v[2] = a0.z + b0.z + c0.z; v[3] = a0.w + b0.w + c0.w;
        v[4] = a1.x + b1.x + c1.x; v[5] = a1.y + b1.y + c1.y;
        v[6] = a1.z + b1.z + c1.z; v[7] = a1.w + b1.w + c1.w;
    }
    float2 st = warp_ln_stats(v);
    float4 sc0 = reinterpret_cast<const float4*>(sscale + col)[0];
    float4 sc1 = reinterpret_cast<const float4*>(sscale + col)[1];
    float4 bi0 = reinterpret_cast<const float4*>(sbias + col)[0];
    float4 bi1 = reinterpret_cast<const float4*>(sbias + col)[1];
    float sc[8] = {sc0.x, sc0.y, sc0.z, sc0.w, sc1.x, sc1.y, sc1.z, sc1.w};
    float bi[8] = {bi0.x, bi0.y, bi0.z, bi0.w, bi1.x, bi1.y, bi1.z, bi1.w};
    uint32_t hp[4], lp[4];
#pragma unroll
    for (int i = 0; i < 4; i++) {
        float y0 = (v[2*i]   - st.x) * st.y * sc[2*i]   + bi[2*i];
        float y1 = (v[2*i+1] - st.x) * st.y * sc[2*i+1] + bi[2*i+1];
        split2(y0, y1, hp[i], lp[i]);
    }
    *reinterpret_cast<uint4*>(dh + off + col) = *reinterpret_cast<uint4*>(hp);
    *reinterpret_cast<uint4*>(dl + off + col) = *reinterpret_cast<uint4*>(lp);
}

// ---------------------------------------------------------------------------
// mma.sync GEMM, bf16 hi/lo A operand, cp.async 2-stage pipeline.
// C[M,NW] = A[M,256] @ W[256,NW];  split-3: Ah*Bh + Ah*Bl + Al*Bh
// CTA 128x128, 8 warps (4x2), warp tile 32x64; K chunks of 32 (8 chunks).
// Stage = 40 KB -> 2 stages = 80 KB -> 2 CTAs/SM.
// MODE: 0 plain, 1 +bias, 2 +bias+gelu.  OUT: 0 fp32 C, 1 bf16 hi/lo.
// ldC = output row stride (256, or 512 for fused K|V).
// ---------------------------------------------------------------------------
#define GPAD 40                           // bf16 elems per smem row (80 B)
#define TILE_B (128 * GPAD * 2)           // 10240
#define STAGE_B (4 * TILE_B)              // 40960
#define GEMM_SMEM_BYTES (2 * STAGE_B)     // 81920

__device__ __forceinline__ void gemm_issue_chunk(
    uint32_t stage, int tid,
    const __nv_bfloat16* Ah, const __nv_bfloat16* Al,
    const __nv_bfloat16* Bh, const __nv_bfloat16* Bl,
    int mBase, int nBase, int k0)
{
    const __nv_bfloat16* srcs[4] = {Ah, Al, Bh, Bl};
#pragma unroll
    for (int t4 = 0; t4 < 4; t4++) {
        int base = (t4 < 2) ? mBase : nBase;
#pragma unroll
        for (int it = 0; it < 2; it++) {
            int seg = tid + it * 256;          // 512 segments of 16B
            int row = seg >> 2, j = seg & 3;   // 4 segs (64B) per row
            const void* gp = srcs[t4] + (size_t)(base + row) * 256 + k0 + j * 8;
            uint32_t d = stage + t4 * TILE_B + (uint32_t)((row * GPAD + j * 8) * 2);
            CP_ASYNC16(d, gp);
        }
    }
    CP_COMMIT();
}

template <int MODE, int OUT>
__global__ __launch_bounds__(256, 2)
void gemm_bf16_kernel(const __nv_bfloat16* __restrict__ Ah,
                      const __nv_bfloat16* __restrict__ Al,
                      const __nv_bfloat16* __restrict__ Bth,
                      const __nv_bfloat16* __restrict__ Btl,
                      const float* __restrict__ bias,
                      float* __restrict__ C,
                      __nv_bfloat16* __restrict__ Ch,
                      __nv_bfloat16* __restrict__ Cl,
                      int ldC) {
    extern __shared__ char smem[];
    const uint32_t sb = smem_u32(smem);

    int tid  = threadIdx.x;
    int wid  = tid >> 5, lane = tid & 31;
    int warpM = wid & 3;
    int warpN = wid >> 2;
    int mBase = blockIdx.x * 128;
    int nBase = blockIdx.y * 128;

    float acc[2][8][4];
#pragma unroll
    for (int i = 0; i < 2; i++)
#pragma unroll
        for (int j = 0; j < 8; j++)
#pragma unroll
            for (int k = 0; k < 4; k++) acc[i][j][k] = 0.f;

    gemm_issue_chunk(sb, tid, Ah, Al, Bth, Btl, mBase, nBase, 0);

    for (int kc = 0; kc < 8; kc++) {
        if (kc < 7)
            gemm_issue_chunk(sb + ((kc + 1) & 1) * STAGE_B, tid, Ah, Al, Bth, Btl,
                             mBase, nBase, (kc + 1) * 32);
        if (kc < 7) { CP_WAIT1(); } else { CP_WAIT0(); }
        __syncthreads();

        uint32_t st = sb + (kc & 1) * STAGE_B;
#pragma unroll
        for (int ks = 0; ks < 2; ks++) {
            int lrow = lane & 15;
            int lcol = ks * 16 + (lane >> 4) * 8;
            uint32_t ah[2][4], al[2][4];
#pragma unroll
            for (int mt = 0; mt < 2; mt++) {
                int row = warpM * 32 + mt * 16 + lrow;
                uint32_t ad = st + (uint32_t)((row * GPAD + lcol) * 2);
                ldmatrix_x4(ah[mt], ad);
                ldmatrix_x4(al[mt], ad + TILE_B);
            }
#pragma unroll
            for (int nt2 = 0; nt2 < 4; nt2++) {
                int row = warpN * 64 + nt2 * 16 + lrow;
                uint32_t bd = st + 2 * TILE_B + (uint32_t)((row * GPAD + lcol) * 2);
                uint32_t bh[4], bl[4];
                ldmatrix_x4(bh, bd);
                ldmatrix_x4(bl, bd + TILE_B);
#pragma unroll
                for (int mt = 0; mt < 2; mt++) {
                    mma16816(acc[mt][nt2 * 2 + 0], ah[mt], bh[0], bh[2]);
                    mma16816(acc[mt][nt2 * 2 + 0], ah[mt], bl[0], bl[2]);
                    mma16816(acc[mt][nt2 * 2 + 0], al[mt], bh[0], bh[2]);
                    mma16816(acc[mt][nt2 * 2 + 1], ah[mt], bh[1], bh[3]);
                    mma16816(acc[mt][nt2 * 2 + 1], ah[mt], bl[1], bl[3]);
                    mma16816(acc[mt][nt2 * 2 + 1], al[mt], bh[1], bh[3]);
                }
            }
        }
        __syncthreads();
    }

    // epilogue
    int g = lane >> 2, tig = lane & 3;
#pragma unroll
    for (int mt = 0; mt < 2; mt++) {
#pragma unroll
        for (int nt = 0; nt < 8; nt++) {
            int row0 = mBase + warpM * 32 + mt * 16 + g;
            int col  = nBase + warpN * 64 + nt * 8 + tig * 2;
            float v0 = acc[mt][nt][0], v1 = acc[mt][nt][1];
            float v2 = acc[mt][nt][2], v3 = acc[mt][nt][3];
            if (MODE >= 1) {
                float bb0 = bias[col], bb1 = bias[col + 1];
                v0 += bb0; v1 += bb1; v2 += bb0; v3 += bb1;
            }
            if (MODE == 2) {
                v0 = gelu_tanh(v0); v1 = gelu_tanh(v1);
                v2 = gelu_tanh(v2); v3 = gelu_tanh(v3);
            }
            if (OUT == 0) {
                *reinterpret_cast<float2*>(C + (size_t)row0 * ldC + col) = make_float2(v0, v1);
                *reinterpret_cast<float2*>(C + (size_t)(row0 + 8) * ldC + col) = make_float2(v2, v3);
            } else {
                uint32_t hp01, lp01, hp23, lp23;
                split2(v0, v1, hp01, lp01);
                split2(v2, v3, hp23, lp23);
                *reinterpret_cast<uint32_t*>(Ch + (size_t)row0 * ldC + col) = hp01;
                *reinterpret_cast<uint32_t*>(Ch + (size_t)(row0 + 8) * ldC + col) = hp23;
                *reinterpret_cast<uint32_t*>(Cl + (size_t)row0 * ldC + col) = lp01;
                *reinterpret_cast<uint32_t*>(Cl + (size_t)(row0 + 8) * ldC + col) = lp23;
            }
        }
    }
}

// ---------------------------------------------------------------------------
// Fused flash attention on HMMA pipe, cp.async double-buffered K/V/mask.
// Static softmax (scores are O(1) after LN; exp never overflows fp32; masked
// entries -> exp(-1e9)=0), so no online-max rescaling and l reduces once.
// grid (NQ/128, H, B), 256 threads (8 warps); warp owns 16 query rows.
// K/V read from interleaved KV buffer (row stride 512, V at +256).
// ---------------------------------------------------------------------------
#define APAD 72
#define A_KH 0
#define A_KL 9216
#define A_VH 18432
#define A_VL 27648
#define A_MS 36864                 // 128 rows x 80 bytes
#define A_STAGE 47104
#define ATTN_SMEM_BYTES (2 * A_STAGE)   // 94208

__device__ __forceinline__ void attn_stage(
    uint32_t st, int tid,
    const __nv_bfloat16* KVh, const __nv_bfloat16* KVl,
    const unsigned char* maskb, int b, int h, int q0, int kb)
{
#pragma unroll
    for (int it = 0; it < 2; it++) {
        int seg = tid + it * 256;        // 512 segments
        int r = seg >> 3, j = seg & 7;
        size_t rowb = ((size_t)(b * NK + kb + r)) * 512 + h * DH + j * 8;
        uint32_t off = (uint32_t)((r * APAD + j * 8) * 2);
        CP_ASYNC16(st + A_KH + off, KVh + rowb);
        CP_ASYNC16(st + A_KL + off, KVl + rowb);
        CP_ASYNC16(st + A_VH + off, KVh + rowb + 256);
        CP_ASYNC16(st + A_VL + off, KVl + rowb + 256);
    }
#pragma unroll
    for (int it = 0; it < 2; it++) {
        int seg = tid + it * 256;        // 512 segments of 16B
        int r = seg >> 2, j = seg & 3;
        CP_ASYNC16(st + A_MS + (uint32_t)(r * 80 + j * 16),
                   maskb + (size_t)(q0 + r) * NK + kb + j * 16);
    }
    CP_COMMIT();
}

__global__ __launch_bounds__(256, 2)
void attn_mma_kernel(const __nv_bfloat16* __restrict__ Qh, const __nv_bfloat16* __restrict__ Ql,
                     const __nv_bfloat16* __restrict__ KVh, const __nv_bfloat16* __restrict__ KVl,
                     const unsigned char* __restrict__ maskb,
                     __nv_bfloat16* __restrict__ ctxh, __nv_bfloat16* __restrict__ ctxl) {
    extern __shared__ char smem[];
    const uint32_t sb = smem_u32(smem);

    int tid = threadIdx.x, wid = tid >> 5, lane = tid & 31;
    int q0 = blockIdx.x * 128, h = blockIdx.y, b = blockIdx.z;
    int g = lane >> 2, tig = lane & 3;
    int lrow = lane & 15, lco = (lane >> 4) * 8;

    // Q fragments directly from gmem
    uint32_t qah[4][4], qal[4][4];
#pragma unroll
    for (int ks = 0; ks < 4; ks++) {
#pragma unroll
        for (int i = 0; i < 4; i++) {
            int row = q0 + wid * 16 + g + (i & 1) * 8;
            int col = h * DH + ks * 16 + tig * 2 + (i >> 1) * 8;
            size_t o = ((size_t)(b * NQ + row)) * D + col;
            qah[ks][i] = *reinterpret_cast<const uint32_t*>(Qh + o);
            qal[ks][i] = *reinterpret_cast<const uint32_t*>(Ql + o);
        }
    }

    float l0 = 0.f, l1 = 0.f;
    float oacc[8][4];
#pragma unroll
    for (int j = 0; j < 8; j++)
#pragma unroll
        for (int k = 0; k < 4; k++) oacc[j][k] = 0.f;

    attn_stage(sb, tid, KVh, KVl, maskb, b, h, q0, 0);

    for (int c = 0; c < 16; c++) {
        if (c < 15)
            attn_stage(sb + ((c + 1) & 1) * A_STAGE, tid, KVh, KVl,
                       maskb, b, h, q0, (c + 1) * 64);
        if (c < 15) { CP_WAIT1(); } else { CP_WAIT0(); }
        __syncthreads();

        uint32_t st = sb + (c & 1) * A_STAGE;
        const unsigned char* msp = reinterpret_cast<const unsigned char*>(
            smem + (c & 1) * A_STAGE + A_MS);

        // S = Q K^T (split-3)
        float sacc[8][4];
#pragma unroll
        for (int j = 0; j < 8; j++)
#pragma unroll
            for (int k = 0; k < 4; k++) sacc[j][k] = 0.f;
#pragma unroll
        for (int ks = 0; ks < 4; ks++) {
#pragma unroll
            for (int nt = 0; nt < 4; nt++) {
                uint32_t bh[4], bl[4];
                uint32_t off = (uint32_t)(((nt * 16 + lrow) * APAD + ks * 16 + lco) * 2);
                ldmatrix_x4(bh, st + A_KH + off);
                ldmatrix_x4(bl, st + A_KL + off);
                mma16816(sacc[nt * 2 + 0], qah[ks], bh[0], bh[2]);
                mma16816(sacc[nt * 2 + 0], qah[ks], bl[0], bl[2]);
                mma16816(sacc[nt * 2 + 0], qal[ks], bh[0], bh[2]);
                mma16816(sacc[nt * 2 + 1], qah[ks], bh[1], bh[3]);
                mma16816(sacc[nt * 2 + 1], qah[ks], bl[1], bl[3]);
                mma16816(sacc[nt * 2 + 1], qal[ks], bh[1], bh[3]);
            }
        }

        // p = exp(scale*s) masked -> 0; accumulate l locally (no rescaling)
        int qr0 = wid * 16 + g, qr1 = qr0 + 8;
        uint32_t pa[4][4], pl[4][4];
#pragma unroll
        for (int j = 0; j < 8; j++) {
            int col = j * 8 + 2 * tig;
            float s0 = msp[qr0 * 80 + col]     ? sacc[j][0] * ATTN_SCALE : -1e9f;
            float s1 = msp[qr0 * 80 + col + 1] ? sacc[j][1] * ATTN_SCALE : -1e9f;
            float s2 = msp[qr1 * 80 + col]     ? sacc[j][2] * ATTN_SCALE : -1e9f;
            float s3 = msp[qr1 * 80 + col + 1] ? sacc[j][3] * ATTN_SCALE : -1e9f;
            float p0 = __expf(s0);
            float p1 = __expf(s1);
            float p2 = __expf(s2);
            float p3 = __expf(s3);
            l0 += p0 + p1; l1 += p2 + p3;
            int kc = j >> 1, o2 = (j & 1) * 2;
            uint32_t hp, lp;
            split2(p0, p1, hp, lp);
            pa[kc][o2 + 0] = hp; pl[kc][o2 + 0] = lp;
            split2(p2, p3, hp, lp);
            pa[kc][o2 + 1] = hp; pl[kc][o2 + 1] = lp;
        }

        // O += P V  (P hi/lo, V hi/lo; three-term split)
        int vro = ((lane >> 4) << 3) + (lane & 7);
        int vcb = ((lane >> 3) & 1) << 3;
#pragma unroll
        for (int kc = 0; kc < 4; kc++) {
            int vr = 16 * kc + vro;
#pragma unroll
            for (int vt = 0; vt < 4; vt++) {
                uint32_t vh[4], vl[4];
                uint32_t off = (uint32_t)((vr * APAD + vt * 16 + vcb) * 2);
                ldmatrix_x4_t(vh, st + A_VH + off);
                ldmatrix_x4_t(vl, st + A_VL + off);
                mma16816(oacc[vt * 2 + 0], pa[kc], vh[0], vh[2]);
                mma16816(oacc[vt * 2 + 0], pa[kc], vl[0], vl[2]);
                mma16816(oacc[vt * 2 + 0], pl[kc], vh[0], vh[2]);
                mma16816(oacc[vt * 2 + 1], pa[kc], vh[1], vh[3]);
                mma16816(oacc[vt * 2 + 1], pa[kc], vl[1], vl[3]);
                mma16816(oacc[vt * 2 + 1], pl[kc], vh[1], vh[3]);
            }
        }
        __syncthreads();
    }

    // row-sum reduction once at the end
    l0 += __shfl_xor_sync(0xffffffffu, l0, 1);
    l0 += __shfl_xor_sync(0xffffffffu, l0, 2);
    l1 += __shfl_xor_sync(0xffffffffu, l1, 1);
    l1 += __shfl_xor_sync(0xffffffffu, l1, 2);

    float inv0 = 1.0f / l0, inv1 = 1.0f / l1;
#pragma unroll
    for (int j = 0; j < 8; j++) {
        int col = h * DH + j * 8 + 2 * tig;
        size_t r0 = ((size_t)(b * NQ + q0 + wid * 16 + g)) * D + col;
        uint32_t hp, lp;
        split2(oacc[j][0] * inv0, oacc[j][1] * inv0, hp, lp);
        *reinterpret_cast<uint32_t*>(ctxh + r0) = hp;
        *reinterpret_cast<uint32_t*>(ctxl + r0) = lp;
        split2(oacc[j][2] * inv1, oacc[j][3] * inv1, hp, lp);
        *reinterpret_cast<uint32_t*>(ctxh + r0 + 8 * D) = hp;
        *reinterpret_cast<uint32_t*>(ctxl + r0 + 8 * D) = lp;
    }
}

// ---------------------------------------------------------------------------
// row LayerNorm -> bf16 hi/lo. Warp per row, 8 rows per block.
// ---------------------------------------------------------------------------
__global__ __launch_bounds__(256)
void ln_rows_kernel(const float* __restrict__ x,
                    const float* __restrict__ scale,
                    const float* __restrict__ bias,
                    __nv_bfloat16* __restrict__ oh,
                    __nv_bfloat16* __restrict__ ol) {
    int r = blockIdx.x * 8 + (threadIdx.x >> 5);
    int lane = threadIdx.x & 31;
    int col = lane * 8;
    size_t base = (size_t)r * D + col;
    float v[8];
    {
        float4 a0 = reinterpret_cast<const float4*>(x + base)[0];
        float4 a1 = reinterpret_cast<const float4*>(x + base)[1];
        v[0] = a0.x; v[1] = a0.y; v[2] = a0.z; v[3] = a0.w;
        v[4] = a1.x; v[5] = a1.y; v[6] = a1.z; v[7] = a1.w;
    }
    float2 st = warp_ln_stats(v);
    float4 sc0 = reinterpret_cast<const float4*>(scale + col)[0];
    float4 sc1 = reinterpret_cast<const float4*>(scale + col)[1];
    float4 bi0 = reinterpret_cast<const float4*>(bias + col)[0];
    float4 bi1 = reinterpret_cast<const float4*>(bias + col)[1];
    float sc[8] = {sc0.x, sc0.y, sc0.z, sc0.w, sc1.x, sc1.y, sc1.z, sc1.w};
    float bi[8] = {bi0.x, bi0.y, bi0.z, bi0.w, bi1.x, bi1.y, bi1.z, bi1.w};
    uint32_t hp[4], lp[4];
#pragma unroll
    for (int i = 0; i < 4; i++) {
        float y0 = (v[2*i]   - st.x) * st.y * sc[2*i]   + bi[2*i];
        float y1 = (v[2*i+1] - st.x) * st.y * sc[2*i+1] + bi[2*i+1];
        split2(y0, y1, hp[i], lp[i]);
    }
    *reinterpret_cast<uint4*>(oh + base) = *reinterpret_cast<uint4*>(hp);
    *reinterpret_cast<uint4*>(ol + base) = *reinterpret_cast<uint4*>(lp);
}

// ---------------------------------------------------------------------------
// res = LN_eff( LN_outer( h + ffn ) ); scatter-add into outp only. Warp/row.
// ---------------------------------------------------------------------------
__global__ __launch_bounds__(256)
void res_scatter_kernel(const __nv_bfloat16* __restrict__ hh,
                        const __nv_bfloat16* __restrict__ hl,
                        const float* __restrict__ ffn,
                        const float* __restrict__ os, const float* __restrict__ ob,
                        const float* __restrict__ es, const float* __restrict__ eb,
                        const int* __restrict__ qidx,
                        float* __restrict__ outp) {
    int bi = blockIdx.x * 8 + (threadIdx.x >> 5);
    int lane = threadIdx.x & 31;
    int col = lane * 8;
    size_t base = (size_t)bi * D + col;

    float v[8];
    {
        uint4 hh4 = *reinterpret_cast<const uint4*>(hh + base);
        uint4 hl4 = *reinterpret_cast<const uint4*>(hl + base);
        const uint32_t* hhp = reinterpret_cast<const uint32_t*>(&hh4);
        const uint32_t* hlp = reinterpret_cast<const uint32_t*>(&hl4);
        float4 f0 = reinterpret_cast<const float4*>(ffn + base)[0];
        float4 f1 = reinterpret_cast<const float4*>(ffn + base)[1];
        float f[8] = {f0.x, f0.y, f0.z, f0.w, f1.x, f1.y, f1.z, f1.w};
#pragma unroll
        for (int i = 0; i < 4; i++) {
            __nv_bfloat162 h2 = *reinterpret_cast<const __nv_bfloat162*>(&hhp[i]);
            __nv_bfloat162 l2 = *reinterpret_cast<const __nv_bfloat162*>(&hlp[i]);
            v[2*i]   = __bfloat162float(h2.x) + __bfloat162float(l2.x) + f[2*i];
            v[2*i+1] = __bfloat162float(h2.y) + __bfloat162float(l2.y) + f[2*i+1];
        }
    }
    float2 st1 = warp_ln_stats(v);
    float4 a0 = reinterpret_cast<const float4*>(os + col)[0];
    float4 a1 = reinterpret_cast<const float4*>(os + col)[1];
    float4 c0 = reinterpret_cast<const float4*>(ob + col)[0];
    float4 c1 = reinterpret_cast<const float4*>(ob + col)[1];
    float osv[8] = {a0.x, a0.y, a0.z, a0.w, a1.x, a1.y, a1.z, a1.w};
    float obv[8] = {c0.x, c0.y, c0.z, c0.w, c1.x, c1.y, c1.z, c1.w};
    float y[8];
#pragma unroll
    for (int i = 0; i < 8; i++) y[i] = (v[i] - st1.x) * st1.y * osv[i] + obv[i];
    float2 st2 = warp_ln_stats(y);
    float4 e0 = reinterpret_cast<const float4*>(es + col)[0];
    float4 e1 = reinterpret_cast<const float4*>(es + col)[1];
    float4 d0 = reinterpret_cast<const float4*>(eb + col)[0];
    float4 d1 = reinterpret_cast<const float4*>(eb + col)[1];
    float esv[8] = {e0.x, e0.y, e0.z, e0.w, e1.x, e1.y, e1.z, e1.w};
    float ebv[8] = {d0.x, d0.y, d0.z, d0.w, d1.x, d1.y, d1.z, d1.w};

    int b = bi / NQ, i = bi % NQ;
    int s = qidx[i];
    size_t off = ((size_t)b * NS + s) * D + col;
#pragma unroll
    for (int k = 0; k < 8; k++) {
        float z = (y[k] - st2.x) * st2.y * esv[k] + ebv[k];
        atomicAdd(&outp[off + k], z);
    }
}

// ---------------------------------------------------------------------------
// launch
// ---------------------------------------------------------------------------
extern "C" void kernel_launch(void* const* d_in, const int* in_sizes, int n_in,
                              void* d_out, int out_size) {
    const float* update_tensor = (const float*)d_in[0];
    const float* emb   = (const float*)d_in[1];
    const float* mask  = (const float*)d_in[2];
    const float* Wq    = (const float*)d_in[3];
    const float* Wk    = (const float*)d_in[4];
    const float* Wv    = (const float*)d_in[5];
    const float* Wo    = (const float*)d_in[6];
    const float* W1    = (const float*)d_in[7];
    const float* b1    = (const float*)d_in[8];
    const float* W2    = (const float*)d_in[9];
    const float* b2    = (const float*)d_in[10];
    const float* sys_s = (const float*)d_in[11];
    const float* sys_b = (const float*)d_in[12];
    const float* eff_s = (const float*)d_in[13];
    const float* eff_b = (const float*)d_in[14];
    const float* in_s  = (const float*)d_in[15];
    const float* in_b  = (const float*)d_in[16];
    const float* out_s = (const float*)d_in[17];
    const float* out_b = (const float*)d_in[18];
    const int*   qidx  = (const int*)d_in[19];
    const int*   kidx  = (const int*)d_in[20];
    float* outp = (float*)d_out;

    float *p_hraw, *p_ffn;
    __nv_bfloat16 *p_wh, *p_wl, *p_qnh, *p_qnl, *p_knh, *p_knl;
    __nv_bfloat16 *p_Qh, *p_Ql, *p_KVh, *p_KVl;
    __nv_bfloat16 *p_ctxh, *p_ctxl, *p_hh, *p_hl, *p_gh, *p_gl;
    unsigned char* p_mb;
    cudaGetSymbolAddress((void**)&p_hraw, g_hraw);
    cudaGetSymbolAddress((void**)&p_ffn,  g_ffn);
    cudaGetSymbolAddress((void**)&p_wh,   g_Wt_hi);
    cudaGetSymbolAddress((void**)&p_wl,   g_Wt_lo);
    cudaGetSymbolAddress((void**)&p_qnh,  g_qnh);
    cudaGetSymbolAddress((void**)&p_qnl,  g_qnl);
    cudaGetSymbolAddress((void**)&p_knh,  g_knh);
    cudaGetSymbolAddress((void**)&p_knl,  g_knl);
    cudaGetSymbolAddress((void**)&p_Qh,   g_Qh);
    cudaGetSymbolAddress((void**)&p_Ql,   g_Ql);
    cudaGetSymbolAddress((void**)&p_KVh,  g_KVh);
    cudaGetSymbolAddress((void**)&p_KVl,  g_KVl);
    cudaGetSymbolAddress((void**)&p_ctxh, g_ctxh);
    cudaGetSymbolAddress((void**)&p_ctxl, g_ctxl);
    cudaGetSymbolAddress((void**)&p_hh,   g_hh);
    cudaGetSymbolAddress((void**)&p_hl,   g_hl);
    cudaGetSymbolAddress((void**)&p_gh,   g_gh);
    cudaGetSymbolAddress((void**)&p_gl,   g_gl);
    cudaGetSymbolAddress((void**)&p_mb,   g_maskb);

    cudaFuncSetAttribute(gemm_bf16_kernel<0,0>, cudaFuncAttributeMaxDynamicSharedMemorySize, GEMM_SMEM_BYTES);
    cudaFuncSetAttribute(gemm_bf16_kernel<0,1>, cudaFuncAttributeMaxDynamicSharedMemorySize, GEMM_SMEM_BYTES);
    cudaFuncSetAttribute(gemm_bf16_kernel<1,0>, cudaFuncAttributeMaxDynamicSharedMemorySize, GEMM_SMEM_BYTES);
    cudaFuncSetAttribute(gemm_bf16_kernel<2,1>, cudaFuncAttributeMaxDynamicSharedMemorySize, GEMM_SMEM_BYTES);
    cudaFuncSetAttribute(attn_mma_kernel, cudaFuncAttributeMaxDynamicSharedMemorySize, ATTN_SMEM_BYTES);

    // 1: zero output (doubles as running update delta)
    init_kernel<<<(B * NS * D / 4) / 256, 256>>>(outp);
    // 2: mask -> bytes (all levels)
    maskb_kernel<<<(LVL * NQ * NK / 4) / 256, 256>>>(mask, p_mb);
    // 3: weight prep
    {
        WPtrs ws;
        ws.w[0] = Wq; ws.w[1] = Wk; ws.w[2] = Wv;
        ws.w[3] = Wo; ws.w[4] = W1; ws.w[5] = W2;
        prep_w_all_kernel<<<dim3(8, 8, 6), dim3(32, 8)>>>(ws, p_wh, p_wl);
    }

    for (int l = 0; l < LVL; l++) {
        const int* qi = qidx + l * NQ;
        const int* ki = kidx + l * NK;
        const unsigned char* mb = p_mb + (size_t)l * NQ * NK;

        gather_ln_kernel<<<B * (NQ + NK) / 8, 256>>>(emb, update_tensor, outp,
                                                     sys_s, sys_b, qi, ki,
                                                     p_qnh, p_qnl, p_knh, p_knl);

        // Q projection (N=256)
        gemm_bf16_kernel<0,1><<<dim3(B * NQ / 128, 2), 256, GEMM_SMEM_BYTES>>>(
            p_qnh, p_qnl, p_wh + 1 * 0 + 0 * 65536, p_wl + 0 * 65536,
            nullptr, nullptr, p_Qh, p_Ql, 256);
        // fused K|V projection (N=512, stacked Wk;Wv weights)
        gemm_bf16_kernel<0,1><<<dim3(B * NK / 128, 4), 256, GEMM_SMEM_BYTES>>>(
            p_knh, p_knl, p_wh + 1 * 65536, p_wl + 1 * 65536,
            nullptr, nullptr, p_KVh, p_KVl, 512);

        attn_mma_kernel<<<dim3(NQ / 128, H, B), 256, ATTN_SMEM_BYTES>>>(
            p_Qh, p_Ql, p_KVh, p_KVl, mb, p_ctxh, p_ctxl);

        gemm_bf16_kernel<0,0><<<dim3(B * NQ / 128, 2), 256, GEMM_SMEM_BYTES>>>(
            p_ctxh, p_ctxl, p_wh + 3 * 65536, p_wl + 3 * 65536,
            nullptr, p_hraw, nullptr, nullptr, 256);
        ln_rows_kernel<<<B * NQ / 8, 256>>>(p_hraw, in_s, in_b, p_hh, p_hl);

        gemm_bf16_kernel<2,1><<<dim3(B * NQ / 128, 2), 256, GEMM_SMEM_BYTES>>>(
            p_hh, p_hl, p_wh + 4 * 65536, p_wl + 4 * 65536,
            b1, nullptr, p_gh, p_gl, 256);
        gemm_bf16_kernel<1,0><<<dim3(B * NQ / 128, 2), 256, GEMM_SMEM_BYTES>>>(
            p_gh, p_gl, p_wh + 5 * 65536, p_wl + 5 * 65536,
            b2, p_ffn, nullptr, nullptr, 256);

        res_scatter_kernel<<<B * NQ / 8, 256>>>(p_hh, p_hl, p_ffn, out_s, out_b,
                                                eff_s, eff_b, qi, outp);
    }
}

// round 9
// speedup vs baseline: 3.1778x; 1.0348x over previous
#include <cuda_runtime.h>
#include <cuda_bf16.h>
#include <math.h>
#include <stdint.h>

// Problem constants
#define B    32
#define NS   4096
#define D    256
#define H    4
#define LVL  6
#define NQ   512
#define NK   1024
#define DH   64
#define ATTN_SCALE 0.125f   // 1/sqrt(64), exact power of two

// ---------------------------------------------------------------------------
// Scratch (no allocations allowed -> device globals)
// ---------------------------------------------------------------------------
__device__ __nv_bfloat16 g_qnh[(size_t)B * NQ * D];
__device__ __nv_bfloat16 g_qnl[(size_t)B * NQ * D];
__device__ __nv_bfloat16 g_knh[(size_t)B * NK * D];
__device__ __nv_bfloat16 g_knl[(size_t)B * NK * D];
__device__ __nv_bfloat16 g_Qh [(size_t)B * NQ * D];
__device__ __nv_bfloat16 g_Ql [(size_t)B * NQ * D];
// interleaved K|V: [B*NK][512]
__device__ __nv_bfloat16 g_KVh[(size_t)B * NK * 512];
__device__ __nv_bfloat16 g_KVl[(size_t)B * NK * 512];
__device__ __nv_bfloat16 g_ctxh[(size_t)B * NQ * D];
__device__ __nv_bfloat16 g_ctxl[(size_t)B * NQ * D];
__device__ __nv_bfloat16 g_hh [(size_t)B * NQ * D];
__device__ __nv_bfloat16 g_hl [(size_t)B * NQ * D];
__device__ __nv_bfloat16 g_gh [(size_t)B * NQ * D];
__device__ __nv_bfloat16 g_gl [(size_t)B * NQ * D];

// transposed + bf16 hi/lo decomposed weights: [6][N=256][K=256]
__device__ __nv_bfloat16 g_Wt_hi[6 * 256 * 256];
__device__ __nv_bfloat16 g_Wt_lo[6 * 256 * 256];

// mask as bytes, all levels
__device__ unsigned char g_maskb[(size_t)LVL * NQ * NK];

// ---------------------------------------------------------------------------
// Helpers
// ---------------------------------------------------------------------------
__device__ __forceinline__ uint32_t smem_u32(const void* p) {
    uint32_t a;
    asm("{ .reg .u64 t; cvta.to.shared.u64 t, %1; cvt.u32.u64 %0, t; }" : "=r"(a) : "l"(p));
    return a;
}

__device__ __forceinline__ float gelu_tanh(float x) {
    float x3 = x * x * x;
    return 0.5f * x * (1.0f + tanhf(0.7978845608028654f * (x + 0.044715f * x3)));
}

__device__ __forceinline__ void mma16816(float* c, const uint32_t* a, uint32_t b0, uint32_t b1) {
    asm volatile(
        "mma.sync.aligned.m16n8k16.row.col.f32.bf16.bf16.f32 "
        "{%0,%1,%2,%3}, {%4,%5,%6,%7}, {%8,%9}, {%0,%1,%2,%3};"
        : "+f"(c[0]), "+f"(c[1]), "+f"(c[2]), "+f"(c[3])
        : "r"(a[0]), "r"(a[1]), "r"(a[2]), "r"(a[3]), "r"(b0), "r"(b1));
}

__device__ __forceinline__ void ldmatrix_x4(uint32_t* r, uint32_t addr) {
    asm volatile("ldmatrix.sync.aligned.m8n8.x4.shared.b16 {%0,%1,%2,%3}, [%4];"
                 : "=r"(r[0]), "=r"(r[1]), "=r"(r[2]), "=r"(r[3]) : "r"(addr));
}
__device__ __forceinline__ void ldmatrix_x4_t(uint32_t* r, uint32_t addr) {
    asm volatile("ldmatrix.sync.aligned.m8n8.x4.trans.shared.b16 {%0,%1,%2,%3}, [%4];"
                 : "=r"(r[0]), "=r"(r[1]), "=r"(r[2]), "=r"(r[3]) : "r"(addr));
}

__device__ __forceinline__ uint32_t packbf2(float x, float y) {
    __nv_bfloat162 h = __floats2bfloat162_rn(x, y);
    return *reinterpret_cast<uint32_t*>(&h);
}

__device__ __forceinline__ void split2(float x, float y, uint32_t& hp, uint32_t& lp) {
    __nv_bfloat16 h0 = __float2bfloat16(x);
    __nv_bfloat16 h1 = __float2bfloat16(y);
    hp = ((uint32_t)__bfloat16_as_ushort(h1) << 16) | __bfloat16_as_ushort(h0);
    lp = packbf2(x - __bfloat162float(h0), y - __bfloat162float(h1));
}

__device__ __forceinline__ float2 bf2_sum(uint32_t hp, uint32_t lp) {
    __nv_bfloat162 h2 = *reinterpret_cast<const __nv_bfloat162*>(&hp);
    __nv_bfloat162 l2 = *reinterpret_cast<const __nv_bfloat162*>(&lp);
    return make_float2(__bfloat162float(h2.x) + __bfloat162float(l2.x),
                       __bfloat162float(h2.y) + __bfloat162float(l2.y));
}

#define CP_ASYNC16(dst, src) \
    asm volatile("cp.async.cg.shared.global [%0], [%1], 16;" :: "r"(dst), "l"(src))
#define CP_COMMIT() asm volatile("cp.async.commit_group;" ::: "memory")
#define CP_WAIT1()  asm volatile("cp.async.wait_group 1;" ::: "memory")
#define CP_WAIT0()  asm volatile("cp.async.wait_group 0;" ::: "memory")

// warp-wide mean/rstd over 8 values per lane (row width 256)
__device__ __forceinline__ float2 warp_ln_stats(const float* v) {
    float s = 0.f, s2 = 0.f;
#pragma unroll
    for (int i = 0; i < 8; i++) { s += v[i]; s2 += v[i] * v[i]; }
#pragma unroll
    for (int o = 16; o > 0; o >>= 1) {
        s  += __shfl_xor_sync(0xffffffffu, s,  o);
        s2 += __shfl_xor_sync(0xffffffffu, s2, o);
    }
    float mean = s * (1.0f / D);
    float var  = s2 * (1.0f / D) - mean * mean;
    return make_float2(mean, rsqrtf(var + 1e-5f));
}

// ---------------------------------------------------------------------------
// init / mask / weight prep
// ---------------------------------------------------------------------------
__global__ void init_kernel(float* __restrict__ outp) {
    size_t i = (size_t)blockIdx.x * blockDim.x + threadIdx.x;
    reinterpret_cast<float4*>(outp)[i] = make_float4(0.f, 0.f, 0.f, 0.f);
}

__global__ void maskb_kernel(const float* __restrict__ mask, unsigned char* __restrict__ mb) {
    size_t i = (size_t)blockIdx.x * 256 + threadIdx.x;
    float4 v = reinterpret_cast<const float4*>(mask)[i];
    uchar4 u;
    u.x = v.x > 0.5f; u.y = v.y > 0.5f; u.z = v.z > 0.5f; u.w = v.w > 0.5f;
    reinterpret_cast<uchar4*>(mb)[i] = u;
}

struct WPtrs { const float* w[6]; };

__global__ void prep_w_all_kernel(WPtrs ws,
                                  __nv_bfloat16* __restrict__ Th,
                                  __nv_bfloat16* __restrict__ Tl) {
    __shared__ float t[32][33];
    int wsel = blockIdx.z;
    const float* W = ws.w[wsel];
    __nv_bfloat16* Thw = Th + (size_t)wsel * 65536;
    __nv_bfloat16* Tlw = Tl + (size_t)wsel * 65536;
    int bx = blockIdx.x * 32;
    int by = blockIdx.y * 32;
#pragma unroll
    for (int i = threadIdx.y; i < 32; i += 8)
        t[i][threadIdx.x] = W[(size_t)(by + i) * 256 + bx + threadIdx.x];
    __syncthreads();
#pragma unroll
    for (int i = threadIdx.y; i < 32; i += 8) {
        float v = t[threadIdx.x][i];
        __nv_bfloat16 h = __float2bfloat16(v);
        float r = v - __bfloat162float(h);
        size_t o = (size_t)(bx + i) * 256 + by + threadIdx.x;
        Thw[o] = h;
        Tlw[o] = __float2bfloat16(r);
    }
}

// ---------------------------------------------------------------------------
// gather + LayerNorm(sys) -> bf16 hi/lo.  Warp per row; 8 rows per block.
// current state = upd0 + outp (running delta)
// ---------------------------------------------------------------------------
__global__ __launch_bounds__(256)
void gather_ln_kernel(const float* __restrict__ emb,
                      const float* __restrict__ upd0,
                      const float* __restrict__ outg,
                      const float* __restrict__ sscale,
                      const float* __restrict__ sbias,
                      const int* __restrict__ qidx,
                      const int* __restrict__ kidx,
                      __nv_bfloat16* __restrict__ qnh,
                      __nv_bfloat16* __restrict__ qnl,
                      __nv_bfloat16* __restrict__ knh,
                      __nv_bfloat16* __restrict__ knl) {
    int r = blockIdx.x * 8 + (threadIdx.x >> 5);
    int lane = threadIdx.x & 31;
    int col = lane * 8;
    int b, s;
    __nv_bfloat16 *dh, *dl;
    size_t off;
    if (r < B * NQ) {
        b = r / NQ;
        s = qidx[r % NQ];
        off = (size_t)r * D;
        dh = qnh; dl = qnl;
    } else {
        int r2 = r - B * NQ;
        b = r2 / NK;
        s = kidx[r2 % NK];
        off = (size_t)r2 * D;
        dh = knh; dl = knl;
    }
    float v[8];
    {
        size_t ub = ((size_t)b * NS + s) * D + col;
        const float4* e4 = reinterpret_cast<const float4*>(emb + (size_t)s * D + col);
        const float4* u4 = reinterpret_cast<const float4*>(upd0 + ub);
        const float4* o4 = reinterpret_cast<const float4*>(outg + ub);
        float4 a0 = e4[0], a1 = e4[1], b0 = u4[0], b1 = u4[1], c0 = o4[0], c1 = o4[1];
        v[0] = a0.x + b0.x + c0.x; v[1] = a0.y + b0.y + c0.y;
        v[2] = a0.z + b0.z + c0.z; v[3] = a0.w + b0.w + c0.w;
        v[4] = a1.x + b1.x + c1.x; v[5] = a1.y + b1.y + c1.y;
        v[6] = a1.z + b1.z + c1.z; v[7] = a1.w + b1.w + c1.w;
    }
    float2 st = warp_ln_stats(v);
    float4 sc0 = reinterpret_cast<const float4*>(sscale + col)[0];
    float4 sc1 = reinterpret_cast<const float4*>(sscale + col)[1];
    float4 bi0 = reinterpret_cast<const float4*>(sbias + col)[0];
    float4 bi1 = reinterpret_cast<const float4*>(sbias + col)[1];
    float sc[8] = {sc0.x, sc0.y, sc0.z, sc0.w, sc1.x, sc1.y, sc1.z, sc1.w};
    float bi[8] = {bi0.x, bi0.y, bi0.z, bi0.w, bi1.x, bi1.y, bi1.z, bi1.w};
    uint32_t hp[4], lp[4];
#pragma unroll
    for (int i = 0; i < 4; i++) {
        float y0 = (v[2*i]   - st.x) * st.y * sc[2*i]   + bi[2*i];
        float y1 = (v[2*i+1] - st.x) * st.y * sc[2*i+1] + bi[2*i+1];
        split2(y0, y1, hp[i], lp[i]);
    }
    *reinterpret_cast<uint4*>(dh + off + col) = *reinterpret_cast<uint4*>(hp);
    *reinterpret_cast<uint4*>(dl + off + col) = *reinterpret_cast<uint4*>(lp);
}

// ---------------------------------------------------------------------------
// GEMM 128x128 tile (projections + W1).
// MODE: 0 plain, 2 +bias+gelu, 3 xATTN_SCALE.  OUT: 1 bf16 hi/lo out.
// ---------------------------------------------------------------------------
#define GPAD 40
#define TILE_B (128 * GPAD * 2)
#define STAGE_B (4 * TILE_B)
#define GEMM_SMEM_BYTES (2 * STAGE_B)

__device__ __forceinline__ void gemm_issue_chunk(
    uint32_t stage, int tid,
    const __nv_bfloat16* Ah, const __nv_bfloat16* Al,
    const __nv_bfloat16* Bh, const __nv_bfloat16* Bl,
    int mBase, int nBase, int k0)
{
    const __nv_bfloat16* srcs[4] = {Ah, Al, Bh, Bl};
#pragma unroll
    for (int t4 = 0; t4 < 4; t4++) {
        int base = (t4 < 2) ? mBase : nBase;
#pragma unroll
        for (int it = 0; it < 2; it++) {
            int seg = tid + it * 256;
            int row = seg >> 2, j = seg & 3;
            const void* gp = srcs[t4] + (size_t)(base + row) * 256 + k0 + j * 8;
            uint32_t d = stage + t4 * TILE_B + (uint32_t)((row * GPAD + j * 8) * 2);
            CP_ASYNC16(d, gp);
        }
    }
    CP_COMMIT();
}

template <int MODE, int OUT>
__global__ __launch_bounds__(256, 2)
void gemm_bf16_kernel(const __nv_bfloat16* __restrict__ Ah,
                      const __nv_bfloat16* __restrict__ Al,
                      const __nv_bfloat16* __restrict__ Bth,
                      const __nv_bfloat16* __restrict__ Btl,
                      const float* __restrict__ bias,
                      __nv_bfloat16* __restrict__ Ch,
                      __nv_bfloat16* __restrict__ Cl,
                      int ldC) {
    extern __shared__ char smem[];
    const uint32_t sb = smem_u32(smem);

    int tid  = threadIdx.x;
    int wid  = tid >> 5, lane = tid & 31;
    int warpM = wid & 3;
    int warpN = wid >> 2;
    int mBase = blockIdx.x * 128;
    int nBase = blockIdx.y * 128;

    float acc[2][8][4];
#pragma unroll
    for (int i = 0; i < 2; i++)
#pragma unroll
        for (int j = 0; j < 8; j++)
#pragma unroll
            for (int k = 0; k < 4; k++) acc[i][j][k] = 0.f;

    gemm_issue_chunk(sb, tid, Ah, Al, Bth, Btl, mBase, nBase, 0);

    for (int kc = 0; kc < 8; kc++) {
        if (kc < 7)
            gemm_issue_chunk(sb + ((kc + 1) & 1) * STAGE_B, tid, Ah, Al, Bth, Btl,
                             mBase, nBase, (kc + 1) * 32);
        if (kc < 7) { CP_WAIT1(); } else { CP_WAIT0(); }
        __syncthreads();

        uint32_t st = sb + (kc & 1) * STAGE_B;
#pragma unroll
        for (int ks = 0; ks < 2; ks++) {
            int lrow = lane & 15;
            int lcol = ks * 16 + (lane >> 4) * 8;
            uint32_t ah[2][4], al[2][4];
#pragma unroll
            for (int mt = 0; mt < 2; mt++) {
                int row = warpM * 32 + mt * 16 + lrow;
                uint32_t ad = st + (uint32_t)((row * GPAD + lcol) * 2);
                ldmatrix_x4(ah[mt], ad);
                ldmatrix_x4(al[mt], ad + TILE_B);
            }
#pragma unroll
            for (int nt2 = 0; nt2 < 4; nt2++) {
                int row = warpN * 64 + nt2 * 16 + lrow;
                uint32_t bd = st + 2 * TILE_B + (uint32_t)((row * GPAD + lcol) * 2);
                uint32_t bh[4], bl[4];
                ldmatrix_x4(bh, bd);
                ldmatrix_x4(bl, bd + TILE_B);
#pragma unroll
                for (int mt = 0; mt < 2; mt++) {
                    mma16816(acc[mt][nt2 * 2 + 0], ah[mt], bh[0], bh[2]);
                    mma16816(acc[mt][nt2 * 2 + 0], ah[mt], bl[0], bl[2]);
                    mma16816(acc[mt][nt2 * 2 + 0], al[mt], bh[0], bh[2]);
                    mma16816(acc[mt][nt2 * 2 + 1], ah[mt], bh[1], bh[3]);
                    mma16816(acc[mt][nt2 * 2 + 1], ah[mt], bl[1], bl[3]);
                    mma16816(acc[mt][nt2 * 2 + 1], al[mt], bh[1], bh[3]);
                }
            }
        }
        __syncthreads();
    }

    int g = lane >> 2, tig = lane & 3;
#pragma unroll
    for (int mt = 0; mt < 2; mt++) {
#pragma unroll
        for (int nt = 0; nt < 8; nt++) {
            int row0 = mBase + warpM * 32 + mt * 16 + g;
            int col  = nBase + warpN * 64 + nt * 8 + tig * 2;
            float v0 = acc[mt][nt][0], v1 = acc[mt][nt][1];
            float v2 = acc[mt][nt][2], v3 = acc[mt][nt][3];
            if (MODE == 2) {
                float bb0 = bias[col], bb1 = bias[col + 1];
                v0 = gelu_tanh(v0 + bb0); v1 = gelu_tanh(v1 + bb1);
                v2 = gelu_tanh(v2 + bb0); v3 = gelu_tanh(v3 + bb1);
            }
            if (MODE == 3) {
                v0 *= ATTN_SCALE; v1 *= ATTN_SCALE;
                v2 *= ATTN_SCALE; v3 *= ATTN_SCALE;
            }
            uint32_t hp01, lp01, hp23, lp23;
            split2(v0, v1, hp01, lp01);
            split2(v2, v3, hp23, lp23);
            *reinterpret_cast<uint32_t*>(Ch + (size_t)row0 * ldC + col) = hp01;
            *reinterpret_cast<uint32_t*>(Ch + (size_t)(row0 + 8) * ldC + col) = hp23;
            *reinterpret_cast<uint32_t*>(Cl + (size_t)row0 * ldC + col) = lp01;
            *reinterpret_cast<uint32_t*>(Cl + (size_t)(row0 + 8) * ldC + col) = lp23;
        }
    }
}

// ---------------------------------------------------------------------------
// GEMM 64(M) x 256(N) tile with fused row-LayerNorm epilogue.
// RES=0: Wo path -> LN(ln1) -> hh/hl
// RES=1: W2 path -> +bias + residual(hh+hl) -> LN(ln1) -> LN(ln2) -> atomic outp
// 8 warps: warpM = wid&1 (2 x 32 rows), warpN = wid>>1 (4 x 64 cols).
// Stage = 50 KB; 2 stages = 100 KB -> 2 CTAs/SM.
// ---------------------------------------------------------------------------
#define G2A (64 * GPAD * 2)        // 5120
#define G2B (256 * GPAD * 2)       // 20480
#define G2_STAGE (2 * G2A + 2 * G2B)   // 51200
#define G2_SMEM (2 * G2_STAGE)         // 102400

__device__ __forceinline__ void g2_issue(
    uint32_t stage, int tid,
    const __nv_bfloat16* Ah, const __nv_bfloat16* Al,
    const __nv_bfloat16* Bh, const __nv_bfloat16* Bl,
    int mBase, int k0)
{
    {
        int row = tid >> 2, j = tid & 3;
        uint32_t off = (uint32_t)((row * GPAD + j * 8) * 2);
        size_t go = (size_t)(mBase + row) * 256 + k0 + j * 8;
        CP_ASYNC16(stage + off, Ah + go);
        CP_ASYNC16(stage + G2A + off, Al + go);
    }
#pragma unroll
    for (int it = 0; it < 4; it++) {
        int seg = tid + it * 256;
        int row = seg >> 2, j = seg & 3;
        uint32_t off = (uint32_t)((row * GPAD + j * 8) * 2);
        size_t go = (size_t)row * 256 + k0 + j * 8;
        CP_ASYNC16(stage + 2 * G2A + off, Bh + go);
        CP_ASYNC16(stage + 2 * G2A + G2B + off, Bl + go);
    }
    CP_COMMIT();
}

// CTA-wide per-row (256 cols) LN stats for the 64x256 tile layout.
__device__ __forceinline__ void cta_ln_stats(
    float (&acc)[2][8][4], char* smemraw,
    int warpM, int warpN, int g, int tig,
    float (&mean)[2][2], float (&rstd)[2][2])
{
    float* redS = reinterpret_cast<float*>(smemraw);
    float* redQ = redS + 256;
    __syncthreads();   // protect smem reuse (stages / previous reduction)
    float ps[2][2], pq[2][2];
#pragma unroll
    for (int mt = 0; mt < 2; mt++)
#pragma unroll
        for (int hf = 0; hf < 2; hf++) {
            float s = 0.f, q = 0.f;
#pragma unroll
            for (int nt = 0; nt < 8; nt++) {
                float a = acc[mt][nt][hf * 2], b = acc[mt][nt][hf * 2 + 1];
                s += a + b; q += a * a + b * b;
            }
            ps[mt][hf] = s; pq[mt][hf] = q;
        }
#pragma unroll
    for (int o = 1; o <= 2; o <<= 1) {
#pragma unroll
        for (int mt = 0; mt < 2; mt++)
#pragma unroll
            for (int hf = 0; hf < 2; hf++) {
                ps[mt][hf] += __shfl_xor_sync(0xffffffffu, ps[mt][hf], o);
                pq[mt][hf] += __shfl_xor_sync(0xffffffffu, pq[mt][hf], o);
            }
    }
    if (tig == 0) {
#pragma unroll
        for (int mt = 0; mt < 2; mt++)
#pragma unroll
            for (int hf = 0; hf < 2; hf++) {
                int lr = warpM * 32 + mt * 16 + g + hf * 8;
                redS[lr * 4 + warpN] = ps[mt][hf];
                redQ[lr * 4 + warpN] = pq[mt][hf];
            }
    }
    __syncthreads();
#pragma unroll
    for (int mt = 0; mt < 2; mt++)
#pragma unroll
        for (int hf = 0; hf < 2; hf++) {
            int lr = warpM * 32 + mt * 16 + g + hf * 8;
            float S = redS[lr * 4] + redS[lr * 4 + 1] + redS[lr * 4 + 2] + redS[lr * 4 + 3];
            float Q = redQ[lr * 4] + redQ[lr * 4 + 1] + redQ[lr * 4 + 2] + redQ[lr * 4 + 3];
            float m = S * (1.0f / D);
            float v = Q * (1.0f / D) - m * m;
            mean[mt][hf] = m;
            rstd[mt][hf] = rsqrtf(v + 1e-5f);
        }
}

template <int RES>
__global__ __launch_bounds__(256, 2)
void gemm_ln_kernel(const __nv_bfloat16* __restrict__ Ah, const __nv_bfloat16* __restrict__ Al,
                    const __nv_bfloat16* __restrict__ Bth, const __nv_bfloat16* __restrict__ Btl,
                    const float* __restrict__ bias,
                    const float* __restrict__ ln1s, const float* __restrict__ ln1b,
                    const float* __restrict__ ln2s, const float* __restrict__ ln2b,
                    const __nv_bfloat16* __restrict__ hh, const __nv_bfloat16* __restrict__ hl,
                    const int* __restrict__ qidx,
                    __nv_bfloat16* __restrict__ Oh, __nv_bfloat16* __restrict__ Ol,
                    float* __restrict__ outp) {
    extern __shared__ char smem[];
    const uint32_t sb = smem_u32(smem);

    int tid  = threadIdx.x;
    int wid  = tid >> 5, lane = tid & 31;
    int warpM = wid & 1;
    int warpN = wid >> 1;
    int mBase = blockIdx.x * 64;
    int g = lane >> 2, tig = lane & 3;

    float acc[2][8][4];
#pragma unroll
    for (int i = 0; i < 2; i++)
#pragma unroll
        for (int j = 0; j < 8; j++)
#pragma unroll
            for (int k = 0; k < 4; k++) acc[i][j][k] = 0.f;

    g2_issue(sb, tid, Ah, Al, Bth, Btl, mBase, 0);

    for (int kc = 0; kc < 8; kc++) {
        if (kc < 7)
            g2_issue(sb + ((kc + 1) & 1) * G2_STAGE, tid, Ah, Al, Bth, Btl,
                     mBase, (kc + 1) * 32);
        if (kc < 7) { CP_WAIT1(); } else { CP_WAIT0(); }
        __syncthreads();

        uint32_t st = sb + (kc & 1) * G2_STAGE;
#pragma unroll
        for (int ks = 0; ks < 2; ks++) {
            int lrow = lane & 15;
            int lcol = ks * 16 + (lane >> 4) * 8;
            uint32_t ah[2][4], al[2][4];
#pragma unroll
            for (int mt = 0; mt < 2; mt++) {
                int row = warpM * 32 + mt * 16 + lrow;
                uint32_t ad = st + (uint32_t)((row * GPAD + lcol) * 2);
                ldmatrix_x4(ah[mt], ad);
                ldmatrix_x4(al[mt], ad + G2A);
            }
#pragma unroll
            for (int nt2 = 0; nt2 < 4; nt2++) {
                int row = warpN * 64 + nt2 * 16 + lrow;
                uint32_t bd = st + 2 * G2A + (uint32_t)((row * GPAD + lcol) * 2);
                uint32_t bh[4], bl[4];
                ldmatrix_x4(bh, bd);
                ldmatrix_x4(bl, bd + G2B);
#pragma unroll
                for (int mt = 0; mt < 2; mt++) {
                    mma16816(acc[mt][nt2 * 2 + 0], ah[mt], bh[0], bh[2]);
                    mma16816(acc[mt][nt2 * 2 + 0], ah[mt], bl[0], bl[2]);
                    mma16816(acc[mt][nt2 * 2 + 0], al[mt], bh[0], bh[2]);
                    mma16816(acc[mt][nt2 * 2 + 1], ah[mt], bh[1], bh[3]);
                    mma16816(acc[mt][nt2 * 2 + 1], ah[mt], bl[1], bl[3]);
                    mma16816(acc[mt][nt2 * 2 + 1], al[mt], bh[1], bh[3]);
                }
            }
        }
        __syncthreads();
    }

    float mean[2][2], rstd[2][2];

    if (RES == 1) {
        // x = gemm + b2 + h  (residual add before the double LN)
#pragma unroll
        for (int mt = 0; mt < 2; mt++)
#pragma unroll
            for (int nt = 0; nt < 8; nt++) {
                int col = warpN * 64 + nt * 8 + tig * 2;
                float bb0 = __ldg(bias + col), bb1 = __ldg(bias + col + 1);
#pragma unroll
                for (int hf = 0; hf < 2; hf++) {
                    int gr = mBase + warpM * 32 + mt * 16 + g + hf * 8;
                    size_t o = (size_t)gr * D + col;
                    float2 hv = bf2_sum(*reinterpret_cast<const uint32_t*>(hh + o),
                                        *reinterpret_cast<const uint32_t*>(hl + o));
                    acc[mt][nt][hf * 2 + 0] += bb0 + hv.x;
                    acc[mt][nt][hf * 2 + 1] += bb1 + hv.y;
                }
            }
    }

    // first LN
    cta_ln_stats(acc, smem, warpM, warpN, g, tig, mean, rstd);
#pragma unroll
    for (int mt = 0; mt < 2; mt++)
#pragma unroll
        for (int nt = 0; nt < 8; nt++) {
            int col = warpN * 64 + nt * 8 + tig * 2;
            float s0 = __ldg(ln1s + col), s1 = __ldg(ln1s + col + 1);
            float c0 = __ldg(ln1b + col), c1 = __ldg(ln1b + col + 1);
#pragma unroll
            for (int hf = 0; hf < 2; hf++) {
                acc[mt][nt][hf * 2 + 0] =
                    (acc[mt][nt][hf * 2 + 0] - mean[mt][hf]) * rstd[mt][hf] * s0 + c0;
                acc[mt][nt][hf * 2 + 1] =
                    (acc[mt][nt][hf * 2 + 1] - mean[mt][hf]) * rstd[mt][hf] * s1 + c1;
            }
        }

    if (RES == 0) {
        // write hh/hl
#pragma unroll
        for (int mt = 0; mt < 2; mt++)
#pragma unroll
            for (int nt = 0; nt < 8; nt++) {
                int col = warpN * 64 + nt * 8 + tig * 2;
#pragma unroll
                for (int hf = 0; hf < 2; hf++) {
                    int gr = mBase + warpM * 32 + mt * 16 + g + hf * 8;
                    uint32_t hp, lp;
                    split2(acc[mt][nt][hf * 2], acc[mt][nt][hf * 2 + 1], hp, lp);
                    *reinterpret_cast<uint32_t*>(Oh + (size_t)gr * D + col) = hp;
                    *reinterpret_cast<uint32_t*>(Ol + (size_t)gr * D + col) = lp;
                }
            }
    } else {
        // second LN + scatter-add
        cta_ln_stats(acc, smem, warpM, warpN, g, tig, mean, rstd);
        int sidx[2][2], bidx[2][2];
#pragma unroll
        for (int mt = 0; mt < 2; mt++)
#pragma unroll
            for (int hf = 0; hf < 2; hf++) {
                int gr = mBase + warpM * 32 + mt * 16 + g + hf * 8;
                bidx[mt][hf] = gr / NQ;
                sidx[mt][hf] = __ldg(qidx + (gr % NQ));
            }
#pragma unroll
        for (int mt = 0; mt < 2; mt++)
#pragma unroll
            for (int nt = 0; nt < 8; nt++) {
                int col = warpN * 64 + nt * 8 + tig * 2;
                float s0 = __ldg(ln2s + col), s1 = __ldg(ln2s + col + 1);
                float c0 = __ldg(ln2b + col), c1 = __ldg(ln2b + col + 1);
#pragma unroll
                for (int hf = 0; hf < 2; hf++) {
                    float z0 = (acc[mt][nt][hf * 2 + 0] - mean[mt][hf]) * rstd[mt][hf] * s0 + c0;
                    float z1 = (acc[mt][nt][hf * 2 + 1] - mean[mt][hf]) * rstd[mt][hf] * s1 + c1;
                    size_t o = ((size_t)bidx[mt][hf] * NS + sidx[mt][hf]) * D + col;
                    atomicAdd(&outp[o], z0);
                    atomicAdd(&outp[o + 1], z1);
                }
            }
    }
}

// ---------------------------------------------------------------------------
// Fused flash attention (static softmax, Q pre-scaled by ATTN_SCALE).
// ---------------------------------------------------------------------------
#define APAD 72
#define A_KH 0
#define A_KL 9216
#define A_VH 18432
#define A_VL 27648
#define A_MS 36864
#define A_STAGE 47104
#define ATTN_SMEM_BYTES (2 * A_STAGE)

__device__ __forceinline__ void attn_stage(
    uint32_t st, int tid,
    const __nv_bfloat16* KVh, const __nv_bfloat16* KVl,
    const unsigned char* maskb, int b, int h, int q0, int kb)
{
#pragma unroll
    for (int it = 0; it < 2; it++) {
        int seg = tid + it * 256;
        int r = seg >> 3, j = seg & 7;
        size_t rowb = ((size_t)(b * NK + kb + r)) * 512 + h * DH + j * 8;
        uint32_t off = (uint32_t)((r * APAD + j * 8) * 2);
        CP_ASYNC16(st + A_KH + off, KVh + rowb);
        CP_ASYNC16(st + A_KL + off, KVl + rowb);
        CP_ASYNC16(st + A_VH + off, KVh + rowb + 256);
        CP_ASYNC16(st + A_VL + off, KVl + rowb + 256);
    }
#pragma unroll
    for (int it = 0; it < 2; it++) {
        int seg = tid + it * 256;
        int r = seg >> 2, j = seg & 3;
        CP_ASYNC16(st + A_MS + (uint32_t)(r * 80 + j * 16),
                   maskb + (size_t)(q0 + r) * NK + kb + j * 16);
    }
    CP_COMMIT();
}

__global__ __launch_bounds__(256, 2)
void attn_mma_kernel(const __nv_bfloat16* __restrict__ Qh, const __nv_bfloat16* __restrict__ Ql,
                     const __nv_bfloat16* __restrict__ KVh, const __nv_bfloat16* __restrict__ KVl,
                     const unsigned char* __restrict__ maskb,
                     __nv_bfloat16* __restrict__ ctxh, __nv_bfloat16* __restrict__ ctxl) {
    extern __shared__ char smem[];
    const uint32_t sb = smem_u32(smem);

    int tid = threadIdx.x, wid = tid >> 5, lane = tid & 31;
    int q0 = blockIdx.x * 128, h = blockIdx.y, b = blockIdx.z;
    int g = lane >> 2, tig = lane & 3;
    int lrow = lane & 15, lco = (lane >> 4) * 8;

    uint32_t qah[4][4], qal[4][4];
#pragma unroll
    for (int ks = 0; ks < 4; ks++) {
#pragma unroll
        for (int i = 0; i < 4; i++) {
            int row = q0 + wid * 16 + g + (i & 1) * 8;
            int col = h * DH + ks * 16 + tig * 2 + (i >> 1) * 8;
            size_t o = ((size_t)(b * NQ + row)) * D + col;
            qah[ks][i] = *reinterpret_cast<const uint32_t*>(Qh + o);
            qal[ks][i] = *reinterpret_cast<const uint32_t*>(Ql + o);
        }
    }

    float l0 = 0.f, l1 = 0.f;
    float oacc[8][4];
#pragma unroll
    for (int j = 0; j < 8; j++)
#pragma unroll
        for (int k = 0; k < 4; k++) oacc[j][k] = 0.f;

    attn_stage(sb, tid, KVh, KVl, maskb, b, h, q0, 0);

    for (int c = 0; c < 16; c++) {
        if (c < 15)
            attn_stage(sb + ((c + 1) & 1) * A_STAGE, tid, KVh, KVl,
                       maskb, b, h, q0, (c + 1) * 64);
        if (c < 15) { CP_WAIT1(); } else { CP_WAIT0(); }
        __syncthreads();

        uint32_t st = sb + (c & 1) * A_STAGE;
        const unsigned char* msp = reinterpret_cast<const unsigned char*>(
            smem + (c & 1) * A_STAGE + A_MS);

        float sacc[8][4];
#pragma unroll
        for (int j = 0; j < 8; j++)
#pragma unroll
            for (int k = 0; k < 4; k++) sacc[j][k] = 0.f;
#pragma unroll
        for (int ks = 0; ks < 4; ks++) {
#pragma unroll
            for (int nt = 0; nt < 4; nt++) {
                uint32_t bh[4], bl[4];
                uint32_t off = (uint32_t)(((nt * 16 + lrow) * APAD + ks * 16 + lco) * 2);
                ldmatrix_x4(bh, st + A_KH + off);
                ldmatrix_x4(bl, st + A_KL + off);
                mma16816(sacc[nt * 2 + 0], qah[ks], bh[0], bh[2]);
                mma16816(sacc[nt * 2 + 0], qah[ks], bl[0], bl[2]);
                mma16816(sacc[nt * 2 + 0], qal[ks], bh[0], bh[2]);
                mma16816(sacc[nt * 2 + 1], qah[ks], bh[1], bh[3]);
                mma16816(sacc[nt * 2 + 1], qah[ks], bl[1], bl[3]);
                mma16816(sacc[nt * 2 + 1], qal[ks], bh[1], bh[3]);
            }
        }

        int qr0 = wid * 16 + g, qr1 = qr0 + 8;
        uint32_t pa[4][4], pl[4][4];
#pragma unroll
        for (int j = 0; j < 8; j++) {
            int col = j * 8 + 2 * tig;
            float p0 = msp[qr0 * 80 + col]     ? __expf(sacc[j][0]) : 0.f;
            float p1 = msp[qr0 * 80 + col + 1] ? __expf(sacc[j][1]) : 0.f;
            float p2 = msp[qr1 * 80 + col]     ? __expf(sacc[j][2]) : 0.f;
            float p3 = msp[qr1 * 80 + col + 1] ? __expf(sacc[j][3]) : 0.f;
            l0 += p0 + p1; l1 += p2 + p3;
            int kc = j >> 1, o2 = (j & 1) * 2;
            uint32_t hp, lp;
            split2(p0, p1, hp, lp);
            pa[kc][o2 + 0] = hp; pl[kc][o2 + 0] = lp;
            split2(p2, p3, hp, lp);
            pa[kc][o2 + 1] = hp; pl[kc][o2 + 1] = lp;
        }

        int vro = ((lane >> 4) << 3) + (lane & 7);
        int vcb = ((lane >> 3) & 1) << 3;
#pragma unroll
        for (int kc = 0; kc < 4; kc++) {
            int vr = 16 * kc + vro;
#pragma unroll
            for (int vt = 0; vt < 4; vt++) {
                uint32_t vh[4], vl[4];
                uint32_t off = (uint32_t)((vr * APAD + vt * 16 + vcb) * 2);
                ldmatrix_x4_t(vh, st + A_VH + off);
                ldmatrix_x4_t(vl, st + A_VL + off);
                mma16816(oacc[vt * 2 + 0], pa[kc], vh[0], vh[2]);
                mma16816(oacc[vt * 2 + 0], pa[kc], vl[0], vl[2]);
                mma16816(oacc[vt * 2 + 0], pl[kc], vh[0], vh[2]);
                mma16816(oacc[vt * 2 + 1], pa[kc], vh[1], vh[3]);
                mma16816(oacc[vt * 2 + 1], pa[kc], vl[1], vl[3]);
                mma16816(oacc[vt * 2 + 1], pl[kc], vh[1], vh[3]);
            }
        }
        __syncthreads();
    }

    l0 += __shfl_xor_sync(0xffffffffu, l0, 1);
    l0 += __shfl_xor_sync(0xffffffffu, l0, 2);
    l1 += __shfl_xor_sync(0xffffffffu, l1, 1);
    l1 += __shfl_xor_sync(0xffffffffu, l1, 2);

    float inv0 = 1.0f / l0, inv1 = 1.0f / l1;
#pragma unroll
    for (int j = 0; j < 8; j++) {
        int col = h * DH + j * 8 + 2 * tig;
        size_t r0 = ((size_t)(b * NQ + q0 + wid * 16 + g)) * D + col;
        uint32_t hp, lp;
        split2(oacc[j][0] * inv0, oacc[j][1] * inv0, hp, lp);
        *reinterpret_cast<uint32_t*>(ctxh + r0) = hp;
        *reinterpret_cast<uint32_t*>(ctxl + r0) = lp;
        split2(oacc[j][2] * inv1, oacc[j][3] * inv1, hp, lp);
        *reinterpret_cast<uint32_t*>(ctxh + r0 + 8 * D) = hp;
        *reinterpret_cast<uint32_t*>(ctxl + r0 + 8 * D) = lp;
    }
}

// ---------------------------------------------------------------------------
// launch
// ---------------------------------------------------------------------------
extern "C" void kernel_launch(void* const* d_in, const int* in_sizes, int n_in,
                              void* d_out, int out_size) {
    const float* update_tensor = (const float*)d_in[0];
    const float* emb   = (const float*)d_in[1];
    const float* mask  = (const float*)d_in[2];
    const float* Wq    = (const float*)d_in[3];
    const float* Wk    = (const float*)d_in[4];
    const float* Wv    = (const float*)d_in[5];
    const float* Wo    = (const float*)d_in[6];
    const float* W1    = (const float*)d_in[7];
    const float* b1    = (const float*)d_in[8];
    const float* W2    = (const float*)d_in[9];
    const float* b2    = (const float*)d_in[10];
    const float* sys_s = (const float*)d_in[11];
    const float* sys_b = (const float*)d_in[12];
    const float* eff_s = (const float*)d_in[13];
    const float* eff_b = (const float*)d_in[14];
    const float* in_s  = (const float*)d_in[15];
    const float* in_b  = (const float*)d_in[16];
    const float* out_s = (const float*)d_in[17];
    const float* out_b = (const float*)d_in[18];
    const int*   qidx  = (const int*)d_in[19];
    const int*   kidx  = (const int*)d_in[20];
    float* outp = (float*)d_out;

    __nv_bfloat16 *p_wh, *p_wl, *p_qnh, *p_qnl, *p_knh, *p_knl;
    __nv_bfloat16 *p_Qh, *p_Ql, *p_KVh, *p_KVl;
    __nv_bfloat16 *p_ctxh, *p_ctxl, *p_hh, *p_hl, *p_gh, *p_gl;
    unsigned char* p_mb;
    cudaGetSymbolAddress((void**)&p_wh,   g_Wt_hi);
    cudaGetSymbolAddress((void**)&p_wl,   g_Wt_lo);
    cudaGetSymbolAddress((void**)&p_qnh,  g_qnh);
    cudaGetSymbolAddress((void**)&p_qnl,  g_qnl);
    cudaGetSymbolAddress((void**)&p_knh,  g_knh);
    cudaGetSymbolAddress((void**)&p_knl,  g_knl);
    cudaGetSymbolAddress((void**)&p_Qh,   g_Qh);
    cudaGetSymbolAddress((void**)&p_Ql,   g_Ql);
    cudaGetSymbolAddress((void**)&p_KVh,  g_KVh);
    cudaGetSymbolAddress((void**)&p_KVl,  g_KVl);
    cudaGetSymbolAddress((void**)&p_ctxh, g_ctxh);
    cudaGetSymbolAddress((void**)&p_ctxl, g_ctxl);
    cudaGetSymbolAddress((void**)&p_hh,   g_hh);
    cudaGetSymbolAddress((void**)&p_hl,   g_hl);
    cudaGetSymbolAddress((void**)&p_gh,   g_gh);
    cudaGetSymbolAddress((void**)&p_gl,   g_gl);
    cudaGetSymbolAddress((void**)&p_mb,   g_maskb);

    cudaFuncSetAttribute(gemm_bf16_kernel<0,1>, cudaFuncAttributeMaxDynamicSharedMemorySize, GEMM_SMEM_BYTES);
    cudaFuncSetAttribute(gemm_bf16_kernel<2,1>, cudaFuncAttributeMaxDynamicSharedMemorySize, GEMM_SMEM_BYTES);
    cudaFuncSetAttribute(gemm_bf16_kernel<3,1>, cudaFuncAttributeMaxDynamicSharedMemorySize, GEMM_SMEM_BYTES);
    cudaFuncSetAttribute(gemm_ln_kernel<0>, cudaFuncAttributeMaxDynamicSharedMemorySize, G2_SMEM);
    cudaFuncSetAttribute(gemm_ln_kernel<1>, cudaFuncAttributeMaxDynamicSharedMemorySize, G2_SMEM);
    cudaFuncSetAttribute(attn_mma_kernel, cudaFuncAttributeMaxDynamicSharedMemorySize, ATTN_SMEM_BYTES);

    init_kernel<<<(B * NS * D / 4) / 256, 256>>>(outp);
    maskb_kernel<<<(LVL * NQ * NK / 4) / 256, 256>>>(mask, p_mb);
    {
        WPtrs ws;
        ws.w[0] = Wq; ws.w[1] = Wk; ws.w[2] = Wv;
        ws.w[3] = Wo; ws.w[4] = W1; ws.w[5] = W2;
        prep_w_all_kernel<<<dim3(8, 8, 6), dim3(32, 8)>>>(ws, p_wh, p_wl);
    }

    for (int l = 0; l < LVL; l++) {
        const int* qi = qidx + l * NQ;
        const int* ki = kidx + l * NK;
        const unsigned char* mb = p_mb + (size_t)l * NQ * NK;

        gather_ln_kernel<<<B * (NQ + NK) / 8, 256>>>(emb, update_tensor, outp,
                                                     sys_s, sys_b, qi, ki,
                                                     p_qnh, p_qnl, p_knh, p_knl);

        // Q projection, pre-scaled by ATTN_SCALE
        gemm_bf16_kernel<3,1><<<dim3(B * NQ / 128, 2), 256, GEMM_SMEM_BYTES>>>(
            p_qnh, p_qnl, p_wh + 0 * 65536, p_wl + 0 * 65536,
            nullptr, p_Qh, p_Ql, 256);
        // fused K|V projection (N=512, stacked Wk;Wv)
        gemm_bf16_kernel<0,1><<<dim3(B * NK / 128, 4), 256, GEMM_SMEM_BYTES>>>(
            p_knh, p_knl, p_wh + 1 * 65536, p_wl + 1 * 65536,
            nullptr, p_KVh, p_KVl, 512);

        attn_mma_kernel<<<dim3(NQ / 128, H, B), 256, ATTN_SMEM_BYTES>>>(
            p_Qh, p_Ql, p_KVh, p_KVl, mb, p_ctxh, p_ctxl);

        // Wo + inner LN -> h (bf16 hi/lo)
        gemm_ln_kernel<0><<<B * NQ / 64, 256, G2_SMEM>>>(
            p_ctxh, p_ctxl, p_wh + 3 * 65536, p_wl + 3 * 65536,
            nullptr, in_s, in_b, nullptr, nullptr,
            nullptr, nullptr, nullptr, p_hh, p_hl, nullptr);

        // W1 + bias + gelu -> g (bf16 hi/lo)
        gemm_bf16_kernel<2,1><<<dim3(B * NQ / 128, 2), 256, GEMM_SMEM_BYTES>>>(
            p_hh, p_hl, p_wh + 4 * 65536, p_wl + 4 * 65536,
            b1, p_gh, p_gl, 256);

        // W2 + b2 + residual + double LN + scatter
        gemm_ln_kernel<1><<<B * NQ / 64, 256, G2_SMEM>>>(
            p_gh, p_gl, p_wh + 5 * 65536, p_wl + 5 * 65536,
            b2, out_s, out_b, eff_s, eff_b,
            p_hh, p_hl, qi, nullptr, nullptr, outp);
    }
}